// round 7
// baseline (speedup 1.0000x reference)
#include <cuda_runtime.h>
#include <cuda_bf16.h>
#include <cstdint>
#include <math.h>

#define BATCH 2
#define SEQ   2048
#define DM    1024
#define NH    16
#define HW    64
#define SM_SCALE 0.125f   // 1/sqrt(64)

#define NELEM (BATCH*NH*SEQ*HW)
#define XN    (BATCH*SEQ*DM)     // 4M elements per input tensor
#define WN    (DM*DM)            // 1M elements per weight

// Pre-split bf16 hi/lo planes of projected Q/K/V in [B, H, S, hw] layout.
__device__ __nv_bfloat16 g_qh[NELEM], g_ql[NELEM];
__device__ __nv_bfloat16 g_kh[NELEM], g_kl[NELEM];
__device__ __nv_bfloat16 g_vh[NELEM], g_vl[NELEM];
// Pre-split bf16 hi/lo planes of inputs X (q,k,v) and weights W (q,k,v).
__device__ __nv_bfloat16 g_xh[3*XN], g_xl[3*XN];
__device__ __nv_bfloat16 g_wh[3*WN], g_wl[3*WN];

// ---------------------------------------------------------------------------
// Helpers
// ---------------------------------------------------------------------------
__device__ __forceinline__ uint32_t smem_u32(const void* p) {
    uint32_t a;
    asm("{ .reg .u64 t; cvta.to.shared.u64 t, %1; cvt.u32.u64 %0, t; }"
        : "=r"(a) : "l"(p));
    return a;
}

__device__ __forceinline__ void ldm4(uint32_t r[4], uint32_t addr) {
    asm volatile("ldmatrix.sync.aligned.m8n8.x4.shared.b16 {%0,%1,%2,%3}, [%4];"
                 : "=r"(r[0]), "=r"(r[1]), "=r"(r[2]), "=r"(r[3]) : "r"(addr));
}
__device__ __forceinline__ void ldm4t(uint32_t r[4], uint32_t addr) {
    asm volatile("ldmatrix.sync.aligned.m8n8.x4.trans.shared.b16 {%0,%1,%2,%3}, [%4];"
                 : "=r"(r[0]), "=r"(r[1]), "=r"(r[2]), "=r"(r[3]) : "r"(addr));
}

__device__ __forceinline__ void mma_bf16(float acc[4], const uint32_t a[4],
                                         uint32_t b0, uint32_t b1) {
    asm volatile(
        "mma.sync.aligned.m16n8k16.row.col.f32.bf16.bf16.f32 "
        "{%0,%1,%2,%3}, {%4,%5,%6,%7}, {%8,%9}, {%0,%1,%2,%3};"
        : "+f"(acc[0]), "+f"(acc[1]), "+f"(acc[2]), "+f"(acc[3])
        : "r"(a[0]), "r"(a[1]), "r"(a[2]), "r"(a[3]), "r"(b0), "r"(b1));
}

__device__ __forceinline__ uint32_t packhi(float a, float b, float& ra, float& rb) {
    __nv_bfloat16 ha = __float2bfloat16(a);
    __nv_bfloat16 hb = __float2bfloat16(b);
    ra = a - __bfloat162float(ha);
    rb = b - __bfloat162float(hb);
    return (uint32_t)__bfloat16_as_ushort(ha) |
           ((uint32_t)__bfloat16_as_ushort(hb) << 16);
}
__device__ __forceinline__ uint32_t packlo(float a, float b) {
    return (uint32_t)__bfloat16_as_ushort(__float2bfloat16(a)) |
           ((uint32_t)__bfloat16_as_ushort(__float2bfloat16(b)) << 16);
}

__device__ __forceinline__ void cpa16(uint32_t saddr, const void* g) {
    asm volatile("cp.async.cg.shared.global [%0], [%1], 16;"
                 :: "r"(saddr), "l"(g) : "memory");
}
#define CPA_COMMIT() asm volatile("cp.async.commit_group;" ::: "memory")
#define CPA_WAIT0()  asm volatile("cp.async.wait_group 0;" ::: "memory")

// ---------------------------------------------------------------------------
// Split inputs/weights into bf16 hi/lo planes (one bandwidth pass).
// grid = (4096, 6), block = 256. y<3: X tensors (1M float4), y>=3: W (256K).
// ---------------------------------------------------------------------------
__global__ __launch_bounds__(256) void split_kernel(
    const float4* __restrict__ xq, const float4* __restrict__ xk,
    const float4* __restrict__ xv, const float4* __restrict__ wq,
    const float4* __restrict__ wk, const float4* __restrict__ wv)
{
    const int y = blockIdx.y;
    const float4* src;
    __nv_bfloat16 *dh, *dl;
    if (y < 3) {
        src = (y == 0) ? xq : (y == 1) ? xk : xv;
        dh = g_xh + (size_t)y * XN;
        dl = g_xl + (size_t)y * XN;
    } else {
        if (blockIdx.x >= 1024) return;
        int w = y - 3;
        src = (w == 0) ? wq : (w == 1) ? wk : wv;
        dh = g_wh + (size_t)w * WN;
        dl = g_wl + (size_t)w * WN;
    }
    size_t i = (size_t)blockIdx.x * 256 + threadIdx.x;
    float4 a = src[i];
    float r0, r1, r2, r3;
    uint32_t h01 = packhi(a.x, a.y, r0, r1);
    uint32_t h23 = packhi(a.z, a.w, r2, r3);
    *(uint2*)(dh + i * 4) = make_uint2(h01, h23);
    *(uint2*)(dl + i * 4) = make_uint2(packlo(r0, r1), packlo(r2, r3));
}

// ---------------------------------------------------------------------------
// Projection GEMM on mma.sync bf16 (hi/lo 3-pass), pure-bf16 mainloop.
// Operands come pre-split; chunks stream via cp.async double-buffering.
// CTA 128x128, BK=32, 8 warps (4M x 2N). grid = (8, 32, 3), block = 256.
// Dynamic smem: 2 buffers x 4 tiles x (128*40*2)B = 81920 B.
// ---------------------------------------------------------------------------
#define SROW   40
#define PTILEB (128*SROW*2)   // 10240 bytes per tile

__global__ __launch_bounds__(256) void proj_mma()
{
    extern __shared__ unsigned short psm[];
    const uint32_t base = smem_u32(psm);

    const int z = blockIdx.z;
    const __nv_bfloat16* Ah = g_xh + (size_t)z * XN;
    const __nv_bfloat16* Al = g_xl + (size_t)z * XN;
    const __nv_bfloat16* Bh = g_wh + (size_t)z * WN;
    const __nv_bfloat16* Bl = g_wl + (size_t)z * WN;
    __nv_bfloat16* Oh = (z == 0) ? g_qh : (z == 1) ? g_kh : g_vh;
    __nv_bfloat16* Ol = (z == 0) ? g_ql : (z == 1) ? g_kl : g_vl;

    const int tid   = threadIdx.x;
    const int wid   = tid >> 5;
    const int lane  = tid & 31;
    const int warpM = wid >> 1;
    const int warpN = wid & 1;
    const int m0    = blockIdx.y * 128;
    const int n0    = blockIdx.x * 128;

    const uint32_t aRow = (uint32_t)(warpM * 32 + (lane & 15));
    const uint32_t aCol = (uint32_t)((lane >> 4) << 3);
    const uint32_t aOff = (aRow * SROW + aCol) * 2;
    const uint32_t bRow = (uint32_t)(warpN * 64 + (lane & 7) + ((lane >> 4) << 3));
    const uint32_t bCol = (uint32_t)(((lane >> 3) & 1) << 3);
    const uint32_t bOff = (bRow * SROW + bCol) * 2;

    // Per-thread cp.async coordinates: 512 x 16B per tile, 2 per thread.
    const int cr0 = tid >> 1;                 // rows tid/2 and tid/2+... (2 iters)
    const int cc0 = (tid & 1) * 2;            // c8 in {0,1} or {2,3}

    float acc[2][8][4];
#pragma unroll
    for (int mf = 0; mf < 2; mf++)
#pragma unroll
        for (int nf = 0; nf < 8; nf++)
#pragma unroll
            for (int i = 0; i < 4; i++) acc[mf][nf][i] = 0.0f;

    // Issue one chunk's 4 tiles (Ah,Al,Bh,Bl) into buffer p.
    auto load_chunk = [&](int c, int p) {
        const uint32_t bb = base + (uint32_t)(p * 4) * PTILEB;
        const int k0 = c * 32;
#pragma unroll
        for (int t = 0; t < 2; t++) {
            int c8 = cc0 + t;                 // 0..3
            uint32_t soff = (uint32_t)(cr0 * SROW + c8 * 8) * 2;
            size_t ga = (size_t)(m0 + cr0) * DM + k0 + c8 * 8;
            size_t gb = (size_t)(n0 + cr0) * DM + k0 + c8 * 8;
            cpa16(bb + 0 * PTILEB + soff, Ah + ga);
            cpa16(bb + 1 * PTILEB + soff, Al + ga);
            cpa16(bb + 2 * PTILEB + soff, Bh + gb);
            cpa16(bb + 3 * PTILEB + soff, Bl + gb);
        }
        CPA_COMMIT();
    };

    load_chunk(0, 0);

    for (int c = 0; c < 32; c++) {
        const int p = c & 1;
        CPA_WAIT0();
        __syncthreads();
        if (c < 31) load_chunk(c + 1, p ^ 1);

        const uint32_t ah32 = base + (uint32_t)(p * 4 + 0) * PTILEB;
        const uint32_t al32 = base + (uint32_t)(p * 4 + 1) * PTILEB;
        const uint32_t bh32 = base + (uint32_t)(p * 4 + 2) * PTILEB;
        const uint32_t bl32 = base + (uint32_t)(p * 4 + 3) * PTILEB;

#pragma unroll
        for (int ks = 0; ks < 2; ks++) {
            const uint32_t kByte = (uint32_t)(ks * 32);
            uint32_t ah[2][4], al[2][4], bh[4][4], bl[4][4];
#pragma unroll
            for (int mf = 0; mf < 2; mf++) {
                uint32_t ad = aOff + (uint32_t)(mf * 16 * SROW * 2) + kByte;
                ldm4(ah[mf], ah32 + ad);
                ldm4(al[mf], al32 + ad);
            }
#pragma unroll
            for (int pp = 0; pp < 4; pp++) {
                uint32_t bd = bOff + (uint32_t)(pp * 16 * SROW * 2) + kByte;
                ldm4(bh[pp], bh32 + bd);
                ldm4(bl[pp], bl32 + bd);
            }
#pragma unroll
            for (int mf = 0; mf < 2; mf++)
#pragma unroll
                for (int nf = 0; nf < 8; nf++) {
                    const int pp = nf >> 1, q = (nf & 1) * 2;
                    mma_bf16(acc[mf][nf], ah[mf], bh[pp][q], bh[pp][q+1]);
                    mma_bf16(acc[mf][nf], al[mf], bh[pp][q], bh[pp][q+1]);
                    mma_bf16(acc[mf][nf], ah[mf], bl[pp][q], bl[pp][q+1]);
                }
        }
        __syncthreads();
    }

    // Epilogue: split fp32 acc -> bf16 hi/lo planes, [B, H, S, hw] layout.
    const int g  = lane >> 2;
    const int t2 = (lane & 3) << 1;
#pragma unroll
    for (int mf = 0; mf < 2; mf++) {
        int mA  = m0 + warpM * 32 + mf * 16 + g;
        int mB  = mA + 8;
        int bbA = mA >> 11, ssA = mA & (SEQ - 1);
        int bbB = mB >> 11, ssB = mB & (SEQ - 1);
#pragma unroll
        for (int nf = 0; nf < 8; nf++) {
            int n  = n0 + warpN * 64 + nf * 8 + t2;
            int hh = n >> 6, dd = n & 63;
            size_t offA = (((size_t)(bbA * NH + hh)) * SEQ + ssA) * HW + dd;
            size_t offB = (((size_t)(bbB * NH + hh)) * SEQ + ssB) * HW + dd;
            float r0, r1;
            uint32_t hp = packhi(acc[mf][nf][0], acc[mf][nf][1], r0, r1);
            *(uint32_t*)(Oh + offA) = hp;
            *(uint32_t*)(Ol + offA) = packlo(r0, r1);
            hp = packhi(acc[mf][nf][2], acc[mf][nf][3], r0, r1);
            *(uint32_t*)(Oh + offB) = hp;
            *(uint32_t*)(Ol + offB) = packlo(r0, r1);
        }
    }
}

// ---------------------------------------------------------------------------
// Flash attention on mma.sync bf16 (hi/lo 3-pass), causal + ALiBi.
// (unchanged from R6 passing kernel)
// ---------------------------------------------------------------------------
#define AROW 72
#define ATILE (128*AROW)
#define TB    (ATILE*2)

__device__ __forceinline__ void tile_async(uint32_t sbase, const __nv_bfloat16* g,
                                           int row0, int tid) {
#pragma unroll
    for (int t = 0; t < 4; t++) {
        int i  = tid + t * 256;
        int r  = i >> 3, c8 = i & 7;
        cpa16(sbase + (uint32_t)(r * AROW + c8 * 8) * 2,
              g + (size_t)(row0 + r) * HW + c8 * 8);
    }
}

__global__ __launch_bounds__(256, 1) void attn_mma(float* __restrict__ out)
{
    extern __shared__ unsigned short asm_[];
    const uint32_t base = smem_u32(asm_);
    const uint32_t qh32 = base;
    const uint32_t ql32 = base + TB;

    const int bh = blockIdx.y;
    const int b  = bh >> 4;
    const int h  = bh & 15;
    const int qt = (int)gridDim.x - 1 - (int)blockIdx.x;
    const int q0 = qt * 128;

    const int tid  = threadIdx.x;
    const int warp = tid >> 5;
    const int lane = tid & 31;
    const int g    = lane >> 2;
    const int t2   = (lane & 3) << 1;

    const float slope = exp2f(-0.5f * (float)(h + 1));

    const __nv_bfloat16* Qh = g_qh + (size_t)bh * SEQ * HW;
    const __nv_bfloat16* Ql = g_ql + (size_t)bh * SEQ * HW;
    const __nv_bfloat16* Kh = g_kh + (size_t)bh * SEQ * HW;
    const __nv_bfloat16* Kl = g_kl + (size_t)bh * SEQ * HW;
    const __nv_bfloat16* Vh = g_vh + (size_t)bh * SEQ * HW;
    const __nv_bfloat16* Vl = g_vl + (size_t)bh * SEQ * HW;

#pragma unroll
    for (int t = 0; t < 4; t++) {
        int i = tid + t * 256;
        int r = i >> 3, c8 = i & 7;
        uint32_t soff = (uint32_t)(r * AROW + c8 * 8) * 2;
        *(uint4*)((char*)asm_ + soff) =
            *(const uint4*)(Qh + (size_t)(q0 + r) * HW + c8 * 8);
        *(uint4*)((char*)asm_ + TB + soff) =
            *(const uint4*)(Ql + (size_t)(q0 + r) * HW + c8 * 8);
    }

    {
        uint32_t b0 = base + 2 * TB;
        tile_async(b0 + 0 * TB, Kh, 0, tid);
        tile_async(b0 + 1 * TB, Kl, 0, tid);
        tile_async(b0 + 2 * TB, Vh, 0, tid);
        tile_async(b0 + 3 * TB, Vl, 0, tid);
        CPA_COMMIT();
    }

    const uint32_t aElem = (uint32_t)((warp * 16 + (lane & 15)) * AROW + ((lane >> 4) << 3));
    const uint32_t bElem = (uint32_t)(((lane & 7) + ((lane >> 4) << 3)) * AROW + (((lane >> 3) & 1) << 3));
    const uint32_t vElem = (uint32_t)((lane & 15) * AROW + ((lane >> 4) << 3));

    float oacc[8][4];
#pragma unroll
    for (int nf = 0; nf < 8; nf++)
#pragma unroll
        for (int e = 0; e < 4; e++) oacc[nf][e] = 0.0f;

    float m0r = -3e38f, m1r = -3e38f, l0 = 0.0f, l1 = 0.0f;
    const int row0 = q0 + warp * 16 + g;
    const int row1 = row0 + 8;

    for (int kt = 0; kt <= qt; kt++) {
        const int p = kt & 1;
        CPA_WAIT0();
        __syncthreads();

        if (kt < qt) {
            uint32_t bn = base + (2 + 4 * (p ^ 1)) * TB;
            int r0n = (kt + 1) * 128;
            tile_async(bn + 0 * TB, Kh, r0n, tid);
            tile_async(bn + 1 * TB, Kl, r0n, tid);
            tile_async(bn + 2 * TB, Vh, r0n, tid);
            tile_async(bn + 3 * TB, Vl, r0n, tid);
            CPA_COMMIT();
        }

        const uint32_t kh32 = base + (2 + 4 * p + 0) * TB;
        const uint32_t kl32 = base + (2 + 4 * p + 1) * TB;
        const uint32_t vh32 = base + (2 + 4 * p + 2) * TB;
        const uint32_t vl32 = base + (2 + 4 * p + 3) * TB;
        const int k0g = kt * 128;

        float sacc[16][4];
#pragma unroll
        for (int nf = 0; nf < 16; nf++)
#pragma unroll
            for (int e = 0; e < 4; e++) sacc[nf][e] = 0.0f;

#pragma unroll
        for (int ks = 0; ks < 4; ks++) {
            uint32_t ah[4], al[4];
            ldm4(ah, qh32 + (aElem + ks * 16) * 2);
            ldm4(al, ql32 + (aElem + ks * 16) * 2);
#pragma unroll
            for (int pp = 0; pp < 8; pp++) {
                uint32_t bhx[4], blx[4];
                uint32_t bd = (bElem + (uint32_t)(pp * 16 * AROW) + (uint32_t)(ks * 16)) * 2;
                ldm4(bhx, kh32 + bd);
                ldm4(blx, kl32 + bd);
                mma_bf16(sacc[2*pp],   ah, bhx[0], bhx[1]);
                mma_bf16(sacc[2*pp],   al, bhx[0], bhx[1]);
                mma_bf16(sacc[2*pp],   ah, blx[0], blx[1]);
                mma_bf16(sacc[2*pp+1], ah, bhx[2], bhx[3]);
                mma_bf16(sacc[2*pp+1], al, bhx[2], bhx[3]);
                mma_bf16(sacc[2*pp+1], ah, blx[2], blx[3]);
            }
        }

        const bool diag = (kt == qt);
        float mx0 = -3e38f, mx1 = -3e38f;
#pragma unroll
        for (int nf = 0; nf < 16; nf++) {
            int c0 = k0g + nf * 8 + t2;
            int c1 = c0 + 1;
            float v0 = sacc[nf][0] * SM_SCALE + slope * (float)(c0 - row0);
            float v1 = sacc[nf][1] * SM_SCALE + slope * (float)(c1 - row0);
            float v2 = sacc[nf][2] * SM_SCALE + slope * (float)(c0 - row1);
            float v3 = sacc[nf][3] * SM_SCALE + slope * (float)(c1 - row1);
            if (diag) {
                if (c0 > row0) v0 = -3e38f;
                if (c1 > row0) v1 = -3e38f;
                if (c0 > row1) v2 = -3e38f;
                if (c1 > row1) v3 = -3e38f;
            }
            sacc[nf][0] = v0; sacc[nf][1] = v1; sacc[nf][2] = v2; sacc[nf][3] = v3;
            mx0 = fmaxf(mx0, fmaxf(v0, v1));
            mx1 = fmaxf(mx1, fmaxf(v2, v3));
        }
        mx0 = fmaxf(mx0, __shfl_xor_sync(0xffffffffu, mx0, 1));
        mx0 = fmaxf(mx0, __shfl_xor_sync(0xffffffffu, mx0, 2));
        mx1 = fmaxf(mx1, __shfl_xor_sync(0xffffffffu, mx1, 1));
        mx1 = fmaxf(mx1, __shfl_xor_sync(0xffffffffu, mx1, 2));

        float mn0 = fmaxf(m0r, mx0);
        float mn1 = fmaxf(m1r, mx1);
        float corr0 = __expf(m0r - mn0);
        float corr1 = __expf(m1r - mn1);
        m0r = mn0; m1r = mn1;

        float rs0 = 0.0f, rs1 = 0.0f;
#pragma unroll
        for (int nf = 0; nf < 16; nf++) {
            float p0 = __expf(sacc[nf][0] - mn0);
            float p1 = __expf(sacc[nf][1] - mn0);
            float p2 = __expf(sacc[nf][2] - mn1);
            float p3 = __expf(sacc[nf][3] - mn1);
            sacc[nf][0] = p0; sacc[nf][1] = p1; sacc[nf][2] = p2; sacc[nf][3] = p3;
            rs0 += p0 + p1; rs1 += p2 + p3;
        }
        rs0 += __shfl_xor_sync(0xffffffffu, rs0, 1);
        rs0 += __shfl_xor_sync(0xffffffffu, rs0, 2);
        rs1 += __shfl_xor_sync(0xffffffffu, rs1, 1);
        rs1 += __shfl_xor_sync(0xffffffffu, rs1, 2);
        l0 = l0 * corr0 + rs0;
        l1 = l1 * corr1 + rs1;

#pragma unroll
        for (int nf = 0; nf < 8; nf++) {
            oacc[nf][0] *= corr0; oacc[nf][1] *= corr0;
            oacc[nf][2] *= corr1; oacc[nf][3] *= corr1;
        }

#pragma unroll
        for (int ks = 0; ks < 8; ks++) {
            uint32_t pah[4], pal[4];
            float r0, r1;
            pah[0] = packhi(sacc[2*ks][0],   sacc[2*ks][1],   r0, r1); pal[0] = packlo(r0, r1);
            pah[1] = packhi(sacc[2*ks][2],   sacc[2*ks][3],   r0, r1); pal[1] = packlo(r0, r1);
            pah[2] = packhi(sacc[2*ks+1][0], sacc[2*ks+1][1], r0, r1); pal[2] = packlo(r0, r1);
            pah[3] = packhi(sacc[2*ks+1][2], sacc[2*ks+1][3], r0, r1); pal[3] = packlo(r0, r1);
#pragma unroll
            for (int nb = 0; nb < 4; nb++) {
                uint32_t bhx[4], blx[4];
                uint32_t vd = (vElem + (uint32_t)(ks * 16 * AROW) + (uint32_t)(nb * 16)) * 2;
                ldm4t(bhx, vh32 + vd);
                ldm4t(blx, vl32 + vd);
                mma_bf16(oacc[2*nb],   pah, bhx[0], bhx[1]);
                mma_bf16(oacc[2*nb],   pal, bhx[0], bhx[1]);
                mma_bf16(oacc[2*nb],   pah, blx[0], blx[1]);
                mma_bf16(oacc[2*nb+1], pah, bhx[2], bhx[3]);
                mma_bf16(oacc[2*nb+1], pal, bhx[2], bhx[3]);
                mma_bf16(oacc[2*nb+1], pah, blx[2], blx[3]);
            }
        }
    }

    const float inv0 = 1.0f / l0;
    const float inv1 = 1.0f / l1;
    float* op = out + (size_t)b * SEQ * DM + (size_t)h * HW;
#pragma unroll
    for (int nf = 0; nf < 8; nf++) {
        int col = nf * 8 + t2;
        *(float2*)(op + (size_t)row0 * DM + col) =
            make_float2(oacc[nf][0] * inv0, oacc[nf][1] * inv0);
        *(float2*)(op + (size_t)row1 * DM + col) =
            make_float2(oacc[nf][2] * inv1, oacc[nf][3] * inv1);
    }
}

// ---------------------------------------------------------------------------
// Launch: inputs order = queries, keys, values, mask, Wq, Wk, Wv.
// ---------------------------------------------------------------------------
extern "C" void kernel_launch(void* const* d_in, const int* in_sizes, int n_in,
                              void* d_out, int out_size)
{
    (void)in_sizes; (void)n_in; (void)out_size;
    const float4* q  = (const float4*)d_in[0];
    const float4* k  = (const float4*)d_in[1];
    const float4* v  = (const float4*)d_in[2];
    const float4* wq = (const float4*)d_in[4];
    const float4* wk = (const float4*)d_in[5];
    const float4* wv = (const float4*)d_in[6];
    float* out = (float*)d_out;

    const int proj_smem = 8 * PTILEB;   // 81920 B
    cudaFuncSetAttribute(proj_mma, cudaFuncAttributeMaxDynamicSharedMemorySize, proj_smem);
    const int attn_smem = 10 * TB;      // 184320 B
    cudaFuncSetAttribute(attn_mma, cudaFuncAttributeMaxDynamicSharedMemorySize, attn_smem);

    split_kernel<<<dim3(4096, 6), 256>>>(q, k, v, wq, wk, wv);
    proj_mma<<<dim3(DM/128, (BATCH*SEQ)/128, 3), 256, proj_smem>>>();
    attn_mma<<<dim3(SEQ/128, BATCH*NH), 256, attn_smem>>>(out);
}

// round 8
// speedup vs baseline: 1.0638x; 1.0638x over previous
#include <cuda_runtime.h>
#include <cuda_bf16.h>
#include <cstdint>
#include <math.h>

#define BATCH 2
#define SEQ   2048
#define DM    1024
#define NH    16
#define HW    64
#define SM_SCALE 0.125f   // 1/sqrt(64)

#define NELEM (BATCH*NH*SEQ*HW)
#define XN    (BATCH*SEQ*DM)
#define WN    (DM*DM)

// Pre-split bf16 hi/lo planes of projected Q/K/V in [B, H, S, hw] layout.
__device__ __nv_bfloat16 g_qh[NELEM], g_ql[NELEM];
__device__ __nv_bfloat16 g_kh[NELEM], g_kl[NELEM];
__device__ __nv_bfloat16 g_vh[NELEM], g_vl[NELEM];
// Pre-split bf16 hi/lo planes of inputs X (q,k,v) and weights W (q,k,v).
__device__ __nv_bfloat16 g_xh[3*XN], g_xl[3*XN];
__device__ __nv_bfloat16 g_wh[3*WN], g_wl[3*WN];

// ---------------------------------------------------------------------------
// Helpers
// ---------------------------------------------------------------------------
__device__ __forceinline__ uint32_t smem_u32(const void* p) {
    uint32_t a;
    asm("{ .reg .u64 t; cvta.to.shared.u64 t, %1; cvt.u32.u64 %0, t; }"
        : "=r"(a) : "l"(p));
    return a;
}

__device__ __forceinline__ void ldm4(uint32_t r[4], uint32_t addr) {
    asm volatile("ldmatrix.sync.aligned.m8n8.x4.shared.b16 {%0,%1,%2,%3}, [%4];"
                 : "=r"(r[0]), "=r"(r[1]), "=r"(r[2]), "=r"(r[3]) : "r"(addr));
}
__device__ __forceinline__ void ldm4t(uint32_t r[4], uint32_t addr) {
    asm volatile("ldmatrix.sync.aligned.m8n8.x4.trans.shared.b16 {%0,%1,%2,%3}, [%4];"
                 : "=r"(r[0]), "=r"(r[1]), "=r"(r[2]), "=r"(r[3]) : "r"(addr));
}

__device__ __forceinline__ void mma_bf16(float acc[4], const uint32_t a[4],
                                         uint32_t b0, uint32_t b1) {
    asm volatile(
        "mma.sync.aligned.m16n8k16.row.col.f32.bf16.bf16.f32 "
        "{%0,%1,%2,%3}, {%4,%5,%6,%7}, {%8,%9}, {%0,%1,%2,%3};"
        : "+f"(acc[0]), "+f"(acc[1]), "+f"(acc[2]), "+f"(acc[3])
        : "r"(a[0]), "r"(a[1]), "r"(a[2]), "r"(a[3]), "r"(b0), "r"(b1));
}

__device__ __forceinline__ uint32_t packhi(float a, float b, float& ra, float& rb) {
    __nv_bfloat16 ha = __float2bfloat16(a);
    __nv_bfloat16 hb = __float2bfloat16(b);
    ra = a - __bfloat162float(ha);
    rb = b - __bfloat162float(hb);
    return (uint32_t)__bfloat16_as_ushort(ha) |
           ((uint32_t)__bfloat16_as_ushort(hb) << 16);
}
__device__ __forceinline__ uint32_t packlo(float a, float b) {
    return (uint32_t)__bfloat16_as_ushort(__float2bfloat16(a)) |
           ((uint32_t)__bfloat16_as_ushort(__float2bfloat16(b)) << 16);
}

__device__ __forceinline__ void cpa16(uint32_t saddr, const void* g) {
    asm volatile("cp.async.cg.shared.global [%0], [%1], 16;"
                 :: "r"(saddr), "l"(g) : "memory");
}
#define CPA_COMMIT() asm volatile("cp.async.commit_group;" ::: "memory")
#define CPA_WAIT0()  asm volatile("cp.async.wait_group 0;" ::: "memory")

// ---------------------------------------------------------------------------
// Split inputs/weights into bf16 hi/lo planes (one bandwidth pass).
// ---------------------------------------------------------------------------
__global__ __launch_bounds__(256) void split_kernel(
    const float4* __restrict__ xq, const float4* __restrict__ xk,
    const float4* __restrict__ xv, const float4* __restrict__ wq,
    const float4* __restrict__ wk, const float4* __restrict__ wv)
{
    const int y = blockIdx.y;
    const float4* src;
    __nv_bfloat16 *dh, *dl;
    if (y < 3) {
        src = (y == 0) ? xq : (y == 1) ? xk : xv;
        dh = g_xh + (size_t)y * XN;
        dl = g_xl + (size_t)y * XN;
    } else {
        if (blockIdx.x >= 1024) return;
        int w = y - 3;
        src = (w == 0) ? wq : (w == 1) ? wk : wv;
        dh = g_wh + (size_t)w * WN;
        dl = g_wl + (size_t)w * WN;
    }
    size_t i = (size_t)blockIdx.x * 256 + threadIdx.x;
    float4 a = src[i];
    float r0, r1, r2, r3;
    uint32_t h01 = packhi(a.x, a.y, r0, r1);
    uint32_t h23 = packhi(a.z, a.w, r2, r3);
    *(uint2*)(dh + i * 4) = make_uint2(h01, h23);
    *(uint2*)(dl + i * 4) = make_uint2(packlo(r0, r1), packlo(r2, r3));
}

// ---------------------------------------------------------------------------
// Projection GEMM on mma.sync bf16 (hi/lo 3-pass), pure-bf16 mainloop.
// 2 CTAs/SM (regs capped at 128 via launch bounds; smem 2x80KB fits).
// ---------------------------------------------------------------------------
#define SROW   40
#define PTILEB (128*SROW*2)   // 10240 bytes per tile

__global__ __launch_bounds__(256, 2) void proj_mma()
{
    extern __shared__ unsigned short psm[];
    const uint32_t base = smem_u32(psm);

    const int z = blockIdx.z;
    const __nv_bfloat16* Ah = g_xh + (size_t)z * XN;
    const __nv_bfloat16* Al = g_xl + (size_t)z * XN;
    const __nv_bfloat16* Bh = g_wh + (size_t)z * WN;
    const __nv_bfloat16* Bl = g_wl + (size_t)z * WN;
    __nv_bfloat16* Oh = (z == 0) ? g_qh : (z == 1) ? g_kh : g_vh;
    __nv_bfloat16* Ol = (z == 0) ? g_ql : (z == 1) ? g_kl : g_vl;

    const int tid   = threadIdx.x;
    const int wid   = tid >> 5;
    const int lane  = tid & 31;
    const int warpM = wid >> 1;
    const int warpN = wid & 1;
    const int m0    = blockIdx.y * 128;
    const int n0    = blockIdx.x * 128;

    const uint32_t aRow = (uint32_t)(warpM * 32 + (lane & 15));
    const uint32_t aCol = (uint32_t)((lane >> 4) << 3);
    const uint32_t aOff = (aRow * SROW + aCol) * 2;
    const uint32_t bRow = (uint32_t)(warpN * 64 + (lane & 7) + ((lane >> 4) << 3));
    const uint32_t bCol = (uint32_t)(((lane >> 3) & 1) << 3);
    const uint32_t bOff = (bRow * SROW + bCol) * 2;

    const int cr0 = tid >> 1;
    const int cc0 = (tid & 1) * 2;

    float acc[2][8][4];
#pragma unroll
    for (int mf = 0; mf < 2; mf++)
#pragma unroll
        for (int nf = 0; nf < 8; nf++)
#pragma unroll
            for (int i = 0; i < 4; i++) acc[mf][nf][i] = 0.0f;

    auto load_chunk = [&](int c, int p) {
        const uint32_t bb = base + (uint32_t)(p * 4) * PTILEB;
        const int k0 = c * 32;
#pragma unroll
        for (int t = 0; t < 2; t++) {
            int c8 = cc0 + t;
            uint32_t soff = (uint32_t)(cr0 * SROW + c8 * 8) * 2;
            size_t ga = (size_t)(m0 + cr0) * DM + k0 + c8 * 8;
            size_t gb = (size_t)(n0 + cr0) * DM + k0 + c8 * 8;
            cpa16(bb + 0 * PTILEB + soff, Ah + ga);
            cpa16(bb + 1 * PTILEB + soff, Al + ga);
            cpa16(bb + 2 * PTILEB + soff, Bh + gb);
            cpa16(bb + 3 * PTILEB + soff, Bl + gb);
        }
        CPA_COMMIT();
    };

    load_chunk(0, 0);

    for (int c = 0; c < 32; c++) {
        const int p = c & 1;
        CPA_WAIT0();
        __syncthreads();
        if (c < 31) load_chunk(c + 1, p ^ 1);

        const uint32_t ah32 = base + (uint32_t)(p * 4 + 0) * PTILEB;
        const uint32_t al32 = base + (uint32_t)(p * 4 + 1) * PTILEB;
        const uint32_t bh32 = base + (uint32_t)(p * 4 + 2) * PTILEB;
        const uint32_t bl32 = base + (uint32_t)(p * 4 + 3) * PTILEB;

#pragma unroll
        for (int ks = 0; ks < 2; ks++) {
            const uint32_t kByte = (uint32_t)(ks * 32);
            uint32_t ah[2][4], al[2][4], bh[4][4], bl[4][4];
#pragma unroll
            for (int mf = 0; mf < 2; mf++) {
                uint32_t ad = aOff + (uint32_t)(mf * 16 * SROW * 2) + kByte;
                ldm4(ah[mf], ah32 + ad);
                ldm4(al[mf], al32 + ad);
            }
#pragma unroll
            for (int pp = 0; pp < 4; pp++) {
                uint32_t bd = bOff + (uint32_t)(pp * 16 * SROW * 2) + kByte;
                ldm4(bh[pp], bh32 + bd);
                ldm4(bl[pp], bl32 + bd);
            }
#pragma unroll
            for (int mf = 0; mf < 2; mf++)
#pragma unroll
                for (int nf = 0; nf < 8; nf++) {
                    const int pp = nf >> 1, q = (nf & 1) * 2;
                    mma_bf16(acc[mf][nf], ah[mf], bh[pp][q], bh[pp][q+1]);
                    mma_bf16(acc[mf][nf], al[mf], bh[pp][q], bh[pp][q+1]);
                    mma_bf16(acc[mf][nf], ah[mf], bl[pp][q], bl[pp][q+1]);
                }
        }
        __syncthreads();
    }

    const int g  = lane >> 2;
    const int t2 = (lane & 3) << 1;
#pragma unroll
    for (int mf = 0; mf < 2; mf++) {
        int mA  = m0 + warpM * 32 + mf * 16 + g;
        int mB  = mA + 8;
        int bbA = mA >> 11, ssA = mA & (SEQ - 1);
        int bbB = mB >> 11, ssB = mB & (SEQ - 1);
#pragma unroll
        for (int nf = 0; nf < 8; nf++) {
            int n  = n0 + warpN * 64 + nf * 8 + t2;
            int hh = n >> 6, dd = n & 63;
            size_t offA = (((size_t)(bbA * NH + hh)) * SEQ + ssA) * HW + dd;
            size_t offB = (((size_t)(bbB * NH + hh)) * SEQ + ssB) * HW + dd;
            float r0, r1;
            uint32_t hp = packhi(acc[mf][nf][0], acc[mf][nf][1], r0, r1);
            *(uint32_t*)(Oh + offA) = hp;
            *(uint32_t*)(Ol + offA) = packlo(r0, r1);
            hp = packhi(acc[mf][nf][2], acc[mf][nf][3], r0, r1);
            *(uint32_t*)(Oh + offB) = hp;
            *(uint32_t*)(Ol + offB) = packlo(r0, r1);
        }
    }
}

// ---------------------------------------------------------------------------
// Flash attention on mma.sync bf16 (hi/lo 3-pass), causal + ALiBi.
// K-tile 64 rows -> smem 110592 B -> 2 CTAs/SM (16 warps).
// Block = 128 q-rows, 8 warps; warp w owns q-rows [16w,16w+16).
// ---------------------------------------------------------------------------
#define AROW 72
#define QTB  (128*AROW*2)     // 18432 B per Q tile
#define KTB  (64*AROW*2)      // 9216 B per K/V tile

__device__ __forceinline__ void tile_async64(uint32_t sbase, const __nv_bfloat16* g,
                                             int row0, int tid) {
#pragma unroll
    for (int t = 0; t < 2; t++) {
        int i  = tid + t * 256;       // 0..511
        int r  = i >> 3, c8 = i & 7;
        cpa16(sbase + (uint32_t)(r * AROW + c8 * 8) * 2,
              g + (size_t)(row0 + r) * HW + c8 * 8);
    }
}

__global__ __launch_bounds__(256, 2) void attn_mma(float* __restrict__ out)
{
    extern __shared__ unsigned short asm_[];
    const uint32_t base = smem_u32(asm_);
    const uint32_t qh32 = base;
    const uint32_t ql32 = base + QTB;
    const uint32_t kvbase = base + 2 * QTB;
    // buffer p tiles: Kh, Kl, Vh, Vl at kvbase + (4p + idx)*KTB

    const int bh = blockIdx.y;
    const int b  = bh >> 4;
    const int h  = bh & 15;
    const int qt = (int)gridDim.x - 1 - (int)blockIdx.x;  // heavy tiles first
    const int q0 = qt * 128;

    const int tid  = threadIdx.x;
    const int warp = tid >> 5;
    const int lane = tid & 31;
    const int g    = lane >> 2;
    const int t2   = (lane & 3) << 1;

    const float slope = exp2f(-0.5f * (float)(h + 1));

    const __nv_bfloat16* Qh = g_qh + (size_t)bh * SEQ * HW;
    const __nv_bfloat16* Ql = g_ql + (size_t)bh * SEQ * HW;
    const __nv_bfloat16* Kh = g_kh + (size_t)bh * SEQ * HW;
    const __nv_bfloat16* Kl = g_kl + (size_t)bh * SEQ * HW;
    const __nv_bfloat16* Vh = g_vh + (size_t)bh * SEQ * HW;
    const __nv_bfloat16* Vl = g_vl + (size_t)bh * SEQ * HW;

    // ---- load Q tile ----
#pragma unroll
    for (int t = 0; t < 4; t++) {
        int i = tid + t * 256;
        int r = i >> 3, c8 = i & 7;
        uint32_t soff = (uint32_t)(r * AROW + c8 * 8) * 2;
        *(uint4*)((char*)asm_ + soff) =
            *(const uint4*)(Qh + (size_t)(q0 + r) * HW + c8 * 8);
        *(uint4*)((char*)asm_ + QTB + soff) =
            *(const uint4*)(Ql + (size_t)(q0 + r) * HW + c8 * 8);
    }

    // ---- preload k-tile 0 ----
    tile_async64(kvbase + 0 * KTB, Kh, 0, tid);
    tile_async64(kvbase + 1 * KTB, Kl, 0, tid);
    tile_async64(kvbase + 2 * KTB, Vh, 0, tid);
    tile_async64(kvbase + 3 * KTB, Vl, 0, tid);
    CPA_COMMIT();

    const uint32_t aElem = (uint32_t)((warp * 16 + (lane & 15)) * AROW + ((lane >> 4) << 3));
    const uint32_t bElem = (uint32_t)(((lane & 7) + ((lane >> 4) << 3)) * AROW + (((lane >> 3) & 1) << 3));
    const uint32_t vElem = (uint32_t)((lane & 15) * AROW + ((lane >> 4) << 3));

    float oacc[8][4];
#pragma unroll
    for (int nf = 0; nf < 8; nf++)
#pragma unroll
        for (int e = 0; e < 4; e++) oacc[nf][e] = 0.0f;

    float m0r = -3e38f, m1r = -3e38f, l0 = 0.0f, l1 = 0.0f;
    const int row0 = q0 + warp * 16 + g;
    const int row1 = row0 + 8;

    const int nkt = 2 * qt + 2;
    for (int kt = 0; kt < nkt; kt++) {
        const int p = kt & 1;
        CPA_WAIT0();
        __syncthreads();

        if (kt + 1 < nkt) {
            uint32_t bn = kvbase + (uint32_t)(4 * (p ^ 1)) * KTB;
            int r0n = (kt + 1) * 64;
            tile_async64(bn + 0 * KTB, Kh, r0n, tid);
            tile_async64(bn + 1 * KTB, Kl, r0n, tid);
            tile_async64(bn + 2 * KTB, Vh, r0n, tid);
            tile_async64(bn + 3 * KTB, Vl, r0n, tid);
            CPA_COMMIT();
        }

        const uint32_t kh32 = kvbase + (uint32_t)(4 * p + 0) * KTB;
        const uint32_t kl32 = kvbase + (uint32_t)(4 * p + 1) * KTB;
        const uint32_t vh32 = kvbase + (uint32_t)(4 * p + 2) * KTB;
        const uint32_t vl32 = kvbase + (uint32_t)(4 * p + 3) * KTB;
        const int k0g = kt * 64;

        // ---- S = Q K^T (3-pass hi/lo), 128x64 tile ----
        float sacc[8][4];
#pragma unroll
        for (int nf = 0; nf < 8; nf++)
#pragma unroll
            for (int e = 0; e < 4; e++) sacc[nf][e] = 0.0f;

#pragma unroll
        for (int ks = 0; ks < 4; ks++) {
            uint32_t ah[4], al[4];
            ldm4(ah, qh32 + (aElem + ks * 16) * 2);
            ldm4(al, ql32 + (aElem + ks * 16) * 2);
#pragma unroll
            for (int pp = 0; pp < 4; pp++) {
                uint32_t bhx[4], blx[4];
                uint32_t bd = (bElem + (uint32_t)(pp * 16 * AROW) + (uint32_t)(ks * 16)) * 2;
                ldm4(bhx, kh32 + bd);
                ldm4(blx, kl32 + bd);
                mma_bf16(sacc[2*pp],   ah, bhx[0], bhx[1]);
                mma_bf16(sacc[2*pp],   al, bhx[0], bhx[1]);
                mma_bf16(sacc[2*pp],   ah, blx[0], blx[1]);
                mma_bf16(sacc[2*pp+1], ah, bhx[2], bhx[3]);
                mma_bf16(sacc[2*pp+1], al, bhx[2], bhx[3]);
                mma_bf16(sacc[2*pp+1], ah, blx[2], blx[3]);
            }
        }

        // ---- scale + ALiBi + causal; online softmax ----
        const bool diag = (kt >= 2 * qt);
        float mx0 = -3e38f, mx1 = -3e38f;
#pragma unroll
        for (int nf = 0; nf < 8; nf++) {
            int c0 = k0g + nf * 8 + t2;
            int c1 = c0 + 1;
            float v0 = sacc[nf][0] * SM_SCALE + slope * (float)(c0 - row0);
            float v1 = sacc[nf][1] * SM_SCALE + slope * (float)(c1 - row0);
            float v2 = sacc[nf][2] * SM_SCALE + slope * (float)(c0 - row1);
            float v3 = sacc[nf][3] * SM_SCALE + slope * (float)(c1 - row1);
            if (diag) {
                if (c0 > row0) v0 = -3e38f;
                if (c1 > row0) v1 = -3e38f;
                if (c0 > row1) v2 = -3e38f;
                if (c1 > row1) v3 = -3e38f;
            }
            sacc[nf][0] = v0; sacc[nf][1] = v1; sacc[nf][2] = v2; sacc[nf][3] = v3;
            mx0 = fmaxf(mx0, fmaxf(v0, v1));
            mx1 = fmaxf(mx1, fmaxf(v2, v3));
        }
        mx0 = fmaxf(mx0, __shfl_xor_sync(0xffffffffu, mx0, 1));
        mx0 = fmaxf(mx0, __shfl_xor_sync(0xffffffffu, mx0, 2));
        mx1 = fmaxf(mx1, __shfl_xor_sync(0xffffffffu, mx1, 1));
        mx1 = fmaxf(mx1, __shfl_xor_sync(0xffffffffu, mx1, 2));

        float mn0 = fmaxf(m0r, mx0);
        float mn1 = fmaxf(m1r, mx1);
        float corr0 = __expf(m0r - mn0);
        float corr1 = __expf(m1r - mn1);
        m0r = mn0; m1r = mn1;

        float rs0 = 0.0f, rs1 = 0.0f;
#pragma unroll
        for (int nf = 0; nf < 8; nf++) {
            float p0 = __expf(sacc[nf][0] - mn0);
            float p1 = __expf(sacc[nf][1] - mn0);
            float p2 = __expf(sacc[nf][2] - mn1);
            float p3 = __expf(sacc[nf][3] - mn1);
            sacc[nf][0] = p0; sacc[nf][1] = p1; sacc[nf][2] = p2; sacc[nf][3] = p3;
            rs0 += p0 + p1; rs1 += p2 + p3;
        }
        rs0 += __shfl_xor_sync(0xffffffffu, rs0, 1);
        rs0 += __shfl_xor_sync(0xffffffffu, rs0, 2);
        rs1 += __shfl_xor_sync(0xffffffffu, rs1, 1);
        rs1 += __shfl_xor_sync(0xffffffffu, rs1, 2);
        l0 = l0 * corr0 + rs0;
        l1 = l1 * corr1 + rs1;

#pragma unroll
        for (int nf = 0; nf < 8; nf++) {
            oacc[nf][0] *= corr0; oacc[nf][1] *= corr0;
            oacc[nf][2] *= corr1; oacc[nf][3] *= corr1;
        }

        // ---- O += P V (3-pass hi/lo, P packed from registers) ----
#pragma unroll
        for (int ks = 0; ks < 4; ks++) {
            uint32_t pah[4], pal[4];
            float r0, r1;
            pah[0] = packhi(sacc[2*ks][0],   sacc[2*ks][1],   r0, r1); pal[0] = packlo(r0, r1);
            pah[1] = packhi(sacc[2*ks][2],   sacc[2*ks][3],   r0, r1); pal[1] = packlo(r0, r1);
            pah[2] = packhi(sacc[2*ks+1][0], sacc[2*ks+1][1], r0, r1); pal[2] = packlo(r0, r1);
            pah[3] = packhi(sacc[2*ks+1][2], sacc[2*ks+1][3], r0, r1); pal[3] = packlo(r0, r1);
#pragma unroll
            for (int nb = 0; nb < 4; nb++) {
                uint32_t bhx[4], blx[4];
                uint32_t vd = (vElem + (uint32_t)(ks * 16 * AROW) + (uint32_t)(nb * 16)) * 2;
                ldm4t(bhx, vh32 + vd);
                ldm4t(blx, vl32 + vd);
                mma_bf16(oacc[2*nb],   pah, bhx[0], bhx[1]);
                mma_bf16(oacc[2*nb],   pal, bhx[0], bhx[1]);
                mma_bf16(oacc[2*nb],   pah, blx[0], blx[1]);
                mma_bf16(oacc[2*nb+1], pah, bhx[2], bhx[3]);
                mma_bf16(oacc[2*nb+1], pal, bhx[2], bhx[3]);
                mma_bf16(oacc[2*nb+1], pah, blx[2], blx[3]);
            }
        }
    }

    // ---- epilogue ----
    const float inv0 = 1.0f / l0;
    const float inv1 = 1.0f / l1;
    float* op = out + (size_t)b * SEQ * DM + (size_t)h * HW;
#pragma unroll
    for (int nf = 0; nf < 8; nf++) {
        int col = nf * 8 + t2;
        *(float2*)(op + (size_t)row0 * DM + col) =
            make_float2(oacc[nf][0] * inv0, oacc[nf][1] * inv0);
        *(float2*)(op + (size_t)row1 * DM + col) =
            make_float2(oacc[nf][2] * inv1, oacc[nf][3] * inv1);
    }
}

// ---------------------------------------------------------------------------
// Launch: inputs order = queries, keys, values, mask, Wq, Wk, Wv.
// ---------------------------------------------------------------------------
extern "C" void kernel_launch(void* const* d_in, const int* in_sizes, int n_in,
                              void* d_out, int out_size)
{
    (void)in_sizes; (void)n_in; (void)out_size;
    const float4* q  = (const float4*)d_in[0];
    const float4* k  = (const float4*)d_in[1];
    const float4* v  = (const float4*)d_in[2];
    const float4* wq = (const float4*)d_in[4];
    const float4* wk = (const float4*)d_in[5];
    const float4* wv = (const float4*)d_in[6];
    float* out = (float*)d_out;

    const int proj_smem = 8 * PTILEB;          // 81920 B
    cudaFuncSetAttribute(proj_mma, cudaFuncAttributeMaxDynamicSharedMemorySize, proj_smem);
    const int attn_smem = 2 * QTB + 8 * KTB;   // 110592 B
    cudaFuncSetAttribute(attn_mma, cudaFuncAttributeMaxDynamicSharedMemorySize, attn_smem);

    split_kernel<<<dim3(4096, 6), 256>>>(q, k, v, wq, wk, wv);
    proj_mma<<<dim3(DM/128, (BATCH*SEQ)/128, 3), 256, proj_smem>>>();
    attn_mma<<<dim3(SEQ/128, BATCH*NH), 256, attn_smem>>>(out);
}

// round 9
// speedup vs baseline: 1.1346x; 1.0665x over previous
#include <cuda_runtime.h>
#include <cuda_bf16.h>
#include <cstdint>
#include <math.h>

#define BATCH 2
#define SEQ   2048
#define DM    1024
#define NH    16
#define HW    64
#define SM_SCALE 0.125f   // 1/sqrt(64)

#define NELEM (BATCH*NH*SEQ*HW)
#define XN    (BATCH*SEQ*DM)
#define WN    (DM*DM)

// Pre-split bf16 hi/lo planes of projected Q/K/V in [B, H, S, hw] layout.
__device__ __nv_bfloat16 g_qh[NELEM], g_ql[NELEM];
__device__ __nv_bfloat16 g_kh[NELEM], g_kl[NELEM];
__device__ __nv_bfloat16 g_vh[NELEM], g_vl[NELEM];
// Pre-split bf16 hi/lo planes of inputs X (q,k,v) and weights W (q,k,v).
__device__ __nv_bfloat16 g_xh[3*XN], g_xl[3*XN];
__device__ __nv_bfloat16 g_wh[3*WN], g_wl[3*WN];

// ---------------------------------------------------------------------------
// Helpers
// ---------------------------------------------------------------------------
__device__ __forceinline__ uint32_t smem_u32(const void* p) {
    uint32_t a;
    asm("{ .reg .u64 t; cvta.to.shared.u64 t, %1; cvt.u32.u64 %0, t; }"
        : "=r"(a) : "l"(p));
    return a;
}

__device__ __forceinline__ void ldm4(uint32_t r[4], uint32_t addr) {
    asm volatile("ldmatrix.sync.aligned.m8n8.x4.shared.b16 {%0,%1,%2,%3}, [%4];"
                 : "=r"(r[0]), "=r"(r[1]), "=r"(r[2]), "=r"(r[3]) : "r"(addr));
}
__device__ __forceinline__ void ldm4t(uint32_t r[4], uint32_t addr) {
    asm volatile("ldmatrix.sync.aligned.m8n8.x4.trans.shared.b16 {%0,%1,%2,%3}, [%4];"
                 : "=r"(r[0]), "=r"(r[1]), "=r"(r[2]), "=r"(r[3]) : "r"(addr));
}

__device__ __forceinline__ void mma_bf16(float acc[4], const uint32_t a[4],
                                         uint32_t b0, uint32_t b1) {
    asm volatile(
        "mma.sync.aligned.m16n8k16.row.col.f32.bf16.bf16.f32 "
        "{%0,%1,%2,%3}, {%4,%5,%6,%7}, {%8,%9}, {%0,%1,%2,%3};"
        : "+f"(acc[0]), "+f"(acc[1]), "+f"(acc[2]), "+f"(acc[3])
        : "r"(a[0]), "r"(a[1]), "r"(a[2]), "r"(a[3]), "r"(b0), "r"(b1));
}

__device__ __forceinline__ uint32_t packhi(float a, float b, float& ra, float& rb) {
    __nv_bfloat16 ha = __float2bfloat16(a);
    __nv_bfloat16 hb = __float2bfloat16(b);
    ra = a - __bfloat162float(ha);
    rb = b - __bfloat162float(hb);
    return (uint32_t)__bfloat16_as_ushort(ha) |
           ((uint32_t)__bfloat16_as_ushort(hb) << 16);
}
__device__ __forceinline__ uint32_t packlo(float a, float b) {
    return (uint32_t)__bfloat16_as_ushort(__float2bfloat16(a)) |
           ((uint32_t)__bfloat16_as_ushort(__float2bfloat16(b)) << 16);
}

__device__ __forceinline__ void cpa16(uint32_t saddr, const void* g) {
    asm volatile("cp.async.cg.shared.global [%0], [%1], 16;"
                 :: "r"(saddr), "l"(g) : "memory");
}
#define CPA_COMMIT() asm volatile("cp.async.commit_group;" ::: "memory")
#define CPA_WAIT0()  asm volatile("cp.async.wait_group 0;" ::: "memory")

// ---------------------------------------------------------------------------
// Split inputs/weights into bf16 hi/lo planes (one bandwidth pass).
// ---------------------------------------------------------------------------
__global__ __launch_bounds__(256) void split_kernel(
    const float4* __restrict__ xq, const float4* __restrict__ xk,
    const float4* __restrict__ xv, const float4* __restrict__ wq,
    const float4* __restrict__ wk, const float4* __restrict__ wv)
{
    const int y = blockIdx.y;
    const float4* src;
    __nv_bfloat16 *dh, *dl;
    if (y < 3) {
        src = (y == 0) ? xq : (y == 1) ? xk : xv;
        dh = g_xh + (size_t)y * XN;
        dl = g_xl + (size_t)y * XN;
    } else {
        if (blockIdx.x >= 1024) return;
        int w = y - 3;
        src = (w == 0) ? wq : (w == 1) ? wk : wv;
        dh = g_wh + (size_t)w * WN;
        dl = g_wl + (size_t)w * WN;
    }
    size_t i = (size_t)blockIdx.x * 256 + threadIdx.x;
    float4 a = src[i];
    float r0, r1, r2, r3;
    uint32_t h01 = packhi(a.x, a.y, r0, r1);
    uint32_t h23 = packhi(a.z, a.w, r2, r3);
    *(uint2*)(dh + i * 4) = make_uint2(h01, h23);
    *(uint2*)(dl + i * 4) = make_uint2(packlo(r0, r1), packlo(r2, r3));
}

// ---------------------------------------------------------------------------
// Projection GEMM on mma.sync bf16 (hi/lo 3-pass), pure-bf16 mainloop.
// CTA tile 128(M) x 64(N), warp tile 32x32, 8 warps (4M x 2N).
// ~100 regs/thread -> genuine 2 CTAs/SM without spills.
// grid = (16, 32, 3), block = 256. smem 2 x 30720 = 61440 B.
// ---------------------------------------------------------------------------
#define SROW   40
#define PA_TB  (128*SROW*2)   // 10240 B per A tile
#define PB_TB  (64*SROW*2)    // 5120 B per B tile
#define PBUF   (2*PA_TB + 2*PB_TB)  // 30720 B per stage

__global__ __launch_bounds__(256, 2) void proj_mma()
{
    extern __shared__ unsigned short psm[];
    const uint32_t base = smem_u32(psm);

    const int z = blockIdx.z;
    const __nv_bfloat16* Ah = g_xh + (size_t)z * XN;
    const __nv_bfloat16* Al = g_xl + (size_t)z * XN;
    const __nv_bfloat16* Bh = g_wh + (size_t)z * WN;
    const __nv_bfloat16* Bl = g_wl + (size_t)z * WN;
    __nv_bfloat16* Oh = (z == 0) ? g_qh : (z == 1) ? g_kh : g_vh;
    __nv_bfloat16* Ol = (z == 0) ? g_ql : (z == 1) ? g_kl : g_vl;

    const int tid   = threadIdx.x;
    const int wid   = tid >> 5;
    const int lane  = tid & 31;
    const int warpM = wid >> 1;      // 0..3 -> 32 rows each
    const int warpN = wid & 1;       // 0..1 -> 32 cols each
    const int m0    = blockIdx.y * 128;
    const int n0    = blockIdx.x * 64;

    const uint32_t aOff = ((uint32_t)(warpM * 32 + (lane & 15)) * SROW +
                           ((uint32_t)(lane >> 4) << 3)) * 2;
    const uint32_t bOff = ((uint32_t)(warpN * 32 + (lane & 7) + ((lane >> 4) << 3)) * SROW +
                           (((uint32_t)(lane >> 3) & 1) << 3)) * 2;

    float acc[2][4][4];
#pragma unroll
    for (int mf = 0; mf < 2; mf++)
#pragma unroll
        for (int nf = 0; nf < 4; nf++)
#pragma unroll
            for (int i = 0; i < 4; i++) acc[mf][nf][i] = 0.0f;

    // cp.async coords: A = 512 x 16B (2/thread), B = 256 x 16B (1/thread).
    const int ar = tid >> 2, ac = tid & 3;

    auto load_chunk = [&](int c, int p) {
        const uint32_t bb = base + (uint32_t)p * PBUF;
        const int k0 = c * 32;
#pragma unroll
        for (int t = 0; t < 2; t++) {
            int i = tid + t * 256;
            int r = i >> 2, c8 = i & 3;
            uint32_t soff = (uint32_t)(r * SROW + c8 * 8) * 2;
            size_t ga = (size_t)(m0 + r) * DM + k0 + c8 * 8;
            cpa16(bb + soff, Ah + ga);
            cpa16(bb + PA_TB + soff, Al + ga);
        }
        {
            uint32_t soff = (uint32_t)(ar * SROW + ac * 8) * 2;
            size_t gb = (size_t)(n0 + ar) * DM + k0 + ac * 8;
            cpa16(bb + 2 * PA_TB + soff, Bh + gb);
            cpa16(bb + 2 * PA_TB + PB_TB + soff, Bl + gb);
        }
        CPA_COMMIT();
    };

    load_chunk(0, 0);

    for (int c = 0; c < 32; c++) {
        const int p = c & 1;
        CPA_WAIT0();
        __syncthreads();
        if (c < 31) load_chunk(c + 1, p ^ 1);

        const uint32_t ah32 = base + (uint32_t)p * PBUF;
        const uint32_t al32 = ah32 + PA_TB;
        const uint32_t bh32 = ah32 + 2 * PA_TB;
        const uint32_t bl32 = bh32 + PB_TB;

#pragma unroll
        for (int ks = 0; ks < 2; ks++) {
            const uint32_t kByte = (uint32_t)(ks * 32);
            uint32_t ah[2][4], al[2][4], bh[2][4], bl[2][4];
#pragma unroll
            for (int mf = 0; mf < 2; mf++) {
                uint32_t ad = aOff + (uint32_t)(mf * 16 * SROW * 2) + kByte;
                ldm4(ah[mf], ah32 + ad);
                ldm4(al[mf], al32 + ad);
            }
#pragma unroll
            for (int pp = 0; pp < 2; pp++) {
                uint32_t bd = bOff + (uint32_t)(pp * 16 * SROW * 2) + kByte;
                ldm4(bh[pp], bh32 + bd);
                ldm4(bl[pp], bl32 + bd);
            }
#pragma unroll
            for (int mf = 0; mf < 2; mf++)
#pragma unroll
                for (int nf = 0; nf < 4; nf++) {
                    const int pp = nf >> 1, q = (nf & 1) * 2;
                    mma_bf16(acc[mf][nf], ah[mf], bh[pp][q], bh[pp][q+1]);
                    mma_bf16(acc[mf][nf], al[mf], bh[pp][q], bh[pp][q+1]);
                    mma_bf16(acc[mf][nf], ah[mf], bl[pp][q], bl[pp][q+1]);
                }
        }
        __syncthreads();
    }

    // Epilogue: split fp32 acc -> bf16 hi/lo planes, [B, H, S, hw] layout.
    const int g  = lane >> 2;
    const int t2 = (lane & 3) << 1;
#pragma unroll
    for (int mf = 0; mf < 2; mf++) {
        int mA  = m0 + warpM * 32 + mf * 16 + g;
        int mB  = mA + 8;
        int bbA = mA >> 11, ssA = mA & (SEQ - 1);
        int bbB = mB >> 11, ssB = mB & (SEQ - 1);
#pragma unroll
        for (int nf = 0; nf < 4; nf++) {
            int n  = n0 + warpN * 32 + nf * 8 + t2;
            int hh = n >> 6, dd = n & 63;
            size_t offA = (((size_t)(bbA * NH + hh)) * SEQ + ssA) * HW + dd;
            size_t offB = (((size_t)(bbB * NH + hh)) * SEQ + ssB) * HW + dd;
            float r0, r1;
            uint32_t hp = packhi(acc[mf][nf][0], acc[mf][nf][1], r0, r1);
            *(uint32_t*)(Oh + offA) = hp;
            *(uint32_t*)(Ol + offA) = packlo(r0, r1);
            hp = packhi(acc[mf][nf][2], acc[mf][nf][3], r0, r1);
            *(uint32_t*)(Oh + offB) = hp;
            *(uint32_t*)(Ol + offB) = packlo(r0, r1);
        }
    }
}

// ---------------------------------------------------------------------------
// Flash attention on mma.sync bf16 (hi/lo 3-pass), causal + ALiBi.
// (unchanged from R8 passing kernel: 64-row K tiles, 2 CTAs/SM)
// ---------------------------------------------------------------------------
#define AROW 72
#define QTB  (128*AROW*2)
#define KTB  (64*AROW*2)

__device__ __forceinline__ void tile_async64(uint32_t sbase, const __nv_bfloat16* g,
                                             int row0, int tid) {
#pragma unroll
    for (int t = 0; t < 2; t++) {
        int i  = tid + t * 256;
        int r  = i >> 3, c8 = i & 7;
        cpa16(sbase + (uint32_t)(r * AROW + c8 * 8) * 2,
              g + (size_t)(row0 + r) * HW + c8 * 8);
    }
}

__global__ __launch_bounds__(256, 2) void attn_mma(float* __restrict__ out)
{
    extern __shared__ unsigned short asm_[];
    const uint32_t base = smem_u32(asm_);
    const uint32_t qh32 = base;
    const uint32_t ql32 = base + QTB;
    const uint32_t kvbase = base + 2 * QTB;

    const int bh = blockIdx.y;
    const int b  = bh >> 4;
    const int h  = bh & 15;
    const int qt = (int)gridDim.x - 1 - (int)blockIdx.x;
    const int q0 = qt * 128;

    const int tid  = threadIdx.x;
    const int warp = tid >> 5;
    const int lane = tid & 31;
    const int g    = lane >> 2;
    const int t2   = (lane & 3) << 1;

    const float slope = exp2f(-0.5f * (float)(h + 1));

    const __nv_bfloat16* Qh = g_qh + (size_t)bh * SEQ * HW;
    const __nv_bfloat16* Ql = g_ql + (size_t)bh * SEQ * HW;
    const __nv_bfloat16* Kh = g_kh + (size_t)bh * SEQ * HW;
    const __nv_bfloat16* Kl = g_kl + (size_t)bh * SEQ * HW;
    const __nv_bfloat16* Vh = g_vh + (size_t)bh * SEQ * HW;
    const __nv_bfloat16* Vl = g_vl + (size_t)bh * SEQ * HW;

#pragma unroll
    for (int t = 0; t < 4; t++) {
        int i = tid + t * 256;
        int r = i >> 3, c8 = i & 7;
        uint32_t soff = (uint32_t)(r * AROW + c8 * 8) * 2;
        *(uint4*)((char*)asm_ + soff) =
            *(const uint4*)(Qh + (size_t)(q0 + r) * HW + c8 * 8);
        *(uint4*)((char*)asm_ + QTB + soff) =
            *(const uint4*)(Ql + (size_t)(q0 + r) * HW + c8 * 8);
    }

    tile_async64(kvbase + 0 * KTB, Kh, 0, tid);
    tile_async64(kvbase + 1 * KTB, Kl, 0, tid);
    tile_async64(kvbase + 2 * KTB, Vh, 0, tid);
    tile_async64(kvbase + 3 * KTB, Vl, 0, tid);
    CPA_COMMIT();

    const uint32_t aElem = (uint32_t)((warp * 16 + (lane & 15)) * AROW + ((lane >> 4) << 3));
    const uint32_t bElem = (uint32_t)(((lane & 7) + ((lane >> 4) << 3)) * AROW + (((lane >> 3) & 1) << 3));
    const uint32_t vElem = (uint32_t)((lane & 15) * AROW + ((lane >> 4) << 3));

    float oacc[8][4];
#pragma unroll
    for (int nf = 0; nf < 8; nf++)
#pragma unroll
        for (int e = 0; e < 4; e++) oacc[nf][e] = 0.0f;

    float m0r = -3e38f, m1r = -3e38f, l0 = 0.0f, l1 = 0.0f;
    const int row0 = q0 + warp * 16 + g;
    const int row1 = row0 + 8;

    const int nkt = 2 * qt + 2;
    for (int kt = 0; kt < nkt; kt++) {
        const int p = kt & 1;
        CPA_WAIT0();
        __syncthreads();

        if (kt + 1 < nkt) {
            uint32_t bn = kvbase + (uint32_t)(4 * (p ^ 1)) * KTB;
            int r0n = (kt + 1) * 64;
            tile_async64(bn + 0 * KTB, Kh, r0n, tid);
            tile_async64(bn + 1 * KTB, Kl, r0n, tid);
            tile_async64(bn + 2 * KTB, Vh, r0n, tid);
            tile_async64(bn + 3 * KTB, Vl, r0n, tid);
            CPA_COMMIT();
        }

        const uint32_t kh32 = kvbase + (uint32_t)(4 * p + 0) * KTB;
        const uint32_t kl32 = kvbase + (uint32_t)(4 * p + 1) * KTB;
        const uint32_t vh32 = kvbase + (uint32_t)(4 * p + 2) * KTB;
        const uint32_t vl32 = kvbase + (uint32_t)(4 * p + 3) * KTB;
        const int k0g = kt * 64;

        float sacc[8][4];
#pragma unroll
        for (int nf = 0; nf < 8; nf++)
#pragma unroll
            for (int e = 0; e < 4; e++) sacc[nf][e] = 0.0f;

#pragma unroll
        for (int ks = 0; ks < 4; ks++) {
            uint32_t ah[4], al[4];
            ldm4(ah, qh32 + (aElem + ks * 16) * 2);
            ldm4(al, ql32 + (aElem + ks * 16) * 2);
#pragma unroll
            for (int pp = 0; pp < 4; pp++) {
                uint32_t bhx[4], blx[4];
                uint32_t bd = (bElem + (uint32_t)(pp * 16 * AROW) + (uint32_t)(ks * 16)) * 2;
                ldm4(bhx, kh32 + bd);
                ldm4(blx, kl32 + bd);
                mma_bf16(sacc[2*pp],   ah, bhx[0], bhx[1]);
                mma_bf16(sacc[2*pp],   al, bhx[0], bhx[1]);
                mma_bf16(sacc[2*pp],   ah, blx[0], blx[1]);
                mma_bf16(sacc[2*pp+1], ah, bhx[2], bhx[3]);
                mma_bf16(sacc[2*pp+1], al, bhx[2], bhx[3]);
                mma_bf16(sacc[2*pp+1], ah, blx[2], blx[3]);
            }
        }

        const bool diag = (kt >= 2 * qt);
        float mx0 = -3e38f, mx1 = -3e38f;
#pragma unroll
        for (int nf = 0; nf < 8; nf++) {
            int c0 = k0g + nf * 8 + t2;
            int c1 = c0 + 1;
            float v0 = sacc[nf][0] * SM_SCALE + slope * (float)(c0 - row0);
            float v1 = sacc[nf][1] * SM_SCALE + slope * (float)(c1 - row0);
            float v2 = sacc[nf][2] * SM_SCALE + slope * (float)(c0 - row1);
            float v3 = sacc[nf][3] * SM_SCALE + slope * (float)(c1 - row1);
            if (diag) {
                if (c0 > row0) v0 = -3e38f;
                if (c1 > row0) v1 = -3e38f;
                if (c0 > row1) v2 = -3e38f;
                if (c1 > row1) v3 = -3e38f;
            }
            sacc[nf][0] = v0; sacc[nf][1] = v1; sacc[nf][2] = v2; sacc[nf][3] = v3;
            mx0 = fmaxf(mx0, fmaxf(v0, v1));
            mx1 = fmaxf(mx1, fmaxf(v2, v3));
        }
        mx0 = fmaxf(mx0, __shfl_xor_sync(0xffffffffu, mx0, 1));
        mx0 = fmaxf(mx0, __shfl_xor_sync(0xffffffffu, mx0, 2));
        mx1 = fmaxf(mx1, __shfl_xor_sync(0xffffffffu, mx1, 1));
        mx1 = fmaxf(mx1, __shfl_xor_sync(0xffffffffu, mx1, 2));

        float mn0 = fmaxf(m0r, mx0);
        float mn1 = fmaxf(m1r, mx1);
        float corr0 = __expf(m0r - mn0);
        float corr1 = __expf(m1r - mn1);
        m0r = mn0; m1r = mn1;

        float rs0 = 0.0f, rs1 = 0.0f;
#pragma unroll
        for (int nf = 0; nf < 8; nf++) {
            float p0 = __expf(sacc[nf][0] - mn0);
            float p1 = __expf(sacc[nf][1] - mn0);
            float p2 = __expf(sacc[nf][2] - mn1);
            float p3 = __expf(sacc[nf][3] - mn1);
            sacc[nf][0] = p0; sacc[nf][1] = p1; sacc[nf][2] = p2; sacc[nf][3] = p3;
            rs0 += p0 + p1; rs1 += p2 + p3;
        }
        rs0 += __shfl_xor_sync(0xffffffffu, rs0, 1);
        rs0 += __shfl_xor_sync(0xffffffffu, rs0, 2);
        rs1 += __shfl_xor_sync(0xffffffffu, rs1, 1);
        rs1 += __shfl_xor_sync(0xffffffffu, rs1, 2);
        l0 = l0 * corr0 + rs0;
        l1 = l1 * corr1 + rs1;

#pragma unroll
        for (int nf = 0; nf < 8; nf++) {
            oacc[nf][0] *= corr0; oacc[nf][1] *= corr0;
            oacc[nf][2] *= corr1; oacc[nf][3] *= corr1;
        }

#pragma unroll
        for (int ks = 0; ks < 4; ks++) {
            uint32_t pah[4], pal[4];
            float r0, r1;
            pah[0] = packhi(sacc[2*ks][0],   sacc[2*ks][1],   r0, r1); pal[0] = packlo(r0, r1);
            pah[1] = packhi(sacc[2*ks][2],   sacc[2*ks][3],   r0, r1); pal[1] = packlo(r0, r1);
            pah[2] = packhi(sacc[2*ks+1][0], sacc[2*ks+1][1], r0, r1); pal[2] = packlo(r0, r1);
            pah[3] = packhi(sacc[2*ks+1][2], sacc[2*ks+1][3], r0, r1); pal[3] = packlo(r0, r1);
#pragma unroll
            for (int nb = 0; nb < 4; nb++) {
                uint32_t bhx[4], blx[4];
                uint32_t vd = (vElem + (uint32_t)(ks * 16 * AROW) + (uint32_t)(nb * 16)) * 2;
                ldm4t(bhx, vh32 + vd);
                ldm4t(blx, vl32 + vd);
                mma_bf16(oacc[2*nb],   pah, bhx[0], bhx[1]);
                mma_bf16(oacc[2*nb],   pal, bhx[0], bhx[1]);
                mma_bf16(oacc[2*nb],   pah, blx[0], blx[1]);
                mma_bf16(oacc[2*nb+1], pah, bhx[2], bhx[3]);
                mma_bf16(oacc[2*nb+1], pal, bhx[2], bhx[3]);
                mma_bf16(oacc[2*nb+1], pah, blx[2], blx[3]);
            }
        }
    }

    const float inv0 = 1.0f / l0;
    const float inv1 = 1.0f / l1;
    float* op = out + (size_t)b * SEQ * DM + (size_t)h * HW;
#pragma unroll
    for (int nf = 0; nf < 8; nf++) {
        int col = nf * 8 + t2;
        *(float2*)(op + (size_t)row0 * DM + col) =
            make_float2(oacc[nf][0] * inv0, oacc[nf][1] * inv0);
        *(float2*)(op + (size_t)row1 * DM + col) =
            make_float2(oacc[nf][2] * inv1, oacc[nf][3] * inv1);
    }
}

// ---------------------------------------------------------------------------
// Launch: inputs order = queries, keys, values, mask, Wq, Wk, Wv.
// ---------------------------------------------------------------------------
extern "C" void kernel_launch(void* const* d_in, const int* in_sizes, int n_in,
                              void* d_out, int out_size)
{
    (void)in_sizes; (void)n_in; (void)out_size;
    const float4* q  = (const float4*)d_in[0];
    const float4* k  = (const float4*)d_in[1];
    const float4* v  = (const float4*)d_in[2];
    const float4* wq = (const float4*)d_in[4];
    const float4* wk = (const float4*)d_in[5];
    const float4* wv = (const float4*)d_in[6];
    float* out = (float*)d_out;

    const int proj_smem = 2 * PBUF;            // 61440 B
    cudaFuncSetAttribute(proj_mma, cudaFuncAttributeMaxDynamicSharedMemorySize, proj_smem);
    const int attn_smem = 2 * QTB + 8 * KTB;   // 110592 B
    cudaFuncSetAttribute(attn_mma, cudaFuncAttributeMaxDynamicSharedMemorySize, attn_smem);

    split_kernel<<<dim3(4096, 6), 256>>>(q, k, v, wq, wk, wv);
    proj_mma<<<dim3(DM/64, (BATCH*SEQ)/128, 3), 256, proj_smem>>>();
    attn_mma<<<dim3(SEQ/128, BATCH*NH), 256, attn_smem>>>(out);
}

// round 10
// speedup vs baseline: 1.3165x; 1.1604x over previous
#include <cuda_runtime.h>
#include <cuda_bf16.h>
#include <cuda_fp16.h>
#include <cstdint>
#include <math.h>

#define BATCH 2
#define SEQ   2048
#define DM    1024
#define NH    16
#define HW    64
#define SM_SCALE 0.125f   // 1/sqrt(64)
#define L2E   1.44269504f

#define NELEM (BATCH*NH*SEQ*HW)
#define XN    (BATCH*SEQ*DM)
#define WN    (DM*DM)

// Projected Q (fp16 hi+lo), K/V (fp16 hi only) in [B, H, S, hw] layout.
__device__ __half g_qh[NELEM], g_ql[NELEM];
__device__ __half g_kh[NELEM];
__device__ __half g_vh[NELEM];
// Pre-split bf16 hi/lo planes of inputs X (q,k,v) and weights W (q,k,v).
__device__ __nv_bfloat16 g_xh[3*XN], g_xl[3*XN];
__device__ __nv_bfloat16 g_wh[3*WN], g_wl[3*WN];

// ---------------------------------------------------------------------------
// Helpers
// ---------------------------------------------------------------------------
__device__ __forceinline__ uint32_t smem_u32(const void* p) {
    uint32_t a;
    asm("{ .reg .u64 t; cvta.to.shared.u64 t, %1; cvt.u32.u64 %0, t; }"
        : "=r"(a) : "l"(p));
    return a;
}

__device__ __forceinline__ void ldm4(uint32_t r[4], uint32_t addr) {
    asm volatile("ldmatrix.sync.aligned.m8n8.x4.shared.b16 {%0,%1,%2,%3}, [%4];"
                 : "=r"(r[0]), "=r"(r[1]), "=r"(r[2]), "=r"(r[3]) : "r"(addr));
}
__device__ __forceinline__ void ldm4t(uint32_t r[4], uint32_t addr) {
    asm volatile("ldmatrix.sync.aligned.m8n8.x4.trans.shared.b16 {%0,%1,%2,%3}, [%4];"
                 : "=r"(r[0]), "=r"(r[1]), "=r"(r[2]), "=r"(r[3]) : "r"(addr));
}

__device__ __forceinline__ void mma_bf16(float acc[4], const uint32_t a[4],
                                         uint32_t b0, uint32_t b1) {
    asm volatile(
        "mma.sync.aligned.m16n8k16.row.col.f32.bf16.bf16.f32 "
        "{%0,%1,%2,%3}, {%4,%5,%6,%7}, {%8,%9}, {%0,%1,%2,%3};"
        : "+f"(acc[0]), "+f"(acc[1]), "+f"(acc[2]), "+f"(acc[3])
        : "r"(a[0]), "r"(a[1]), "r"(a[2]), "r"(a[3]), "r"(b0), "r"(b1));
}
__device__ __forceinline__ void mma_f16(float acc[4], const uint32_t a[4],
                                        uint32_t b0, uint32_t b1) {
    asm volatile(
        "mma.sync.aligned.m16n8k16.row.col.f32.f16.f16.f32 "
        "{%0,%1,%2,%3}, {%4,%5,%6,%7}, {%8,%9}, {%0,%1,%2,%3};"
        : "+f"(acc[0]), "+f"(acc[1]), "+f"(acc[2]), "+f"(acc[3])
        : "r"(a[0]), "r"(a[1]), "r"(a[2]), "r"(a[3]), "r"(b0), "r"(b1));
}

// bf16 hi/lo split (proj internals)
__device__ __forceinline__ uint32_t packhi(float a, float b, float& ra, float& rb) {
    __nv_bfloat16 ha = __float2bfloat16(a);
    __nv_bfloat16 hb = __float2bfloat16(b);
    ra = a - __bfloat162float(ha);
    rb = b - __bfloat162float(hb);
    return (uint32_t)__bfloat16_as_ushort(ha) |
           ((uint32_t)__bfloat16_as_ushort(hb) << 16);
}
__device__ __forceinline__ uint32_t packlo(float a, float b) {
    return (uint32_t)__bfloat16_as_ushort(__float2bfloat16(a)) |
           ((uint32_t)__bfloat16_as_ushort(__float2bfloat16(b)) << 16);
}
// fp16 hi/lo split (attention operands)
__device__ __forceinline__ uint32_t packhi_h(float a, float b, float& ra, float& rb) {
    __half2 h = __floats2half2_rn(a, b);
    ra = a - __half2float(__low2half(h));
    rb = b - __half2float(__high2half(h));
    return *reinterpret_cast<uint32_t*>(&h);
}
__device__ __forceinline__ uint32_t packlo_h(float a, float b) {
    __half2 h = __floats2half2_rn(a, b);
    return *reinterpret_cast<uint32_t*>(&h);
}

__device__ __forceinline__ void cpa16(uint32_t saddr, const void* g) {
    asm volatile("cp.async.cg.shared.global [%0], [%1], 16;"
                 :: "r"(saddr), "l"(g) : "memory");
}
#define CPA_COMMIT() asm volatile("cp.async.commit_group;" ::: "memory")
#define CPA_WAIT0()  asm volatile("cp.async.wait_group 0;" ::: "memory")
#define CPA_WAIT1()  asm volatile("cp.async.wait_group 1;" ::: "memory")

// ---------------------------------------------------------------------------
// Split inputs/weights into bf16 hi/lo planes (one bandwidth pass).
// ---------------------------------------------------------------------------
__global__ __launch_bounds__(256) void split_kernel(
    const float4* __restrict__ xq, const float4* __restrict__ xk,
    const float4* __restrict__ xv, const float4* __restrict__ wq,
    const float4* __restrict__ wk, const float4* __restrict__ wv)
{
    const int y = blockIdx.y;
    const float4* src;
    __nv_bfloat16 *dh, *dl;
    if (y < 3) {
        src = (y == 0) ? xq : (y == 1) ? xk : xv;
        dh = g_xh + (size_t)y * XN;
        dl = g_xl + (size_t)y * XN;
    } else {
        if (blockIdx.x >= 1024) return;
        int w = y - 3;
        src = (w == 0) ? wq : (w == 1) ? wk : wv;
        dh = g_wh + (size_t)w * WN;
        dl = g_wl + (size_t)w * WN;
    }
    size_t i = (size_t)blockIdx.x * 256 + threadIdx.x;
    float4 a = src[i];
    float r0, r1, r2, r3;
    uint32_t h01 = packhi(a.x, a.y, r0, r1);
    uint32_t h23 = packhi(a.z, a.w, r2, r3);
    *(uint2*)(dh + i * 4) = make_uint2(h01, h23);
    *(uint2*)(dl + i * 4) = make_uint2(packlo(r0, r1), packlo(r2, r3));
}

// ---------------------------------------------------------------------------
// Projection GEMM on mma.sync bf16 (hi/lo 3-pass), pure-bf16 mainloop.
// CTA 128x64, warp tile 32x32, 8 warps (4M x 2N), 2 CTAs/SM.
// Epilogue: fp16 hi (+lo for Q only) planes for the attention kernel.
// ---------------------------------------------------------------------------
#define SROW   40
#define PA_TB  (128*SROW*2)
#define PB_TB  (64*SROW*2)
#define PBUF   (2*PA_TB + 2*PB_TB)  // 30720 B per stage

__global__ __launch_bounds__(256, 2) void proj_mma()
{
    extern __shared__ unsigned short psm[];
    const uint32_t base = smem_u32(psm);

    const int z = blockIdx.z;
    const __nv_bfloat16* Ah = g_xh + (size_t)z * XN;
    const __nv_bfloat16* Al = g_xl + (size_t)z * XN;
    const __nv_bfloat16* Bh = g_wh + (size_t)z * WN;
    const __nv_bfloat16* Bl = g_wl + (size_t)z * WN;
    __half* Oh = (z == 0) ? g_qh : (z == 1) ? g_kh : g_vh;

    const int tid   = threadIdx.x;
    const int wid   = tid >> 5;
    const int lane  = tid & 31;
    const int warpM = wid >> 1;
    const int warpN = wid & 1;
    const int m0    = blockIdx.y * 128;
    const int n0    = blockIdx.x * 64;

    const uint32_t aOff = ((uint32_t)(warpM * 32 + (lane & 15)) * SROW +
                           ((uint32_t)(lane >> 4) << 3)) * 2;
    const uint32_t bOff = ((uint32_t)(warpN * 32 + (lane & 7) + ((lane >> 4) << 3)) * SROW +
                           (((uint32_t)(lane >> 3) & 1) << 3)) * 2;

    float acc[2][4][4];
#pragma unroll
    for (int mf = 0; mf < 2; mf++)
#pragma unroll
        for (int nf = 0; nf < 4; nf++)
#pragma unroll
            for (int i = 0; i < 4; i++) acc[mf][nf][i] = 0.0f;

    const int ar = tid >> 2, ac = tid & 3;

    auto load_chunk = [&](int c, int p) {
        const uint32_t bb = base + (uint32_t)p * PBUF;
        const int k0 = c * 32;
#pragma unroll
        for (int t = 0; t < 2; t++) {
            int i = tid + t * 256;
            int r = i >> 2, c8 = i & 3;
            uint32_t soff = (uint32_t)(r * SROW + c8 * 8) * 2;
            size_t ga = (size_t)(m0 + r) * DM + k0 + c8 * 8;
            cpa16(bb + soff, Ah + ga);
            cpa16(bb + PA_TB + soff, Al + ga);
        }
        {
            uint32_t soff = (uint32_t)(ar * SROW + ac * 8) * 2;
            size_t gb = (size_t)(n0 + ar) * DM + k0 + ac * 8;
            cpa16(bb + 2 * PA_TB + soff, Bh + gb);
            cpa16(bb + 2 * PA_TB + PB_TB + soff, Bl + gb);
        }
        CPA_COMMIT();
    };

    load_chunk(0, 0);

    for (int c = 0; c < 32; c++) {
        const int p = c & 1;
        CPA_WAIT0();
        __syncthreads();
        if (c < 31) load_chunk(c + 1, p ^ 1);

        const uint32_t ah32 = base + (uint32_t)p * PBUF;
        const uint32_t al32 = ah32 + PA_TB;
        const uint32_t bh32 = ah32 + 2 * PA_TB;
        const uint32_t bl32 = bh32 + PB_TB;

#pragma unroll
        for (int ks = 0; ks < 2; ks++) {
            const uint32_t kByte = (uint32_t)(ks * 32);
            uint32_t ah[2][4], al[2][4], bh[2][4], bl[2][4];
#pragma unroll
            for (int mf = 0; mf < 2; mf++) {
                uint32_t ad = aOff + (uint32_t)(mf * 16 * SROW * 2) + kByte;
                ldm4(ah[mf], ah32 + ad);
                ldm4(al[mf], al32 + ad);
            }
#pragma unroll
            for (int pp = 0; pp < 2; pp++) {
                uint32_t bd = bOff + (uint32_t)(pp * 16 * SROW * 2) + kByte;
                ldm4(bh[pp], bh32 + bd);
                ldm4(bl[pp], bl32 + bd);
            }
#pragma unroll
            for (int mf = 0; mf < 2; mf++)
#pragma unroll
                for (int nf = 0; nf < 4; nf++) {
                    const int pp = nf >> 1, q = (nf & 1) * 2;
                    mma_bf16(acc[mf][nf], ah[mf], bh[pp][q], bh[pp][q+1]);
                    mma_bf16(acc[mf][nf], al[mf], bh[pp][q], bh[pp][q+1]);
                    mma_bf16(acc[mf][nf], ah[mf], bl[pp][q], bl[pp][q+1]);
                }
        }
        __syncthreads();
    }

    // Epilogue: fp16 hi (+ lo for Q) planes, [B, H, S, hw] layout.
    const int g  = lane >> 2;
    const int t2 = (lane & 3) << 1;
#pragma unroll
    for (int mf = 0; mf < 2; mf++) {
        int mA  = m0 + warpM * 32 + mf * 16 + g;
        int mB  = mA + 8;
        int bbA = mA >> 11, ssA = mA & (SEQ - 1);
        int bbB = mB >> 11, ssB = mB & (SEQ - 1);
#pragma unroll
        for (int nf = 0; nf < 4; nf++) {
            int n  = n0 + warpN * 32 + nf * 8 + t2;
            int hh = n >> 6, dd = n & 63;
            size_t offA = (((size_t)(bbA * NH + hh)) * SEQ + ssA) * HW + dd;
            size_t offB = (((size_t)(bbB * NH + hh)) * SEQ + ssB) * HW + dd;
            float r0, r1;
            uint32_t hp = packhi_h(acc[mf][nf][0], acc[mf][nf][1], r0, r1);
            *(uint32_t*)(Oh + offA) = hp;
            if (z == 0) *(uint32_t*)(g_ql + offA) = packlo_h(r0, r1);
            hp = packhi_h(acc[mf][nf][2], acc[mf][nf][3], r0, r1);
            *(uint32_t*)(Oh + offB) = hp;
            if (z == 0) *(uint32_t*)(g_ql + offB) = packlo_h(r0, r1);
        }
    }
}

// ---------------------------------------------------------------------------
// Flash attention on mma.sync fp16: Q hi/lo 2-pass, K/V single fp16.
// K-tile 64 rows, 3-stage cp.async pipeline (2 tiles/stage: Kh, Vh).
// smem = 2*QTB + 6*KTB = 92160 B -> 2 CTAs/SM. Softmax in log2 domain.
// ---------------------------------------------------------------------------
#define AROW 72
#define QTB  (128*AROW*2)
#define KTB  (64*AROW*2)

__device__ __forceinline__ void tile_async64(uint32_t sbase, const __half* g,
                                             int row0, int tid) {
#pragma unroll
    for (int t = 0; t < 2; t++) {
        int i  = tid + t * 256;
        int r  = i >> 3, c8 = i & 7;
        cpa16(sbase + (uint32_t)(r * AROW + c8 * 8) * 2,
              g + (size_t)(row0 + r) * HW + c8 * 8);
    }
}

__global__ __launch_bounds__(256, 2) void attn_mma(float* __restrict__ out)
{
    extern __shared__ unsigned short asm_[];
    const uint32_t base = smem_u32(asm_);
    const uint32_t qh32 = base;
    const uint32_t ql32 = base + QTB;
    const uint32_t kvbase = base + 2 * QTB;   // stage s: Kh at (2s)*KTB, Vh at (2s+1)*KTB

    const int bh = blockIdx.y;
    const int b  = bh >> 4;
    const int h  = bh & 15;
    const int qt = (int)gridDim.x - 1 - (int)blockIdx.x;
    const int q0 = qt * 128;

    const int tid  = threadIdx.x;
    const int warp = tid >> 5;
    const int lane = tid & 31;
    const int g    = lane >> 2;
    const int t2   = (lane & 3) << 1;

    const float SC2    = SM_SCALE * L2E;                    // score scale, log2 domain
    const float slope2 = exp2f(-0.5f * (float)(h + 1)) * L2E;

    const __half* Qh = g_qh + (size_t)bh * SEQ * HW;
    const __half* Ql = g_ql + (size_t)bh * SEQ * HW;
    const __half* Kh = g_kh + (size_t)bh * SEQ * HW;
    const __half* Vh = g_vh + (size_t)bh * SEQ * HW;

    // ---- load Q tile (hi/lo fp16) ----
#pragma unroll
    for (int t = 0; t < 4; t++) {
        int i = tid + t * 256;
        int r = i >> 3, c8 = i & 7;
        uint32_t soff = (uint32_t)(r * AROW + c8 * 8) * 2;
        *(uint4*)((char*)asm_ + soff) =
            *(const uint4*)(Qh + (size_t)(q0 + r) * HW + c8 * 8);
        *(uint4*)((char*)asm_ + QTB + soff) =
            *(const uint4*)(Ql + (size_t)(q0 + r) * HW + c8 * 8);
    }

    const int nkt = 2 * qt + 2;
    // ---- preload stages 0 and 1 ----
    tile_async64(kvbase + 0 * KTB, Kh, 0, tid);
    tile_async64(kvbase + 1 * KTB, Vh, 0, tid);
    CPA_COMMIT();
    if (1 < nkt) {
        tile_async64(kvbase + 2 * KTB, Kh, 64, tid);
        tile_async64(kvbase + 3 * KTB, Vh, 64, tid);
    }
    CPA_COMMIT();

    const uint32_t aElem = (uint32_t)((warp * 16 + (lane & 15)) * AROW + ((lane >> 4) << 3));
    const uint32_t bElem = (uint32_t)(((lane & 7) + ((lane >> 4) << 3)) * AROW + (((lane >> 3) & 1) << 3));
    const uint32_t vElem = (uint32_t)((lane & 15) * AROW + ((lane >> 4) << 3));

    float oacc[8][4];
#pragma unroll
    for (int nf = 0; nf < 8; nf++)
#pragma unroll
        for (int e = 0; e < 4; e++) oacc[nf][e] = 0.0f;

    float m0r = -3e38f, m1r = -3e38f, l0 = 0.0f, l1 = 0.0f;
    const int row0 = q0 + warp * 16 + g;
    const int row1 = row0 + 8;

    for (int kt = 0; kt < nkt; kt++) {
        CPA_WAIT1();           // stage kt's data resident (kt+1 may be in flight)
        __syncthreads();

        if (kt + 2 < nkt) {    // refill stage (kt+2)%3 (all warps done reading kt-1)
            int s = (kt + 2) % 3;
            int r0n = (kt + 2) * 64;
            tile_async64(kvbase + (uint32_t)(2 * s + 0) * KTB, Kh, r0n, tid);
            tile_async64(kvbase + (uint32_t)(2 * s + 1) * KTB, Vh, r0n, tid);
        }
        CPA_COMMIT();          // commit every iter (possibly empty) to keep counts aligned

        const int s = kt % 3;
        const uint32_t kh32 = kvbase + (uint32_t)(2 * s + 0) * KTB;
        const uint32_t vh32 = kvbase + (uint32_t)(2 * s + 1) * KTB;
        const int k0g = kt * 64;

        // ---- S = Q K^T (fp16, Q hi/lo 2-pass) ----
        float sacc[8][4];
#pragma unroll
        for (int nf = 0; nf < 8; nf++)
#pragma unroll
            for (int e = 0; e < 4; e++) sacc[nf][e] = 0.0f;

#pragma unroll
        for (int ks = 0; ks < 4; ks++) {
            uint32_t ah[4], al[4];
            ldm4(ah, qh32 + (aElem + ks * 16) * 2);
            ldm4(al, ql32 + (aElem + ks * 16) * 2);
#pragma unroll
            for (int pp = 0; pp < 4; pp++) {
                uint32_t bhx[4];
                uint32_t bd = (bElem + (uint32_t)(pp * 16 * AROW) + (uint32_t)(ks * 16)) * 2;
                ldm4(bhx, kh32 + bd);
                mma_f16(sacc[2*pp],   ah, bhx[0], bhx[1]);
                mma_f16(sacc[2*pp],   al, bhx[0], bhx[1]);
                mma_f16(sacc[2*pp+1], ah, bhx[2], bhx[3]);
                mma_f16(sacc[2*pp+1], al, bhx[2], bhx[3]);
            }
        }

        // ---- scale + ALiBi + causal (log2 domain); online softmax ----
        const bool diag = (kt >= 2 * qt);
        float mx0 = -3e38f, mx1 = -3e38f;
#pragma unroll
        for (int nf = 0; nf < 8; nf++) {
            int c0 = k0g + nf * 8 + t2;
            int c1 = c0 + 1;
            float v0 = sacc[nf][0] * SC2 + slope2 * (float)(c0 - row0);
            float v1 = sacc[nf][1] * SC2 + slope2 * (float)(c1 - row0);
            float v2 = sacc[nf][2] * SC2 + slope2 * (float)(c0 - row1);
            float v3 = sacc[nf][3] * SC2 + slope2 * (float)(c1 - row1);
            if (diag) {
                if (c0 > row0) v0 = -3e38f;
                if (c1 > row0) v1 = -3e38f;
                if (c0 > row1) v2 = -3e38f;
                if (c1 > row1) v3 = -3e38f;
            }
            sacc[nf][0] = v0; sacc[nf][1] = v1; sacc[nf][2] = v2; sacc[nf][3] = v3;
            mx0 = fmaxf(mx0, fmaxf(v0, v1));
            mx1 = fmaxf(mx1, fmaxf(v2, v3));
        }
        mx0 = fmaxf(mx0, __shfl_xor_sync(0xffffffffu, mx0, 1));
        mx0 = fmaxf(mx0, __shfl_xor_sync(0xffffffffu, mx0, 2));
        mx1 = fmaxf(mx1, __shfl_xor_sync(0xffffffffu, mx1, 1));
        mx1 = fmaxf(mx1, __shfl_xor_sync(0xffffffffu, mx1, 2));

        float mn0 = fmaxf(m0r, mx0);
        float mn1 = fmaxf(m1r, mx1);
        float corr0 = exp2f(m0r - mn0);
        float corr1 = exp2f(m1r - mn1);
        m0r = mn0; m1r = mn1;

        float rs0 = 0.0f, rs1 = 0.0f;
#pragma unroll
        for (int nf = 0; nf < 8; nf++) {
            float p0 = exp2f(sacc[nf][0] - mn0);
            float p1 = exp2f(sacc[nf][1] - mn0);
            float p2 = exp2f(sacc[nf][2] - mn1);
            float p3 = exp2f(sacc[nf][3] - mn1);
            sacc[nf][0] = p0; sacc[nf][1] = p1; sacc[nf][2] = p2; sacc[nf][3] = p3;
            rs0 += p0 + p1; rs1 += p2 + p3;
        }
        rs0 += __shfl_xor_sync(0xffffffffu, rs0, 1);
        rs0 += __shfl_xor_sync(0xffffffffu, rs0, 2);
        rs1 += __shfl_xor_sync(0xffffffffu, rs1, 1);
        rs1 += __shfl_xor_sync(0xffffffffu, rs1, 2);
        l0 = l0 * corr0 + rs0;
        l1 = l1 * corr1 + rs1;

#pragma unroll
        for (int nf = 0; nf < 8; nf++) {
            oacc[nf][0] *= corr0; oacc[nf][1] *= corr0;
            oacc[nf][2] *= corr1; oacc[nf][3] *= corr1;
        }

        // ---- O += P V (P hi/lo fp16 2-pass, V single) ----
#pragma unroll
        for (int ks = 0; ks < 4; ks++) {
            uint32_t pah[4], pal[4];
            float r0, r1;
            pah[0] = packhi_h(sacc[2*ks][0],   sacc[2*ks][1],   r0, r1); pal[0] = packlo_h(r0, r1);
            pah[1] = packhi_h(sacc[2*ks][2],   sacc[2*ks][3],   r0, r1); pal[1] = packlo_h(r0, r1);
            pah[2] = packhi_h(sacc[2*ks+1][0], sacc[2*ks+1][1], r0, r1); pal[2] = packlo_h(r0, r1);
            pah[3] = packhi_h(sacc[2*ks+1][2], sacc[2*ks+1][3], r0, r1); pal[3] = packlo_h(r0, r1);
#pragma unroll
            for (int nb = 0; nb < 4; nb++) {
                uint32_t vhx[4];
                uint32_t vd = (vElem + (uint32_t)(ks * 16 * AROW) + (uint32_t)(nb * 16)) * 2;
                ldm4t(vhx, vh32 + vd);
                mma_f16(oacc[2*nb],   pah, vhx[0], vhx[1]);
                mma_f16(oacc[2*nb],   pal, vhx[0], vhx[1]);
                mma_f16(oacc[2*nb+1], pah, vhx[2], vhx[3]);
                mma_f16(oacc[2*nb+1], pal, vhx[2], vhx[3]);
            }
        }
    }

    // ---- epilogue: normalize + store to [B, S, D] ----
    const float inv0 = 1.0f / l0;
    const float inv1 = 1.0f / l1;
    float* op = out + (size_t)b * SEQ * DM + (size_t)h * HW;
#pragma unroll
    for (int nf = 0; nf < 8; nf++) {
        int col = nf * 8 + t2;
        *(float2*)(op + (size_t)row0 * DM + col) =
            make_float2(oacc[nf][0] * inv0, oacc[nf][1] * inv0);
        *(float2*)(op + (size_t)row1 * DM + col) =
            make_float2(oacc[nf][2] * inv1, oacc[nf][3] * inv1);
    }
}

// ---------------------------------------------------------------------------
// Launch: inputs order = queries, keys, values, mask, Wq, Wk, Wv.
// ---------------------------------------------------------------------------
extern "C" void kernel_launch(void* const* d_in, const int* in_sizes, int n_in,
                              void* d_out, int out_size)
{
    (void)in_sizes; (void)n_in; (void)out_size;
    const float4* q  = (const float4*)d_in[0];
    const float4* k  = (const float4*)d_in[1];
    const float4* v  = (const float4*)d_in[2];
    const float4* wq = (const float4*)d_in[4];
    const float4* wk = (const float4*)d_in[5];
    const float4* wv = (const float4*)d_in[6];
    float* out = (float*)d_out;

    const int proj_smem = 2 * PBUF;            // 61440 B
    cudaFuncSetAttribute(proj_mma, cudaFuncAttributeMaxDynamicSharedMemorySize, proj_smem);
    const int attn_smem = 2 * QTB + 6 * KTB;   // 92160 B
    cudaFuncSetAttribute(attn_mma, cudaFuncAttributeMaxDynamicSharedMemorySize, attn_smem);

    split_kernel<<<dim3(4096, 6), 256>>>(q, k, v, wq, wk, wv);
    proj_mma<<<dim3(DM/64, (BATCH*SEQ)/128, 3), 256, proj_smem>>>();
    attn_mma<<<dim3(SEQ/128, BATCH*NH), 256, attn_smem>>>(out);
}

// round 11
// speedup vs baseline: 1.4843x; 1.1274x over previous
#include <cuda_runtime.h>
#include <cuda_bf16.h>
#include <cuda_fp16.h>
#include <cstdint>
#include <math.h>

#define BATCH 2
#define SEQ   2048
#define DM    1024
#define NH    16
#define HW    64
#define SM_SCALE 0.125f   // 1/sqrt(64)
#define L2E   1.44269504f

#define NELEM (BATCH*NH*SEQ*HW)
#define XN    (BATCH*SEQ*DM)
#define WN    (DM*DM)

// Projected Q (fp16 hi+lo), K/V (fp16 hi only) in [B, H, S, hw] layout.
__device__ __half g_qh[NELEM], g_ql[NELEM];
__device__ __half g_kh[NELEM];
__device__ __half g_vh[NELEM];
// fp16 planes of inputs X (hi+lo) and weights W (single) for the projections.
__device__ __half g_xh[3*XN], g_xl[3*XN];
__device__ __half g_wh[3*WN];

// ---------------------------------------------------------------------------
// Helpers
// ---------------------------------------------------------------------------
__device__ __forceinline__ uint32_t smem_u32(const void* p) {
    uint32_t a;
    asm("{ .reg .u64 t; cvta.to.shared.u64 t, %1; cvt.u32.u64 %0, t; }"
        : "=r"(a) : "l"(p));
    return a;
}

__device__ __forceinline__ void ldm4(uint32_t r[4], uint32_t addr) {
    asm volatile("ldmatrix.sync.aligned.m8n8.x4.shared.b16 {%0,%1,%2,%3}, [%4];"
                 : "=r"(r[0]), "=r"(r[1]), "=r"(r[2]), "=r"(r[3]) : "r"(addr));
}
__device__ __forceinline__ void ldm4t(uint32_t r[4], uint32_t addr) {
    asm volatile("ldmatrix.sync.aligned.m8n8.x4.trans.shared.b16 {%0,%1,%2,%3}, [%4];"
                 : "=r"(r[0]), "=r"(r[1]), "=r"(r[2]), "=r"(r[3]) : "r"(addr));
}

__device__ __forceinline__ void mma_f16(float acc[4], const uint32_t a[4],
                                        uint32_t b0, uint32_t b1) {
    asm volatile(
        "mma.sync.aligned.m16n8k16.row.col.f32.f16.f16.f32 "
        "{%0,%1,%2,%3}, {%4,%5,%6,%7}, {%8,%9}, {%0,%1,%2,%3};"
        : "+f"(acc[0]), "+f"(acc[1]), "+f"(acc[2]), "+f"(acc[3])
        : "r"(a[0]), "r"(a[1]), "r"(a[2]), "r"(a[3]), "r"(b0), "r"(b1));
}

// fp16 hi/lo split
__device__ __forceinline__ uint32_t packhi_h(float a, float b, float& ra, float& rb) {
    __half2 h = __floats2half2_rn(a, b);
    ra = a - __half2float(__low2half(h));
    rb = b - __half2float(__high2half(h));
    return *reinterpret_cast<uint32_t*>(&h);
}
__device__ __forceinline__ uint32_t packlo_h(float a, float b) {
    __half2 h = __floats2half2_rn(a, b);
    return *reinterpret_cast<uint32_t*>(&h);
}

__device__ __forceinline__ void cpa16(uint32_t saddr, const void* g) {
    asm volatile("cp.async.cg.shared.global [%0], [%1], 16;"
                 :: "r"(saddr), "l"(g) : "memory");
}
#define CPA_COMMIT() asm volatile("cp.async.commit_group;" ::: "memory")
#define CPA_WAIT0()  asm volatile("cp.async.wait_group 0;" ::: "memory")
#define CPA_WAIT1()  asm volatile("cp.async.wait_group 1;" ::: "memory")

// ---------------------------------------------------------------------------
// Split inputs/weights into fp16 planes (one bandwidth pass).
// X (q,k,v): hi + lo planes (exact). W (q,k,v): single fp16 (rounded).
// ---------------------------------------------------------------------------
__global__ __launch_bounds__(256) void split_kernel(
    const float4* __restrict__ xq, const float4* __restrict__ xk,
    const float4* __restrict__ xv, const float4* __restrict__ wq,
    const float4* __restrict__ wk, const float4* __restrict__ wv)
{
    const int y = blockIdx.y;
    if (y < 3) {
        const float4* src = (y == 0) ? xq : (y == 1) ? xk : xv;
        __half* dh = g_xh + (size_t)y * XN;
        __half* dl = g_xl + (size_t)y * XN;
        size_t i = (size_t)blockIdx.x * 256 + threadIdx.x;
        float4 a = src[i];
        float r0, r1, r2, r3;
        uint32_t h01 = packhi_h(a.x, a.y, r0, r1);
        uint32_t h23 = packhi_h(a.z, a.w, r2, r3);
        *(uint2*)(dh + i * 4) = make_uint2(h01, h23);
        *(uint2*)(dl + i * 4) = make_uint2(packlo_h(r0, r1), packlo_h(r2, r3));
    } else {
        if (blockIdx.x >= 1024) return;
        int w = y - 3;
        const float4* src = (w == 0) ? wq : (w == 1) ? wk : wv;
        __half* dh = g_wh + (size_t)w * WN;
        size_t i = (size_t)blockIdx.x * 256 + threadIdx.x;
        float4 a = src[i];
        *(uint2*)(dh + i * 4) = make_uint2(packlo_h(a.x, a.y), packlo_h(a.z, a.w));
    }
}

// ---------------------------------------------------------------------------
// Projection GEMM on mma.sync fp16: X hi/lo 2-pass, W single fp16.
// CTA 128x64, warp tile 32x32, 8 warps (4M x 2N), 2 CTAs/SM.
// Epilogue: fp16 hi (+lo for Q only) planes for the attention kernel.
// grid = (16, 32, 3), block = 256. smem 2 x 25600 = 51200 B.
// ---------------------------------------------------------------------------
#define SROW   40
#define PA_TB  (128*SROW*2)         // 10240 B per A tile
#define PB_TB  (64*SROW*2)          // 5120 B per B tile
#define PBUF   (2*PA_TB + PB_TB)    // 25600 B per stage

__global__ __launch_bounds__(256, 2) void proj_mma()
{
    extern __shared__ unsigned short psm[];
    const uint32_t base = smem_u32(psm);

    const int z = blockIdx.z;
    const __half* Ah = g_xh + (size_t)z * XN;
    const __half* Al = g_xl + (size_t)z * XN;
    const __half* Bh = g_wh + (size_t)z * WN;
    __half* Oh = (z == 0) ? g_qh : (z == 1) ? g_kh : g_vh;

    const int tid   = threadIdx.x;
    const int wid   = tid >> 5;
    const int lane  = tid & 31;
    const int warpM = wid >> 1;
    const int warpN = wid & 1;
    const int m0    = blockIdx.y * 128;
    const int n0    = blockIdx.x * 64;

    const uint32_t aOff = ((uint32_t)(warpM * 32 + (lane & 15)) * SROW +
                           ((uint32_t)(lane >> 4) << 3)) * 2;
    const uint32_t bOff = ((uint32_t)(warpN * 32 + (lane & 7) + ((lane >> 4) << 3)) * SROW +
                           (((uint32_t)(lane >> 3) & 1) << 3)) * 2;

    float acc[2][4][4];
#pragma unroll
    for (int mf = 0; mf < 2; mf++)
#pragma unroll
        for (int nf = 0; nf < 4; nf++)
#pragma unroll
            for (int i = 0; i < 4; i++) acc[mf][nf][i] = 0.0f;

    const int ar = tid >> 2, ac = tid & 3;

    auto load_chunk = [&](int c, int p) {
        const uint32_t bb = base + (uint32_t)p * PBUF;
        const int k0 = c * 32;
#pragma unroll
        for (int t = 0; t < 2; t++) {
            int i = tid + t * 256;
            int r = i >> 2, c8 = i & 3;
            uint32_t soff = (uint32_t)(r * SROW + c8 * 8) * 2;
            size_t ga = (size_t)(m0 + r) * DM + k0 + c8 * 8;
            cpa16(bb + soff, Ah + ga);
            cpa16(bb + PA_TB + soff, Al + ga);
        }
        {
            uint32_t soff = (uint32_t)(ar * SROW + ac * 8) * 2;
            size_t gb = (size_t)(n0 + ar) * DM + k0 + ac * 8;
            cpa16(bb + 2 * PA_TB + soff, Bh + gb);
        }
        CPA_COMMIT();
    };

    load_chunk(0, 0);

    for (int c = 0; c < 32; c++) {
        const int p = c & 1;
        CPA_WAIT0();
        __syncthreads();
        if (c < 31) load_chunk(c + 1, p ^ 1);

        const uint32_t ah32 = base + (uint32_t)p * PBUF;
        const uint32_t al32 = ah32 + PA_TB;
        const uint32_t bh32 = ah32 + 2 * PA_TB;

#pragma unroll
        for (int ks = 0; ks < 2; ks++) {
            const uint32_t kByte = (uint32_t)(ks * 32);
            uint32_t ah[2][4], al[2][4], bh[2][4];
#pragma unroll
            for (int mf = 0; mf < 2; mf++) {
                uint32_t ad = aOff + (uint32_t)(mf * 16 * SROW * 2) + kByte;
                ldm4(ah[mf], ah32 + ad);
                ldm4(al[mf], al32 + ad);
            }
#pragma unroll
            for (int pp = 0; pp < 2; pp++) {
                uint32_t bd = bOff + (uint32_t)(pp * 16 * SROW * 2) + kByte;
                ldm4(bh[pp], bh32 + bd);
            }
#pragma unroll
            for (int mf = 0; mf < 2; mf++)
#pragma unroll
                for (int nf = 0; nf < 4; nf++) {
                    const int pp = nf >> 1, q = (nf & 1) * 2;
                    mma_f16(acc[mf][nf], ah[mf], bh[pp][q], bh[pp][q+1]);
                    mma_f16(acc[mf][nf], al[mf], bh[pp][q], bh[pp][q+1]);
                }
        }
        __syncthreads();
    }

    // Epilogue: fp16 hi (+ lo for Q) planes, [B, H, S, hw] layout.
    const int g  = lane >> 2;
    const int t2 = (lane & 3) << 1;
#pragma unroll
    for (int mf = 0; mf < 2; mf++) {
        int mA  = m0 + warpM * 32 + mf * 16 + g;
        int mB  = mA + 8;
        int bbA = mA >> 11, ssA = mA & (SEQ - 1);
        int bbB = mB >> 11, ssB = mB & (SEQ - 1);
#pragma unroll
        for (int nf = 0; nf < 4; nf++) {
            int n  = n0 + warpN * 32 + nf * 8 + t2;
            int hh = n >> 6, dd = n & 63;
            size_t offA = (((size_t)(bbA * NH + hh)) * SEQ + ssA) * HW + dd;
            size_t offB = (((size_t)(bbB * NH + hh)) * SEQ + ssB) * HW + dd;
            float r0, r1;
            uint32_t hp = packhi_h(acc[mf][nf][0], acc[mf][nf][1], r0, r1);
            *(uint32_t*)(Oh + offA) = hp;
            if (z == 0) *(uint32_t*)(g_ql + offA) = packlo_h(r0, r1);
            hp = packhi_h(acc[mf][nf][2], acc[mf][nf][3], r0, r1);
            *(uint32_t*)(Oh + offB) = hp;
            if (z == 0) *(uint32_t*)(g_ql + offB) = packlo_h(r0, r1);
        }
    }
}

// ---------------------------------------------------------------------------
// Flash attention on mma.sync fp16: Q hi/lo 2-pass, K/V single fp16.
// (unchanged from R10 passing kernel)
// ---------------------------------------------------------------------------
#define AROW 72
#define QTB  (128*AROW*2)
#define KTB  (64*AROW*2)

__device__ __forceinline__ void tile_async64(uint32_t sbase, const __half* g,
                                             int row0, int tid) {
#pragma unroll
    for (int t = 0; t < 2; t++) {
        int i  = tid + t * 256;
        int r  = i >> 3, c8 = i & 7;
        cpa16(sbase + (uint32_t)(r * AROW + c8 * 8) * 2,
              g + (size_t)(row0 + r) * HW + c8 * 8);
    }
}

__global__ __launch_bounds__(256, 2) void attn_mma(float* __restrict__ out)
{
    extern __shared__ unsigned short asm_[];
    const uint32_t base = smem_u32(asm_);
    const uint32_t qh32 = base;
    const uint32_t ql32 = base + QTB;
    const uint32_t kvbase = base + 2 * QTB;

    const int bh = blockIdx.y;
    const int b  = bh >> 4;
    const int h  = bh & 15;
    const int qt = (int)gridDim.x - 1 - (int)blockIdx.x;
    const int q0 = qt * 128;

    const int tid  = threadIdx.x;
    const int warp = tid >> 5;
    const int lane = tid & 31;
    const int g    = lane >> 2;
    const int t2   = (lane & 3) << 1;

    const float SC2    = SM_SCALE * L2E;
    const float slope2 = exp2f(-0.5f * (float)(h + 1)) * L2E;

    const __half* Qh = g_qh + (size_t)bh * SEQ * HW;
    const __half* Ql = g_ql + (size_t)bh * SEQ * HW;
    const __half* Kh = g_kh + (size_t)bh * SEQ * HW;
    const __half* Vh = g_vh + (size_t)bh * SEQ * HW;

#pragma unroll
    for (int t = 0; t < 4; t++) {
        int i = tid + t * 256;
        int r = i >> 3, c8 = i & 7;
        uint32_t soff = (uint32_t)(r * AROW + c8 * 8) * 2;
        *(uint4*)((char*)asm_ + soff) =
            *(const uint4*)(Qh + (size_t)(q0 + r) * HW + c8 * 8);
        *(uint4*)((char*)asm_ + QTB + soff) =
            *(const uint4*)(Ql + (size_t)(q0 + r) * HW + c8 * 8);
    }

    const int nkt = 2 * qt + 2;
    tile_async64(kvbase + 0 * KTB, Kh, 0, tid);
    tile_async64(kvbase + 1 * KTB, Vh, 0, tid);
    CPA_COMMIT();
    if (1 < nkt) {
        tile_async64(kvbase + 2 * KTB, Kh, 64, tid);
        tile_async64(kvbase + 3 * KTB, Vh, 64, tid);
    }
    CPA_COMMIT();

    const uint32_t aElem = (uint32_t)((warp * 16 + (lane & 15)) * AROW + ((lane >> 4) << 3));
    const uint32_t bElem = (uint32_t)(((lane & 7) + ((lane >> 4) << 3)) * AROW + (((lane >> 3) & 1) << 3));
    const uint32_t vElem = (uint32_t)((lane & 15) * AROW + ((lane >> 4) << 3));

    float oacc[8][4];
#pragma unroll
    for (int nf = 0; nf < 8; nf++)
#pragma unroll
        for (int e = 0; e < 4; e++) oacc[nf][e] = 0.0f;

    float m0r = -3e38f, m1r = -3e38f, l0 = 0.0f, l1 = 0.0f;
    const int row0 = q0 + warp * 16 + g;
    const int row1 = row0 + 8;

    for (int kt = 0; kt < nkt; kt++) {
        CPA_WAIT1();
        __syncthreads();

        if (kt + 2 < nkt) {
            int s = (kt + 2) % 3;
            int r0n = (kt + 2) * 64;
            tile_async64(kvbase + (uint32_t)(2 * s + 0) * KTB, Kh, r0n, tid);
            tile_async64(kvbase + (uint32_t)(2 * s + 1) * KTB, Vh, r0n, tid);
        }
        CPA_COMMIT();

        const int s = kt % 3;
        const uint32_t kh32 = kvbase + (uint32_t)(2 * s + 0) * KTB;
        const uint32_t vh32 = kvbase + (uint32_t)(2 * s + 1) * KTB;
        const int k0g = kt * 64;

        float sacc[8][4];
#pragma unroll
        for (int nf = 0; nf < 8; nf++)
#pragma unroll
            for (int e = 0; e < 4; e++) sacc[nf][e] = 0.0f;

#pragma unroll
        for (int ks = 0; ks < 4; ks++) {
            uint32_t ah[4], al[4];
            ldm4(ah, qh32 + (aElem + ks * 16) * 2);
            ldm4(al, ql32 + (aElem + ks * 16) * 2);
#pragma unroll
            for (int pp = 0; pp < 4; pp++) {
                uint32_t bhx[4];
                uint32_t bd = (bElem + (uint32_t)(pp * 16 * AROW) + (uint32_t)(ks * 16)) * 2;
                ldm4(bhx, kh32 + bd);
                mma_f16(sacc[2*pp],   ah, bhx[0], bhx[1]);
                mma_f16(sacc[2*pp],   al, bhx[0], bhx[1]);
                mma_f16(sacc[2*pp+1], ah, bhx[2], bhx[3]);
                mma_f16(sacc[2*pp+1], al, bhx[2], bhx[3]);
            }
        }

        const bool diag = (kt >= 2 * qt);
        float mx0 = -3e38f, mx1 = -3e38f;
#pragma unroll
        for (int nf = 0; nf < 8; nf++) {
            int c0 = k0g + nf * 8 + t2;
            int c1 = c0 + 1;
            float v0 = sacc[nf][0] * SC2 + slope2 * (float)(c0 - row0);
            float v1 = sacc[nf][1] * SC2 + slope2 * (float)(c1 - row0);
            float v2 = sacc[nf][2] * SC2 + slope2 * (float)(c0 - row1);
            float v3 = sacc[nf][3] * SC2 + slope2 * (float)(c1 - row1);
            if (diag) {
                if (c0 > row0) v0 = -3e38f;
                if (c1 > row0) v1 = -3e38f;
                if (c0 > row1) v2 = -3e38f;
                if (c1 > row1) v3 = -3e38f;
            }
            sacc[nf][0] = v0; sacc[nf][1] = v1; sacc[nf][2] = v2; sacc[nf][3] = v3;
            mx0 = fmaxf(mx0, fmaxf(v0, v1));
            mx1 = fmaxf(mx1, fmaxf(v2, v3));
        }
        mx0 = fmaxf(mx0, __shfl_xor_sync(0xffffffffu, mx0, 1));
        mx0 = fmaxf(mx0, __shfl_xor_sync(0xffffffffu, mx0, 2));
        mx1 = fmaxf(mx1, __shfl_xor_sync(0xffffffffu, mx1, 1));
        mx1 = fmaxf(mx1, __shfl_xor_sync(0xffffffffu, mx1, 2));

        float mn0 = fmaxf(m0r, mx0);
        float mn1 = fmaxf(m1r, mx1);
        float corr0 = exp2f(m0r - mn0);
        float corr1 = exp2f(m1r - mn1);
        m0r = mn0; m1r = mn1;

        float rs0 = 0.0f, rs1 = 0.0f;
#pragma unroll
        for (int nf = 0; nf < 8; nf++) {
            float p0 = exp2f(sacc[nf][0] - mn0);
            float p1 = exp2f(sacc[nf][1] - mn0);
            float p2 = exp2f(sacc[nf][2] - mn1);
            float p3 = exp2f(sacc[nf][3] - mn1);
            sacc[nf][0] = p0; sacc[nf][1] = p1; sacc[nf][2] = p2; sacc[nf][3] = p3;
            rs0 += p0 + p1; rs1 += p2 + p3;
        }
        rs0 += __shfl_xor_sync(0xffffffffu, rs0, 1);
        rs0 += __shfl_xor_sync(0xffffffffu, rs0, 2);
        rs1 += __shfl_xor_sync(0xffffffffu, rs1, 1);
        rs1 += __shfl_xor_sync(0xffffffffu, rs1, 2);
        l0 = l0 * corr0 + rs0;
        l1 = l1 * corr1 + rs1;

#pragma unroll
        for (int nf = 0; nf < 8; nf++) {
            oacc[nf][0] *= corr0; oacc[nf][1] *= corr0;
            oacc[nf][2] *= corr1; oacc[nf][3] *= corr1;
        }

#pragma unroll
        for (int ks = 0; ks < 4; ks++) {
            uint32_t pah[4], pal[4];
            float r0, r1;
            pah[0] = packhi_h(sacc[2*ks][0],   sacc[2*ks][1],   r0, r1); pal[0] = packlo_h(r0, r1);
            pah[1] = packhi_h(sacc[2*ks][2],   sacc[2*ks][3],   r0, r1); pal[1] = packlo_h(r0, r1);
            pah[2] = packhi_h(sacc[2*ks+1][0], sacc[2*ks+1][1], r0, r1); pal[2] = packlo_h(r0, r1);
            pah[3] = packhi_h(sacc[2*ks+1][2], sacc[2*ks+1][3], r0, r1); pal[3] = packlo_h(r0, r1);
#pragma unroll
            for (int nb = 0; nb < 4; nb++) {
                uint32_t vhx[4];
                uint32_t vd = (vElem + (uint32_t)(ks * 16 * AROW) + (uint32_t)(nb * 16)) * 2;
                ldm4t(vhx, vh32 + vd);
                mma_f16(oacc[2*nb],   pah, vhx[0], vhx[1]);
                mma_f16(oacc[2*nb],   pal, vhx[0], vhx[1]);
                mma_f16(oacc[2*nb+1], pah, vhx[2], vhx[3]);
                mma_f16(oacc[2*nb+1], pal, vhx[2], vhx[3]);
            }
        }
    }

    const float inv0 = 1.0f / l0;
    const float inv1 = 1.0f / l1;
    float* op = out + (size_t)b * SEQ * DM + (size_t)h * HW;
#pragma unroll
    for (int nf = 0; nf < 8; nf++) {
        int col = nf * 8 + t2;
        *(float2*)(op + (size_t)row0 * DM + col) =
            make_float2(oacc[nf][0] * inv0, oacc[nf][1] * inv0);
        *(float2*)(op + (size_t)row1 * DM + col) =
            make_float2(oacc[nf][2] * inv1, oacc[nf][3] * inv1);
    }
}

// ---------------------------------------------------------------------------
// Launch: inputs order = queries, keys, values, mask, Wq, Wk, Wv.
// ---------------------------------------------------------------------------
extern "C" void kernel_launch(void* const* d_in, const int* in_sizes, int n_in,
                              void* d_out, int out_size)
{
    (void)in_sizes; (void)n_in; (void)out_size;
    const float4* q  = (const float4*)d_in[0];
    const float4* k  = (const float4*)d_in[1];
    const float4* v  = (const float4*)d_in[2];
    const float4* wq = (const float4*)d_in[4];
    const float4* wk = (const float4*)d_in[5];
    const float4* wv = (const float4*)d_in[6];
    float* out = (float*)d_out;

    const int proj_smem = 2 * PBUF;            // 51200 B
    cudaFuncSetAttribute(proj_mma, cudaFuncAttributeMaxDynamicSharedMemorySize, proj_smem);
    const int attn_smem = 2 * QTB + 6 * KTB;   // 92160 B
    cudaFuncSetAttribute(attn_mma, cudaFuncAttributeMaxDynamicSharedMemorySize, attn_smem);

    split_kernel<<<dim3(4096, 6), 256>>>(q, k, v, wq, wk, wv);
    proj_mma<<<dim3(DM/64, (BATCH*SEQ)/128, 3), 256, proj_smem>>>();
    attn_mma<<<dim3(SEQ/128, BATCH*NH), 256, attn_smem>>>(out);
}

// round 12
// speedup vs baseline: 1.9645x; 1.3235x over previous
#include <cuda_runtime.h>
#include <cuda_fp16.h>
#include <cstdint>
#include <math.h>

#define BATCH 2
#define SEQ   2048
#define DM    1024
#define NH    16
#define HW    64
#define SM_SCALE 0.125f   // 1/sqrt(64)
#define L2E   1.44269504f

#define NELEM (BATCH*NH*SEQ*HW)
#define XN    (BATCH*SEQ*DM)
#define WN    (DM*DM)

// Projected Q (fp16 hi+lo), K/V (fp16 hi only) in [B, H, S, hw] layout.
__device__ __half g_qh[NELEM], g_ql[NELEM];
__device__ __half g_kh[NELEM];
__device__ __half g_vh[NELEM];
// fp16 planes of inputs X and weights W (single plane each) for the projections.
__device__ __half g_xh[3*XN];
__device__ __half g_wh[3*WN];

// ---------------------------------------------------------------------------
// Helpers
// ---------------------------------------------------------------------------
__device__ __forceinline__ uint32_t smem_u32(const void* p) {
    uint32_t a;
    asm("{ .reg .u64 t; cvta.to.shared.u64 t, %1; cvt.u32.u64 %0, t; }"
        : "=r"(a) : "l"(p));
    return a;
}

__device__ __forceinline__ void ldm4(uint32_t r[4], uint32_t addr) {
    asm volatile("ldmatrix.sync.aligned.m8n8.x4.shared.b16 {%0,%1,%2,%3}, [%4];"
                 : "=r"(r[0]), "=r"(r[1]), "=r"(r[2]), "=r"(r[3]) : "r"(addr));
}
__device__ __forceinline__ void ldm4t(uint32_t r[4], uint32_t addr) {
    asm volatile("ldmatrix.sync.aligned.m8n8.x4.trans.shared.b16 {%0,%1,%2,%3}, [%4];"
                 : "=r"(r[0]), "=r"(r[1]), "=r"(r[2]), "=r"(r[3]) : "r"(addr));
}

__device__ __forceinline__ void mma_f16(float acc[4], const uint32_t a[4],
                                        uint32_t b0, uint32_t b1) {
    asm volatile(
        "mma.sync.aligned.m16n8k16.row.col.f32.f16.f16.f32 "
        "{%0,%1,%2,%3}, {%4,%5,%6,%7}, {%8,%9}, {%0,%1,%2,%3};"
        : "+f"(acc[0]), "+f"(acc[1]), "+f"(acc[2]), "+f"(acc[3])
        : "r"(a[0]), "r"(a[1]), "r"(a[2]), "r"(a[3]), "r"(b0), "r"(b1));
}

// fp16 hi/lo split
__device__ __forceinline__ uint32_t packhi_h(float a, float b, float& ra, float& rb) {
    __half2 h = __floats2half2_rn(a, b);
    ra = a - __half2float(__low2half(h));
    rb = b - __half2float(__high2half(h));
    return *reinterpret_cast<uint32_t*>(&h);
}
__device__ __forceinline__ uint32_t packlo_h(float a, float b) {
    __half2 h = __floats2half2_rn(a, b);
    return *reinterpret_cast<uint32_t*>(&h);
}

__device__ __forceinline__ void cpa16(uint32_t saddr, const void* g) {
    asm volatile("cp.async.cg.shared.global [%0], [%1], 16;"
                 :: "r"(saddr), "l"(g) : "memory");
}
#define CPA_COMMIT() asm volatile("cp.async.commit_group;" ::: "memory")
#define CPA_WAIT1()  asm volatile("cp.async.wait_group 1;" ::: "memory")

// ---------------------------------------------------------------------------
// Split inputs/weights into single fp16 planes (one bandwidth pass).
// ---------------------------------------------------------------------------
__global__ __launch_bounds__(256) void split_kernel(
    const float4* __restrict__ xq, const float4* __restrict__ xk,
    const float4* __restrict__ xv, const float4* __restrict__ wq,
    const float4* __restrict__ wk, const float4* __restrict__ wv)
{
    const int y = blockIdx.y;
    if (y < 3) {
        const float4* src = (y == 0) ? xq : (y == 1) ? xk : xv;
        __half* dh = g_xh + (size_t)y * XN;
        size_t i = (size_t)blockIdx.x * 256 + threadIdx.x;
        float4 a = src[i];
        *(uint2*)(dh + i * 4) = make_uint2(packlo_h(a.x, a.y), packlo_h(a.z, a.w));
    } else {
        if (blockIdx.x >= 1024) return;
        int w = y - 3;
        const float4* src = (w == 0) ? wq : (w == 1) ? wk : wv;
        __half* dh = g_wh + (size_t)w * WN;
        size_t i = (size_t)blockIdx.x * 256 + threadIdx.x;
        float4 a = src[i];
        *(uint2*)(dh + i * 4) = make_uint2(packlo_h(a.x, a.y), packlo_h(a.z, a.w));
    }
}

// ---------------------------------------------------------------------------
// Projection GEMM on mma.sync fp16, single pass (X fp16 @ W fp16, fp32 acc).
// CTA 128x64, warp tile 32x32, 8 warps (4M x 2N), 2 CTAs/SM.
// 3-stage cp.async pipeline. Epilogue: fp16 hi (+lo for Q only) planes.
// grid = (16, 32, 3), block = 256. smem 3 x 15360 = 46080 B.
// ---------------------------------------------------------------------------
#define SROW   40
#define PA_TB  (128*SROW*2)        // 10240 B per A tile
#define PB_TB  (64*SROW*2)         // 5120 B per B tile
#define PSTG   (PA_TB + PB_TB)     // 15360 B per stage

__global__ __launch_bounds__(256, 2) void proj_mma()
{
    extern __shared__ unsigned short psm[];
    const uint32_t base = smem_u32(psm);

    const int z = blockIdx.z;
    const __half* Ah = g_xh + (size_t)z * XN;
    const __half* Bh = g_wh + (size_t)z * WN;
    __half* Oh = (z == 0) ? g_qh : (z == 1) ? g_kh : g_vh;

    const int tid   = threadIdx.x;
    const int wid   = tid >> 5;
    const int lane  = tid & 31;
    const int warpM = wid >> 1;
    const int warpN = wid & 1;
    const int m0    = blockIdx.y * 128;
    const int n0    = blockIdx.x * 64;

    const uint32_t aOff = ((uint32_t)(warpM * 32 + (lane & 15)) * SROW +
                           ((uint32_t)(lane >> 4) << 3)) * 2;
    const uint32_t bOff = ((uint32_t)(warpN * 32 + (lane & 7) + ((lane >> 4) << 3)) * SROW +
                           (((uint32_t)(lane >> 3) & 1) << 3)) * 2;

    float acc[2][4][4];
#pragma unroll
    for (int mf = 0; mf < 2; mf++)
#pragma unroll
        for (int nf = 0; nf < 4; nf++)
#pragma unroll
            for (int i = 0; i < 4; i++) acc[mf][nf][i] = 0.0f;

    const int ar = tid >> 2, ac = tid & 3;

    // Issue one chunk's A+B tiles into stage s (no commit; caller commits).
    auto load_chunk = [&](int c, int s) {
        const uint32_t bb = base + (uint32_t)s * PSTG;
        const int k0 = c * 32;
#pragma unroll
        for (int t = 0; t < 2; t++) {
            int i = tid + t * 256;
            int r = i >> 2, c8 = i & 3;
            cpa16(bb + (uint32_t)(r * SROW + c8 * 8) * 2,
                  Ah + (size_t)(m0 + r) * DM + k0 + c8 * 8);
        }
        cpa16(bb + PA_TB + (uint32_t)(ar * SROW + ac * 8) * 2,
              Bh + (size_t)(n0 + ar) * DM + k0 + ac * 8);
    };

    load_chunk(0, 0); CPA_COMMIT();
    load_chunk(1, 1); CPA_COMMIT();

    for (int c = 0; c < 32; c++) {
        CPA_WAIT1();
        __syncthreads();
        if (c + 2 < 32) load_chunk(c + 2, (c + 2) % 3);
        CPA_COMMIT();

        const uint32_t ah32 = base + (uint32_t)(c % 3) * PSTG;
        const uint32_t bh32 = ah32 + PA_TB;

#pragma unroll
        for (int ks = 0; ks < 2; ks++) {
            const uint32_t kByte = (uint32_t)(ks * 32);
            uint32_t ah[2][4], bh[2][4];
#pragma unroll
            for (int mf = 0; mf < 2; mf++)
                ldm4(ah[mf], ah32 + aOff + (uint32_t)(mf * 16 * SROW * 2) + kByte);
#pragma unroll
            for (int pp = 0; pp < 2; pp++)
                ldm4(bh[pp], bh32 + bOff + (uint32_t)(pp * 16 * SROW * 2) + kByte);
#pragma unroll
            for (int mf = 0; mf < 2; mf++)
#pragma unroll
                for (int nf = 0; nf < 4; nf++) {
                    const int pp = nf >> 1, q = (nf & 1) * 2;
                    mma_f16(acc[mf][nf], ah[mf], bh[pp][q], bh[pp][q+1]);
                }
        }
    }

    // Epilogue: fp16 hi (+ lo for Q) planes, [B, H, S, hw] layout.
    const int g  = lane >> 2;
    const int t2 = (lane & 3) << 1;
#pragma unroll
    for (int mf = 0; mf < 2; mf++) {
        int mA  = m0 + warpM * 32 + mf * 16 + g;
        int mB  = mA + 8;
        int bbA = mA >> 11, ssA = mA & (SEQ - 1);
        int bbB = mB >> 11, ssB = mB & (SEQ - 1);
#pragma unroll
        for (int nf = 0; nf < 4; nf++) {
            int n  = n0 + warpN * 32 + nf * 8 + t2;
            int hh = n >> 6, dd = n & 63;
            size_t offA = (((size_t)(bbA * NH + hh)) * SEQ + ssA) * HW + dd;
            size_t offB = (((size_t)(bbB * NH + hh)) * SEQ + ssB) * HW + dd;
            float r0, r1;
            uint32_t hp = packhi_h(acc[mf][nf][0], acc[mf][nf][1], r0, r1);
            *(uint32_t*)(Oh + offA) = hp;
            if (z == 0) *(uint32_t*)(g_ql + offA) = packlo_h(r0, r1);
            hp = packhi_h(acc[mf][nf][2], acc[mf][nf][3], r0, r1);
            *(uint32_t*)(Oh + offB) = hp;
            if (z == 0) *(uint32_t*)(g_ql + offB) = packlo_h(r0, r1);
        }
    }
}

// ---------------------------------------------------------------------------
// Flash attention on mma.sync fp16: Q hi/lo 2-pass, K/V single fp16.
// (unchanged from R10/R11 passing kernel)
// ---------------------------------------------------------------------------
#define AROW 72
#define QTB  (128*AROW*2)
#define KTB  (64*AROW*2)

__device__ __forceinline__ void tile_async64(uint32_t sbase, const __half* g,
                                             int row0, int tid) {
#pragma unroll
    for (int t = 0; t < 2; t++) {
        int i  = tid + t * 256;
        int r  = i >> 3, c8 = i & 7;
        cpa16(sbase + (uint32_t)(r * AROW + c8 * 8) * 2,
              g + (size_t)(row0 + r) * HW + c8 * 8);
    }
}

__global__ __launch_bounds__(256, 2) void attn_mma(float* __restrict__ out)
{
    extern __shared__ unsigned short asm_[];
    const uint32_t base = smem_u32(asm_);
    const uint32_t qh32 = base;
    const uint32_t ql32 = base + QTB;
    const uint32_t kvbase = base + 2 * QTB;

    const int bh = blockIdx.y;
    const int b  = bh >> 4;
    const int h  = bh & 15;
    const int qt = (int)gridDim.x - 1 - (int)blockIdx.x;
    const int q0 = qt * 128;

    const int tid  = threadIdx.x;
    const int warp = tid >> 5;
    const int lane = tid & 31;
    const int g    = lane >> 2;
    const int t2   = (lane & 3) << 1;

    const float SC2    = SM_SCALE * L2E;
    const float slope2 = exp2f(-0.5f * (float)(h + 1)) * L2E;

    const __half* Qh = g_qh + (size_t)bh * SEQ * HW;
    const __half* Ql = g_ql + (size_t)bh * SEQ * HW;
    const __half* Kh = g_kh + (size_t)bh * SEQ * HW;
    const __half* Vh = g_vh + (size_t)bh * SEQ * HW;

#pragma unroll
    for (int t = 0; t < 4; t++) {
        int i = tid + t * 256;
        int r = i >> 3, c8 = i & 7;
        uint32_t soff = (uint32_t)(r * AROW + c8 * 8) * 2;
        *(uint4*)((char*)asm_ + soff) =
            *(const uint4*)(Qh + (size_t)(q0 + r) * HW + c8 * 8);
        *(uint4*)((char*)asm_ + QTB + soff) =
            *(const uint4*)(Ql + (size_t)(q0 + r) * HW + c8 * 8);
    }

    const int nkt = 2 * qt + 2;
    tile_async64(kvbase + 0 * KTB, Kh, 0, tid);
    tile_async64(kvbase + 1 * KTB, Vh, 0, tid);
    CPA_COMMIT();
    if (1 < nkt) {
        tile_async64(kvbase + 2 * KTB, Kh, 64, tid);
        tile_async64(kvbase + 3 * KTB, Vh, 64, tid);
    }
    CPA_COMMIT();

    const uint32_t aElem = (uint32_t)((warp * 16 + (lane & 15)) * AROW + ((lane >> 4) << 3));
    const uint32_t bElem = (uint32_t)(((lane & 7) + ((lane >> 4) << 3)) * AROW + (((lane >> 3) & 1) << 3));
    const uint32_t vElem = (uint32_t)((lane & 15) * AROW + ((lane >> 4) << 3));

    float oacc[8][4];
#pragma unroll
    for (int nf = 0; nf < 8; nf++)
#pragma unroll
        for (int e = 0; e < 4; e++) oacc[nf][e] = 0.0f;

    float m0r = -3e38f, m1r = -3e38f, l0 = 0.0f, l1 = 0.0f;
    const int row0 = q0 + warp * 16 + g;
    const int row1 = row0 + 8;

    for (int kt = 0; kt < nkt; kt++) {
        CPA_WAIT1();
        __syncthreads();

        if (kt + 2 < nkt) {
            int s = (kt + 2) % 3;
            int r0n = (kt + 2) * 64;
            tile_async64(kvbase + (uint32_t)(2 * s + 0) * KTB, Kh, r0n, tid);
            tile_async64(kvbase + (uint32_t)(2 * s + 1) * KTB, Vh, r0n, tid);
        }
        CPA_COMMIT();

        const int s = kt % 3;
        const uint32_t kh32 = kvbase + (uint32_t)(2 * s + 0) * KTB;
        const uint32_t vh32 = kvbase + (uint32_t)(2 * s + 1) * KTB;
        const int k0g = kt * 64;

        float sacc[8][4];
#pragma unroll
        for (int nf = 0; nf < 8; nf++)
#pragma unroll
            for (int e = 0; e < 4; e++) sacc[nf][e] = 0.0f;

#pragma unroll
        for (int ks = 0; ks < 4; ks++) {
            uint32_t ah[4], al[4];
            ldm4(ah, qh32 + (aElem + ks * 16) * 2);
            ldm4(al, ql32 + (aElem + ks * 16) * 2);
#pragma unroll
            for (int pp = 0; pp < 4; pp++) {
                uint32_t bhx[4];
                uint32_t bd = (bElem + (uint32_t)(pp * 16 * AROW) + (uint32_t)(ks * 16)) * 2;
                ldm4(bhx, kh32 + bd);
                mma_f16(sacc[2*pp],   ah, bhx[0], bhx[1]);
                mma_f16(sacc[2*pp],   al, bhx[0], bhx[1]);
                mma_f16(sacc[2*pp+1], ah, bhx[2], bhx[3]);
                mma_f16(sacc[2*pp+1], al, bhx[2], bhx[3]);
            }
        }

        const bool diag = (kt >= 2 * qt);
        float mx0 = -3e38f, mx1 = -3e38f;
#pragma unroll
        for (int nf = 0; nf < 8; nf++) {
            int c0 = k0g + nf * 8 + t2;
            int c1 = c0 + 1;
            float v0 = sacc[nf][0] * SC2 + slope2 * (float)(c0 - row0);
            float v1 = sacc[nf][1] * SC2 + slope2 * (float)(c1 - row0);
            float v2 = sacc[nf][2] * SC2 + slope2 * (float)(c0 - row1);
            float v3 = sacc[nf][3] * SC2 + slope2 * (float)(c1 - row1);
            if (diag) {
                if (c0 > row0) v0 = -3e38f;
                if (c1 > row0) v1 = -3e38f;
                if (c0 > row1) v2 = -3e38f;
                if (c1 > row1) v3 = -3e38f;
            }
            sacc[nf][0] = v0; sacc[nf][1] = v1; sacc[nf][2] = v2; sacc[nf][3] = v3;
            mx0 = fmaxf(mx0, fmaxf(v0, v1));
            mx1 = fmaxf(mx1, fmaxf(v2, v3));
        }
        mx0 = fmaxf(mx0, __shfl_xor_sync(0xffffffffu, mx0, 1));
        mx0 = fmaxf(mx0, __shfl_xor_sync(0xffffffffu, mx0, 2));
        mx1 = fmaxf(mx1, __shfl_xor_sync(0xffffffffu, mx1, 1));
        mx1 = fmaxf(mx1, __shfl_xor_sync(0xffffffffu, mx1, 2));

        float mn0 = fmaxf(m0r, mx0);
        float mn1 = fmaxf(m1r, mx1);
        float corr0 = exp2f(m0r - mn0);
        float corr1 = exp2f(m1r - mn1);
        m0r = mn0; m1r = mn1;

        float rs0 = 0.0f, rs1 = 0.0f;
#pragma unroll
        for (int nf = 0; nf < 8; nf++) {
            float p0 = exp2f(sacc[nf][0] - mn0);
            float p1 = exp2f(sacc[nf][1] - mn0);
            float p2 = exp2f(sacc[nf][2] - mn1);
            float p3 = exp2f(sacc[nf][3] - mn1);
            sacc[nf][0] = p0; sacc[nf][1] = p1; sacc[nf][2] = p2; sacc[nf][3] = p3;
            rs0 += p0 + p1; rs1 += p2 + p3;
        }
        rs0 += __shfl_xor_sync(0xffffffffu, rs0, 1);
        rs0 += __shfl_xor_sync(0xffffffffu, rs0, 2);
        rs1 += __shfl_xor_sync(0xffffffffu, rs1, 1);
        rs1 += __shfl_xor_sync(0xffffffffu, rs1, 2);
        l0 = l0 * corr0 + rs0;
        l1 = l1 * corr1 + rs1;

#pragma unroll
        for (int nf = 0; nf < 8; nf++) {
            oacc[nf][0] *= corr0; oacc[nf][1] *= corr0;
            oacc[nf][2] *= corr1; oacc[nf][3] *= corr1;
        }

#pragma unroll
        for (int ks = 0; ks < 4; ks++) {
            uint32_t pah[4], pal[4];
            float r0, r1;
            pah[0] = packhi_h(sacc[2*ks][0],   sacc[2*ks][1],   r0, r1); pal[0] = packlo_h(r0, r1);
            pah[1] = packhi_h(sacc[2*ks][2],   sacc[2*ks][3],   r0, r1); pal[1] = packlo_h(r0, r1);
            pah[2] = packhi_h(sacc[2*ks+1][0], sacc[2*ks+1][1], r0, r1); pal[2] = packlo_h(r0, r1);
            pah[3] = packhi_h(sacc[2*ks+1][2], sacc[2*ks+1][3], r0, r1); pal[3] = packlo_h(r0, r1);
#pragma unroll
            for (int nb = 0; nb < 4; nb++) {
                uint32_t vhx[4];
                uint32_t vd = (vElem + (uint32_t)(ks * 16 * AROW) + (uint32_t)(nb * 16)) * 2;
                ldm4t(vhx, vh32 + vd);
                mma_f16(oacc[2*nb],   pah, vhx[0], vhx[1]);
                mma_f16(oacc[2*nb],   pal, vhx[0], vhx[1]);
                mma_f16(oacc[2*nb+1], pah, vhx[2], vhx[3]);
                mma_f16(oacc[2*nb+1], pal, vhx[2], vhx[3]);
            }
        }
    }

    const float inv0 = 1.0f / l0;
    const float inv1 = 1.0f / l1;
    float* op = out + (size_t)b * SEQ * DM + (size_t)h * HW;
#pragma unroll
    for (int nf = 0; nf < 8; nf++) {
        int col = nf * 8 + t2;
        *(float2*)(op + (size_t)row0 * DM + col) =
            make_float2(oacc[nf][0] * inv0, oacc[nf][1] * inv0);
        *(float2*)(op + (size_t)row1 * DM + col) =
            make_float2(oacc[nf][2] * inv1, oacc[nf][3] * inv1);
    }
}

// ---------------------------------------------------------------------------
// Launch: inputs order = queries, keys, values, mask, Wq, Wk, Wv.
// ---------------------------------------------------------------------------
extern "C" void kernel_launch(void* const* d_in, const int* in_sizes, int n_in,
                              void* d_out, int out_size)
{
    (void)in_sizes; (void)n_in; (void)out_size;
    const float4* q  = (const float4*)d_in[0];
    const float4* k  = (const float4*)d_in[1];
    const float4* v  = (const float4*)d_in[2];
    const float4* wq = (const float4*)d_in[4];
    const float4* wk = (const float4*)d_in[5];
    const float4* wv = (const float4*)d_in[6];
    float* out = (float*)d_out;

    const int proj_smem = 3 * PSTG;            // 46080 B
    cudaFuncSetAttribute(proj_mma, cudaFuncAttributeMaxDynamicSharedMemorySize, proj_smem);
    const int attn_smem = 2 * QTB + 6 * KTB;   // 92160 B
    cudaFuncSetAttribute(attn_mma, cudaFuncAttributeMaxDynamicSharedMemorySize, attn_smem);

    split_kernel<<<dim3(4096, 6), 256>>>(q, k, v, wq, wk, wv);
    proj_mma<<<dim3(DM/64, (BATCH*SEQ)/128, 3), 256, proj_smem>>>();
    attn_mma<<<dim3(SEQ/128, BATCH*NH), 256, attn_smem>>>(out);
}

// round 13
// speedup vs baseline: 2.1072x; 1.0726x over previous
#include <cuda_runtime.h>
#include <cuda_fp16.h>
#include <cstdint>
#include <math.h>

#define BATCH 2
#define SEQ   2048
#define DM    1024
#define NH    16
#define HW    64
#define SM_SCALE 0.125f   // 1/sqrt(64)
#define L2E   1.44269504f

#define NELEM (BATCH*NH*SEQ*HW)
#define XN    (BATCH*SEQ*DM)
#define WN    (DM*DM)

// Projected Q/K/V (single fp16 plane each) in [B, H, S, hw] layout.
__device__ __half g_qh[NELEM];
__device__ __half g_kh[NELEM];
__device__ __half g_vh[NELEM];
// fp16 planes of inputs X and weights W for the projections.
__device__ __half g_xh[3*XN];
__device__ __half g_wh[3*WN];

// ---------------------------------------------------------------------------
// Helpers
// ---------------------------------------------------------------------------
__device__ __forceinline__ uint32_t smem_u32(const void* p) {
    uint32_t a;
    asm("{ .reg .u64 t; cvta.to.shared.u64 t, %1; cvt.u32.u64 %0, t; }"
        : "=r"(a) : "l"(p));
    return a;
}

__device__ __forceinline__ void ldm4(uint32_t r[4], uint32_t addr) {
    asm volatile("ldmatrix.sync.aligned.m8n8.x4.shared.b16 {%0,%1,%2,%3}, [%4];"
                 : "=r"(r[0]), "=r"(r[1]), "=r"(r[2]), "=r"(r[3]) : "r"(addr));
}
__device__ __forceinline__ void ldm4t(uint32_t r[4], uint32_t addr) {
    asm volatile("ldmatrix.sync.aligned.m8n8.x4.trans.shared.b16 {%0,%1,%2,%3}, [%4];"
                 : "=r"(r[0]), "=r"(r[1]), "=r"(r[2]), "=r"(r[3]) : "r"(addr));
}

__device__ __forceinline__ void mma_f16(float acc[4], const uint32_t a[4],
                                        uint32_t b0, uint32_t b1) {
    asm volatile(
        "mma.sync.aligned.m16n8k16.row.col.f32.f16.f16.f32 "
        "{%0,%1,%2,%3}, {%4,%5,%6,%7}, {%8,%9}, {%0,%1,%2,%3};"
        : "+f"(acc[0]), "+f"(acc[1]), "+f"(acc[2]), "+f"(acc[3])
        : "r"(a[0]), "r"(a[1]), "r"(a[2]), "r"(a[3]), "r"(b0), "r"(b1));
}

// fp16 pack / hi-lo split
__device__ __forceinline__ uint32_t packhi_h(float a, float b, float& ra, float& rb) {
    __half2 h = __floats2half2_rn(a, b);
    ra = a - __half2float(__low2half(h));
    rb = b - __half2float(__high2half(h));
    return *reinterpret_cast<uint32_t*>(&h);
}
__device__ __forceinline__ uint32_t packlo_h(float a, float b) {
    __half2 h = __floats2half2_rn(a, b);
    return *reinterpret_cast<uint32_t*>(&h);
}

__device__ __forceinline__ void cpa16(uint32_t saddr, const void* g) {
    asm volatile("cp.async.cg.shared.global [%0], [%1], 16;"
                 :: "r"(saddr), "l"(g) : "memory");
}
#define CPA_COMMIT() asm volatile("cp.async.commit_group;" ::: "memory")
#define CPA_WAIT0()  asm volatile("cp.async.wait_group 0;" ::: "memory")
#define CPA_WAIT1()  asm volatile("cp.async.wait_group 1;" ::: "memory")

// ---------------------------------------------------------------------------
// Split inputs/weights into single fp16 planes (one bandwidth pass).
// ---------------------------------------------------------------------------
__global__ __launch_bounds__(256) void split_kernel(
    const float4* __restrict__ xq, const float4* __restrict__ xk,
    const float4* __restrict__ xv, const float4* __restrict__ wq,
    const float4* __restrict__ wk, const float4* __restrict__ wv)
{
    const int y = blockIdx.y;
    const float4* src;
    __half* dh;
    if (y < 3) {
        src = (y == 0) ? xq : (y == 1) ? xk : xv;
        dh = g_xh + (size_t)y * XN;
    } else {
        if (blockIdx.x >= 1024) return;
        int w = y - 3;
        src = (w == 0) ? wq : (w == 1) ? wk : wv;
        dh = g_wh + (size_t)w * WN;
    }
    size_t i = (size_t)blockIdx.x * 256 + threadIdx.x;
    float4 a = src[i];
    *(uint2*)(dh + i * 4) = make_uint2(packlo_h(a.x, a.y), packlo_h(a.z, a.w));
}

// ---------------------------------------------------------------------------
// Projection GEMM on mma.sync fp16, single pass, K-chunk 64 (halved syncs).
// CTA 128x64, warp tile 32x32, 8 warps (4M x 2N), 2 CTAs/SM.
// Rows of 64 fp16 padded to 72 (144B stride, conflict-free like attn tiles).
// grid = (16, 32, 3), block = 256. smem 2 x 27648 = 55296 B.
// ---------------------------------------------------------------------------
#define PROW   72
#define PA_TB  (128*PROW*2)        // 18432 B per A tile
#define PB_TB  (64*PROW*2)         // 9216 B per B tile
#define PSTG   (PA_TB + PB_TB)     // 27648 B per stage

__global__ __launch_bounds__(256, 2) void proj_mma()
{
    extern __shared__ unsigned short psm[];
    const uint32_t base = smem_u32(psm);

    const int z = blockIdx.z;
    const __half* Ah = g_xh + (size_t)z * XN;
    const __half* Bh = g_wh + (size_t)z * WN;
    __half* Oh = (z == 0) ? g_qh : (z == 1) ? g_kh : g_vh;

    const int tid   = threadIdx.x;
    const int wid   = tid >> 5;
    const int lane  = tid & 31;
    const int warpM = wid >> 1;
    const int warpN = wid & 1;
    const int m0    = blockIdx.y * 128;
    const int n0    = blockIdx.x * 64;

    const uint32_t aOff = ((uint32_t)(warpM * 32 + (lane & 15)) * PROW +
                           ((uint32_t)(lane >> 4) << 3)) * 2;
    const uint32_t bOff = ((uint32_t)(warpN * 32 + (lane & 7) + ((lane >> 4) << 3)) * PROW +
                           (((uint32_t)(lane >> 3) & 1) << 3)) * 2;

    float acc[2][4][4];
#pragma unroll
    for (int mf = 0; mf < 2; mf++)
#pragma unroll
        for (int nf = 0; nf < 4; nf++)
#pragma unroll
            for (int i = 0; i < 4; i++) acc[mf][nf][i] = 0.0f;

    // Issue one 64-col chunk's A+B tiles into stage s.
    auto load_chunk = [&](int c, int s) {
        const uint32_t bb = base + (uint32_t)s * PSTG;
        const int k0 = c * 64;
#pragma unroll
        for (int t = 0; t < 4; t++) {       // A: 128 rows x 8 x16B
            int i = tid + t * 256;
            int r = i >> 3, c8 = i & 7;
            cpa16(bb + (uint32_t)(r * PROW + c8 * 8) * 2,
                  Ah + (size_t)(m0 + r) * DM + k0 + c8 * 8);
        }
#pragma unroll
        for (int t = 0; t < 2; t++) {       // B: 64 rows x 8 x16B
            int i = tid + t * 256;
            int r = i >> 3, c8 = i & 7;
            cpa16(bb + PA_TB + (uint32_t)(r * PROW + c8 * 8) * 2,
                  Bh + (size_t)(n0 + r) * DM + k0 + c8 * 8);
        }
        CPA_COMMIT();
    };

    load_chunk(0, 0);

    for (int c = 0; c < 16; c++) {
        const int p = c & 1;
        CPA_WAIT0();
        __syncthreads();
        if (c < 15) load_chunk(c + 1, p ^ 1);

        const uint32_t ah32 = base + (uint32_t)p * PSTG;
        const uint32_t bh32 = ah32 + PA_TB;

#pragma unroll
        for (int ks = 0; ks < 4; ks++) {
            const uint32_t kByte = (uint32_t)(ks * 32);
            uint32_t ah[2][4], bh[2][4];
#pragma unroll
            for (int mf = 0; mf < 2; mf++)
                ldm4(ah[mf], ah32 + aOff + (uint32_t)(mf * 16 * PROW * 2) + kByte);
#pragma unroll
            for (int pp = 0; pp < 2; pp++)
                ldm4(bh[pp], bh32 + bOff + (uint32_t)(pp * 16 * PROW * 2) + kByte);
#pragma unroll
            for (int mf = 0; mf < 2; mf++)
#pragma unroll
                for (int nf = 0; nf < 4; nf++) {
                    const int pp = nf >> 1, q = (nf & 1) * 2;
                    mma_f16(acc[mf][nf], ah[mf], bh[pp][q], bh[pp][q+1]);
                }
        }
        __syncthreads();
    }

    // Epilogue: single fp16 plane, [B, H, S, hw] layout.
    const int g  = lane >> 2;
    const int t2 = (lane & 3) << 1;
#pragma unroll
    for (int mf = 0; mf < 2; mf++) {
        int mA  = m0 + warpM * 32 + mf * 16 + g;
        int mB  = mA + 8;
        int bbA = mA >> 11, ssA = mA & (SEQ - 1);
        int bbB = mB >> 11, ssB = mB & (SEQ - 1);
#pragma unroll
        for (int nf = 0; nf < 4; nf++) {
            int n  = n0 + warpN * 32 + nf * 8 + t2;
            int hh = n >> 6, dd = n & 63;
            size_t offA = (((size_t)(bbA * NH + hh)) * SEQ + ssA) * HW + dd;
            size_t offB = (((size_t)(bbB * NH + hh)) * SEQ + ssB) * HW + dd;
            *(uint32_t*)(Oh + offA) = packlo_h(acc[mf][nf][0], acc[mf][nf][1]);
            *(uint32_t*)(Oh + offB) = packlo_h(acc[mf][nf][2], acc[mf][nf][3]);
        }
    }
}

// ---------------------------------------------------------------------------
// Flash attention on mma.sync fp16: Q/K/V single fp16, P hi/lo 2-pass.
// K-tile 64 rows, 3-stage cp.async pipeline.
// smem = QTB + 6*KTB = 73728 B -> 2 CTAs/SM.
// ---------------------------------------------------------------------------
#define AROW 72
#define QTB  (128*AROW*2)
#define KTB  (64*AROW*2)

__device__ __forceinline__ void tile_async64(uint32_t sbase, const __half* g,
                                             int row0, int tid) {
#pragma unroll
    for (int t = 0; t < 2; t++) {
        int i  = tid + t * 256;
        int r  = i >> 3, c8 = i & 7;
        cpa16(sbase + (uint32_t)(r * AROW + c8 * 8) * 2,
              g + (size_t)(row0 + r) * HW + c8 * 8);
    }
}

__global__ __launch_bounds__(256, 2) void attn_mma(float* __restrict__ out)
{
    extern __shared__ unsigned short asm_[];
    const uint32_t base = smem_u32(asm_);
    const uint32_t qh32 = base;
    const uint32_t kvbase = base + QTB;

    const int bh = blockIdx.y;
    const int b  = bh >> 4;
    const int h  = bh & 15;
    const int qt = (int)gridDim.x - 1 - (int)blockIdx.x;
    const int q0 = qt * 128;

    const int tid  = threadIdx.x;
    const int warp = tid >> 5;
    const int lane = tid & 31;
    const int g    = lane >> 2;
    const int t2   = (lane & 3) << 1;

    const float SC2    = SM_SCALE * L2E;
    const float slope2 = exp2f(-0.5f * (float)(h + 1)) * L2E;

    const __half* Qh = g_qh + (size_t)bh * SEQ * HW;
    const __half* Kh = g_kh + (size_t)bh * SEQ * HW;
    const __half* Vh = g_vh + (size_t)bh * SEQ * HW;

    // ---- load Q tile (single fp16) ----
#pragma unroll
    for (int t = 0; t < 4; t++) {
        int i = tid + t * 256;
        int r = i >> 3, c8 = i & 7;
        *(uint4*)((char*)asm_ + (uint32_t)(r * AROW + c8 * 8) * 2) =
            *(const uint4*)(Qh + (size_t)(q0 + r) * HW + c8 * 8);
    }

    const int nkt = 2 * qt + 2;
    tile_async64(kvbase + 0 * KTB, Kh, 0, tid);
    tile_async64(kvbase + 1 * KTB, Vh, 0, tid);
    CPA_COMMIT();
    if (1 < nkt) {
        tile_async64(kvbase + 2 * KTB, Kh, 64, tid);
        tile_async64(kvbase + 3 * KTB, Vh, 64, tid);
    }
    CPA_COMMIT();

    const uint32_t aElem = (uint32_t)((warp * 16 + (lane & 15)) * AROW + ((lane >> 4) << 3));
    const uint32_t bElem = (uint32_t)(((lane & 7) + ((lane >> 4) << 3)) * AROW + (((lane >> 3) & 1) << 3));
    const uint32_t vElem = (uint32_t)((lane & 15) * AROW + ((lane >> 4) << 3));

    float oacc[8][4];
#pragma unroll
    for (int nf = 0; nf < 8; nf++)
#pragma unroll
        for (int e = 0; e < 4; e++) oacc[nf][e] = 0.0f;

    float m0r = -3e38f, m1r = -3e38f, l0 = 0.0f, l1 = 0.0f;
    const int row0 = q0 + warp * 16 + g;
    const int row1 = row0 + 8;

    for (int kt = 0; kt < nkt; kt++) {
        CPA_WAIT1();
        __syncthreads();

        if (kt + 2 < nkt) {
            int s = (kt + 2) % 3;
            int r0n = (kt + 2) * 64;
            tile_async64(kvbase + (uint32_t)(2 * s + 0) * KTB, Kh, r0n, tid);
            tile_async64(kvbase + (uint32_t)(2 * s + 1) * KTB, Vh, r0n, tid);
        }
        CPA_COMMIT();

        const int s = kt % 3;
        const uint32_t kh32 = kvbase + (uint32_t)(2 * s + 0) * KTB;
        const uint32_t vh32 = kvbase + (uint32_t)(2 * s + 1) * KTB;
        const int k0g = kt * 64;

        // ---- S = Q K^T (single-pass fp16) ----
        float sacc[8][4];
#pragma unroll
        for (int nf = 0; nf < 8; nf++)
#pragma unroll
            for (int e = 0; e < 4; e++) sacc[nf][e] = 0.0f;

#pragma unroll
        for (int ks = 0; ks < 4; ks++) {
            uint32_t ah[4];
            ldm4(ah, qh32 + (aElem + ks * 16) * 2);
#pragma unroll
            for (int pp = 0; pp < 4; pp++) {
                uint32_t bhx[4];
                uint32_t bd = (bElem + (uint32_t)(pp * 16 * AROW) + (uint32_t)(ks * 16)) * 2;
                ldm4(bhx, kh32 + bd);
                mma_f16(sacc[2*pp],   ah, bhx[0], bhx[1]);
                mma_f16(sacc[2*pp+1], ah, bhx[2], bhx[3]);
            }
        }

        // ---- scale + ALiBi + causal (log2 domain); online softmax ----
        const bool diag = (kt >= 2 * qt);
        float mx0 = -3e38f, mx1 = -3e38f;
#pragma unroll
        for (int nf = 0; nf < 8; nf++) {
            int c0 = k0g + nf * 8 + t2;
            int c1 = c0 + 1;
            float v0 = sacc[nf][0] * SC2 + slope2 * (float)(c0 - row0);
            float v1 = sacc[nf][1] * SC2 + slope2 * (float)(c1 - row0);
            float v2 = sacc[nf][2] * SC2 + slope2 * (float)(c0 - row1);
            float v3 = sacc[nf][3] * SC2 + slope2 * (float)(c1 - row1);
            if (diag) {
                if (c0 > row0) v0 = -3e38f;
                if (c1 > row0) v1 = -3e38f;
                if (c0 > row1) v2 = -3e38f;
                if (c1 > row1) v3 = -3e38f;
            }
            sacc[nf][0] = v0; sacc[nf][1] = v1; sacc[nf][2] = v2; sacc[nf][3] = v3;
            mx0 = fmaxf(mx0, fmaxf(v0, v1));
            mx1 = fmaxf(mx1, fmaxf(v2, v3));
        }
        mx0 = fmaxf(mx0, __shfl_xor_sync(0xffffffffu, mx0, 1));
        mx0 = fmaxf(mx0, __shfl_xor_sync(0xffffffffu, mx0, 2));
        mx1 = fmaxf(mx1, __shfl_xor_sync(0xffffffffu, mx1, 1));
        mx1 = fmaxf(mx1, __shfl_xor_sync(0xffffffffu, mx1, 2));

        float mn0 = fmaxf(m0r, mx0);
        float mn1 = fmaxf(m1r, mx1);
        float corr0 = exp2f(m0r - mn0);
        float corr1 = exp2f(m1r - mn1);
        m0r = mn0; m1r = mn1;

        float rs0 = 0.0f, rs1 = 0.0f;
#pragma unroll
        for (int nf = 0; nf < 8; nf++) {
            float p0 = exp2f(sacc[nf][0] - mn0);
            float p1 = exp2f(sacc[nf][1] - mn0);
            float p2 = exp2f(sacc[nf][2] - mn1);
            float p3 = exp2f(sacc[nf][3] - mn1);
            sacc[nf][0] = p0; sacc[nf][1] = p1; sacc[nf][2] = p2; sacc[nf][3] = p3;
            rs0 += p0 + p1; rs1 += p2 + p3;
        }
        rs0 += __shfl_xor_sync(0xffffffffu, rs0, 1);
        rs0 += __shfl_xor_sync(0xffffffffu, rs0, 2);
        rs1 += __shfl_xor_sync(0xffffffffu, rs1, 1);
        rs1 += __shfl_xor_sync(0xffffffffu, rs1, 2);
        l0 = l0 * corr0 + rs0;
        l1 = l1 * corr1 + rs1;

#pragma unroll
        for (int nf = 0; nf < 8; nf++) {
            oacc[nf][0] *= corr0; oacc[nf][1] *= corr0;
            oacc[nf][2] *= corr1; oacc[nf][3] *= corr1;
        }

        // ---- O += P V (P hi/lo fp16 2-pass, V single) ----
#pragma unroll
        for (int ks = 0; ks < 4; ks++) {
            uint32_t pah[4], pal[4];
            float r0, r1;
            pah[0] = packhi_h(sacc[2*ks][0],   sacc[2*ks][1],   r0, r1); pal[0] = packlo_h(r0, r1);
            pah[1] = packhi_h(sacc[2*ks][2],   sacc[2*ks][3],   r0, r1); pal[1] = packlo_h(r0, r1);
            pah[2] = packhi_h(sacc[2*ks+1][0], sacc[2*ks+1][1], r0, r1); pal[2] = packlo_h(r0, r1);
            pah[3] = packhi_h(sacc[2*ks+1][2], sacc[2*ks+1][3], r0, r1); pal[3] = packlo_h(r0, r1);
#pragma unroll
            for (int nb = 0; nb < 4; nb++) {
                uint32_t vhx[4];
                uint32_t vd = (vElem + (uint32_t)(ks * 16 * AROW) + (uint32_t)(nb * 16)) * 2;
                ldm4t(vhx, vh32 + vd);
                mma_f16(oacc[2*nb],   pah, vhx[0], vhx[1]);
                mma_f16(oacc[2*nb],   pal, vhx[0], vhx[1]);
                mma_f16(oacc[2*nb+1], pah, vhx[2], vhx[3]);
                mma_f16(oacc[2*nb+1], pal, vhx[2], vhx[3]);
            }
        }
    }

    // ---- epilogue: normalize + store to [B, S, D] ----
    const float inv0 = 1.0f / l0;
    const float inv1 = 1.0f / l1;
    float* op = out + (size_t)b * SEQ * DM + (size_t)h * HW;
#pragma unroll
    for (int nf = 0; nf < 8; nf++) {
        int col = nf * 8 + t2;
        *(float2*)(op + (size_t)row0 * DM + col) =
            make_float2(oacc[nf][0] * inv0, oacc[nf][1] * inv0);
        *(float2*)(op + (size_t)row1 * DM + col) =
            make_float2(oacc[nf][2] * inv1, oacc[nf][3] * inv1);
    }
}

// ---------------------------------------------------------------------------
// Launch: inputs order = queries, keys, values, mask, Wq, Wk, Wv.
// ---------------------------------------------------------------------------
extern "C" void kernel_launch(void* const* d_in, const int* in_sizes, int n_in,
                              void* d_out, int out_size)
{
    (void)in_sizes; (void)n_in; (void)out_size;
    const float4* q  = (const float4*)d_in[0];
    const float4* k  = (const float4*)d_in[1];
    const float4* v  = (const float4*)d_in[2];
    const float4* wq = (const float4*)d_in[4];
    const float4* wk = (const float4*)d_in[5];
    const float4* wv = (const float4*)d_in[6];
    float* out = (float*)d_out;

    const int proj_smem = 2 * PSTG;            // 55296 B
    cudaFuncSetAttribute(proj_mma, cudaFuncAttributeMaxDynamicSharedMemorySize, proj_smem);
    const int attn_smem = QTB + 6 * KTB;       // 73728 B
    cudaFuncSetAttribute(attn_mma, cudaFuncAttributeMaxDynamicSharedMemorySize, attn_smem);

    split_kernel<<<dim3(4096, 6), 256>>>(q, k, v, wq, wk, wv);
    proj_mma<<<dim3(DM/64, (BATCH*SEQ)/128, 3), 256, proj_smem>>>();
    attn_mma<<<dim3(SEQ/128, BATCH*NH), 256, attn_smem>>>(out);
}

// round 14
// speedup vs baseline: 2.4023x; 1.1401x over previous
#include <cuda_runtime.h>
#include <cuda_fp16.h>
#include <cstdint>
#include <math.h>

#define BATCH 2
#define SEQ   2048
#define DM    1024
#define NH    16
#define HW    64
#define SM_SCALE 0.125f   // 1/sqrt(64)
#define L2E   1.44269504f

#define NELEM (BATCH*NH*SEQ*HW)
#define XN    (BATCH*SEQ*DM)
#define WN    (DM*DM)

// Projected Q/K/V (single fp16 plane each) in [B, H, S, hw] layout.
__device__ __half g_qh[NELEM];
__device__ __half g_kh[NELEM];
__device__ __half g_vh[NELEM];
// fp16 planes of inputs X and weights W for the projections.
__device__ __half g_xh[3*XN];
__device__ __half g_wh[3*WN];

// ---------------------------------------------------------------------------
// Helpers
// ---------------------------------------------------------------------------
__device__ __forceinline__ uint32_t smem_u32(const void* p) {
    uint32_t a;
    asm("{ .reg .u64 t; cvta.to.shared.u64 t, %1; cvt.u32.u64 %0, t; }"
        : "=r"(a) : "l"(p));
    return a;
}

__device__ __forceinline__ void ldm4(uint32_t r[4], uint32_t addr) {
    asm volatile("ldmatrix.sync.aligned.m8n8.x4.shared.b16 {%0,%1,%2,%3}, [%4];"
                 : "=r"(r[0]), "=r"(r[1]), "=r"(r[2]), "=r"(r[3]) : "r"(addr));
}
__device__ __forceinline__ void ldm4t(uint32_t r[4], uint32_t addr) {
    asm volatile("ldmatrix.sync.aligned.m8n8.x4.trans.shared.b16 {%0,%1,%2,%3}, [%4];"
                 : "=r"(r[0]), "=r"(r[1]), "=r"(r[2]), "=r"(r[3]) : "r"(addr));
}

__device__ __forceinline__ void mma_f16(float acc[4], const uint32_t a[4],
                                        uint32_t b0, uint32_t b1) {
    asm volatile(
        "mma.sync.aligned.m16n8k16.row.col.f32.f16.f16.f32 "
        "{%0,%1,%2,%3}, {%4,%5,%6,%7}, {%8,%9}, {%0,%1,%2,%3};"
        : "+f"(acc[0]), "+f"(acc[1]), "+f"(acc[2]), "+f"(acc[3])
        : "r"(a[0]), "r"(a[1]), "r"(a[2]), "r"(a[3]), "r"(b0), "r"(b1));
}

__device__ __forceinline__ uint32_t packlo_h(float a, float b) {
    __half2 h = __floats2half2_rn(a, b);
    return *reinterpret_cast<uint32_t*>(&h);
}

__device__ __forceinline__ void cpa16(uint32_t saddr, const void* g) {
    asm volatile("cp.async.cg.shared.global [%0], [%1], 16;"
                 :: "r"(saddr), "l"(g) : "memory");
}
#define CPA_COMMIT() asm volatile("cp.async.commit_group;" ::: "memory")
#define CPA_WAIT1()  asm volatile("cp.async.wait_group 1;" ::: "memory")

// ---------------------------------------------------------------------------
// Split inputs/weights into single fp16 planes (one bandwidth pass).
// ---------------------------------------------------------------------------
__global__ __launch_bounds__(256) void split_kernel(
    const float4* __restrict__ xq, const float4* __restrict__ xk,
    const float4* __restrict__ xv, const float4* __restrict__ wq,
    const float4* __restrict__ wk, const float4* __restrict__ wv)
{
    const int y = blockIdx.y;
    const float4* src;
    __half* dh;
    if (y < 3) {
        src = (y == 0) ? xq : (y == 1) ? xk : xv;
        dh = g_xh + (size_t)y * XN;
    } else {
        if (blockIdx.x >= 1024) return;
        int w = y - 3;
        src = (w == 0) ? wq : (w == 1) ? wk : wv;
        dh = g_wh + (size_t)w * WN;
    }
    size_t i = (size_t)blockIdx.x * 256 + threadIdx.x;
    float4 a = src[i];
    *(uint2*)(dh + i * 4) = make_uint2(packlo_h(a.x, a.y), packlo_h(a.z, a.w));
}

// ---------------------------------------------------------------------------
// Projection GEMM on mma.sync fp16, single pass.
// CTA 128x128, warp tile 32x64, 8 warps (4M x 2N), 2 CTAs/SM.
// K-chunk 32, 3-stage cp.async pipeline. smem 3 x 20480 = 61440 B.
// grid = (8, 32, 3), block = 256.
// ---------------------------------------------------------------------------
#define SROW   40
#define PA_TB  (128*SROW*2)        // 10240 B per A tile (128 rows x 32 fp16)
#define PB_TB  (128*SROW*2)        // 10240 B per B tile
#define PSTG   (PA_TB + PB_TB)     // 20480 B per stage

__global__ __launch_bounds__(256, 2) void proj_mma()
{
    extern __shared__ unsigned short psm[];
    const uint32_t base = smem_u32(psm);

    const int z = blockIdx.z;
    const __half* Ah = g_xh + (size_t)z * XN;
    const __half* Bh = g_wh + (size_t)z * WN;
    __half* Oh = (z == 0) ? g_qh : (z == 1) ? g_kh : g_vh;

    const int tid   = threadIdx.x;
    const int wid   = tid >> 5;
    const int lane  = tid & 31;
    const int warpM = wid >> 1;      // 0..3 -> 32 rows
    const int warpN = wid & 1;       // 0..1 -> 64 cols
    const int m0    = blockIdx.y * 128;
    const int n0    = blockIdx.x * 128;

    const uint32_t aOff = ((uint32_t)(warpM * 32 + (lane & 15)) * SROW +
                           ((uint32_t)(lane >> 4) << 3)) * 2;
    const uint32_t bOff = ((uint32_t)(warpN * 64 + (lane & 7) + ((lane >> 4) << 3)) * SROW +
                           (((uint32_t)(lane >> 3) & 1) << 3)) * 2;

    float acc[2][8][4];
#pragma unroll
    for (int mf = 0; mf < 2; mf++)
#pragma unroll
        for (int nf = 0; nf < 8; nf++)
#pragma unroll
            for (int i = 0; i < 4; i++) acc[mf][nf][i] = 0.0f;

    // Per chunk: A = 512 x 16B, B = 512 x 16B -> 2+2 cpa16 per thread.
    auto load_chunk = [&](int c, int s) {
        const uint32_t bb = base + (uint32_t)s * PSTG;
        const int k0 = c * 32;
#pragma unroll
        for (int t = 0; t < 2; t++) {
            int i = tid + t * 256;
            int r = i >> 2, c8 = i & 3;
            uint32_t soff = (uint32_t)(r * SROW + c8 * 8) * 2;
            cpa16(bb + soff, Ah + (size_t)(m0 + r) * DM + k0 + c8 * 8);
            cpa16(bb + PA_TB + soff, Bh + (size_t)(n0 + r) * DM + k0 + c8 * 8);
        }
    };

    load_chunk(0, 0); CPA_COMMIT();
    load_chunk(1, 1); CPA_COMMIT();

    for (int c = 0; c < 32; c++) {
        CPA_WAIT1();
        __syncthreads();
        if (c + 2 < 32) load_chunk(c + 2, (c + 2) % 3);
        CPA_COMMIT();

        const uint32_t ah32 = base + (uint32_t)(c % 3) * PSTG;
        const uint32_t bh32 = ah32 + PA_TB;

#pragma unroll
        for (int ks = 0; ks < 2; ks++) {
            const uint32_t kByte = (uint32_t)(ks * 32);
            uint32_t ah[2][4], bh[4][4];
#pragma unroll
            for (int mf = 0; mf < 2; mf++)
                ldm4(ah[mf], ah32 + aOff + (uint32_t)(mf * 16 * SROW * 2) + kByte);
#pragma unroll
            for (int pp = 0; pp < 4; pp++)
                ldm4(bh[pp], bh32 + bOff + (uint32_t)(pp * 16 * SROW * 2) + kByte);
#pragma unroll
            for (int mf = 0; mf < 2; mf++)
#pragma unroll
                for (int nf = 0; nf < 8; nf++) {
                    const int pp = nf >> 1, q = (nf & 1) * 2;
                    mma_f16(acc[mf][nf], ah[mf], bh[pp][q], bh[pp][q+1]);
                }
        }
    }

    // Epilogue: single fp16 plane, [B, H, S, hw] layout.
    const int g  = lane >> 2;
    const int t2 = (lane & 3) << 1;
#pragma unroll
    for (int mf = 0; mf < 2; mf++) {
        int mA  = m0 + warpM * 32 + mf * 16 + g;
        int mB  = mA + 8;
        int bbA = mA >> 11, ssA = mA & (SEQ - 1);
        int bbB = mB >> 11, ssB = mB & (SEQ - 1);
#pragma unroll
        for (int nf = 0; nf < 8; nf++) {
            int n  = n0 + warpN * 64 + nf * 8 + t2;
            int hh = n >> 6, dd = n & 63;
            size_t offA = (((size_t)(bbA * NH + hh)) * SEQ + ssA) * HW + dd;
            size_t offB = (((size_t)(bbB * NH + hh)) * SEQ + ssB) * HW + dd;
            *(uint32_t*)(Oh + offA) = packlo_h(acc[mf][nf][0], acc[mf][nf][1]);
            *(uint32_t*)(Oh + offB) = packlo_h(acc[mf][nf][2], acc[mf][nf][3]);
        }
    }
}

// ---------------------------------------------------------------------------
// Flash attention on mma.sync fp16: Q/K/V/P all single fp16 (fp32 accum).
// K-tile 64 rows, 3-stage cp.async pipeline. smem = QTB + 6*KTB = 73728 B.
// ---------------------------------------------------------------------------
#define AROW 72
#define QTB  (128*AROW*2)
#define KTB  (64*AROW*2)

__device__ __forceinline__ void tile_async64(uint32_t sbase, const __half* g,
                                             int row0, int tid) {
#pragma unroll
    for (int t = 0; t < 2; t++) {
        int i  = tid + t * 256;
        int r  = i >> 3, c8 = i & 7;
        cpa16(sbase + (uint32_t)(r * AROW + c8 * 8) * 2,
              g + (size_t)(row0 + r) * HW + c8 * 8);
    }
}

__global__ __launch_bounds__(256, 2) void attn_mma(float* __restrict__ out)
{
    extern __shared__ unsigned short asm_[];
    const uint32_t base = smem_u32(asm_);
    const uint32_t qh32 = base;
    const uint32_t kvbase = base + QTB;

    const int bh = blockIdx.y;
    const int b  = bh >> 4;
    const int h  = bh & 15;
    const int qt = (int)gridDim.x - 1 - (int)blockIdx.x;
    const int q0 = qt * 128;

    const int tid  = threadIdx.x;
    const int warp = tid >> 5;
    const int lane = tid & 31;
    const int g    = lane >> 2;
    const int t2   = (lane & 3) << 1;

    const float SC2    = SM_SCALE * L2E;
    const float slope2 = exp2f(-0.5f * (float)(h + 1)) * L2E;

    const __half* Qh = g_qh + (size_t)bh * SEQ * HW;
    const __half* Kh = g_kh + (size_t)bh * SEQ * HW;
    const __half* Vh = g_vh + (size_t)bh * SEQ * HW;

#pragma unroll
    for (int t = 0; t < 4; t++) {
        int i = tid + t * 256;
        int r = i >> 3, c8 = i & 7;
        *(uint4*)((char*)asm_ + (uint32_t)(r * AROW + c8 * 8) * 2) =
            *(const uint4*)(Qh + (size_t)(q0 + r) * HW + c8 * 8);
    }

    const int nkt = 2 * qt + 2;
    tile_async64(kvbase + 0 * KTB, Kh, 0, tid);
    tile_async64(kvbase + 1 * KTB, Vh, 0, tid);
    CPA_COMMIT();
    if (1 < nkt) {
        tile_async64(kvbase + 2 * KTB, Kh, 64, tid);
        tile_async64(kvbase + 3 * KTB, Vh, 64, tid);
    }
    CPA_COMMIT();

    const uint32_t aElem = (uint32_t)((warp * 16 + (lane & 15)) * AROW + ((lane >> 4) << 3));
    const uint32_t bElem = (uint32_t)(((lane & 7) + ((lane >> 4) << 3)) * AROW + (((lane >> 3) & 1) << 3));
    const uint32_t vElem = (uint32_t)((lane & 15) * AROW + ((lane >> 4) << 3));

    float oacc[8][4];
#pragma unroll
    for (int nf = 0; nf < 8; nf++)
#pragma unroll
        for (int e = 0; e < 4; e++) oacc[nf][e] = 0.0f;

    float m0r = -3e38f, m1r = -3e38f, l0 = 0.0f, l1 = 0.0f;
    const int row0 = q0 + warp * 16 + g;
    const int row1 = row0 + 8;

    for (int kt = 0; kt < nkt; kt++) {
        CPA_WAIT1();
        __syncthreads();

        if (kt + 2 < nkt) {
            int s = (kt + 2) % 3;
            int r0n = (kt + 2) * 64;
            tile_async64(kvbase + (uint32_t)(2 * s + 0) * KTB, Kh, r0n, tid);
            tile_async64(kvbase + (uint32_t)(2 * s + 1) * KTB, Vh, r0n, tid);
        }
        CPA_COMMIT();

        const int s = kt % 3;
        const uint32_t kh32 = kvbase + (uint32_t)(2 * s + 0) * KTB;
        const uint32_t vh32 = kvbase + (uint32_t)(2 * s + 1) * KTB;
        const int k0g = kt * 64;

        // ---- S = Q K^T (single-pass fp16) ----
        float sacc[8][4];
#pragma unroll
        for (int nf = 0; nf < 8; nf++)
#pragma unroll
            for (int e = 0; e < 4; e++) sacc[nf][e] = 0.0f;

#pragma unroll
        for (int ks = 0; ks < 4; ks++) {
            uint32_t ah[4];
            ldm4(ah, qh32 + (aElem + ks * 16) * 2);
#pragma unroll
            for (int pp = 0; pp < 4; pp++) {
                uint32_t bhx[4];
                uint32_t bd = (bElem + (uint32_t)(pp * 16 * AROW) + (uint32_t)(ks * 16)) * 2;
                ldm4(bhx, kh32 + bd);
                mma_f16(sacc[2*pp],   ah, bhx[0], bhx[1]);
                mma_f16(sacc[2*pp+1], ah, bhx[2], bhx[3]);
            }
        }

        // ---- scale + ALiBi + causal (log2 domain); online softmax ----
        const bool diag = (kt >= 2 * qt);
        float mx0 = -3e38f, mx1 = -3e38f;
#pragma unroll
        for (int nf = 0; nf < 8; nf++) {
            int c0 = k0g + nf * 8 + t2;
            int c1 = c0 + 1;
            float v0 = sacc[nf][0] * SC2 + slope2 * (float)(c0 - row0);
            float v1 = sacc[nf][1] * SC2 + slope2 * (float)(c1 - row0);
            float v2 = sacc[nf][2] * SC2 + slope2 * (float)(c0 - row1);
            float v3 = sacc[nf][3] * SC2 + slope2 * (float)(c1 - row1);
            if (diag) {
                if (c0 > row0) v0 = -3e38f;
                if (c1 > row0) v1 = -3e38f;
                if (c0 > row1) v2 = -3e38f;
                if (c1 > row1) v3 = -3e38f;
            }
            sacc[nf][0] = v0; sacc[nf][1] = v1; sacc[nf][2] = v2; sacc[nf][3] = v3;
            mx0 = fmaxf(mx0, fmaxf(v0, v1));
            mx1 = fmaxf(mx1, fmaxf(v2, v3));
        }
        mx0 = fmaxf(mx0, __shfl_xor_sync(0xffffffffu, mx0, 1));
        mx0 = fmaxf(mx0, __shfl_xor_sync(0xffffffffu, mx0, 2));
        mx1 = fmaxf(mx1, __shfl_xor_sync(0xffffffffu, mx1, 1));
        mx1 = fmaxf(mx1, __shfl_xor_sync(0xffffffffu, mx1, 2));

        float mn0 = fmaxf(m0r, mx0);
        float mn1 = fmaxf(m1r, mx1);
        float corr0 = exp2f(m0r - mn0);
        float corr1 = exp2f(m1r - mn1);
        m0r = mn0; m1r = mn1;

        float rs0 = 0.0f, rs1 = 0.0f;
#pragma unroll
        for (int nf = 0; nf < 8; nf++) {
            float p0 = exp2f(sacc[nf][0] - mn0);
            float p1 = exp2f(sacc[nf][1] - mn0);
            float p2 = exp2f(sacc[nf][2] - mn1);
            float p3 = exp2f(sacc[nf][3] - mn1);
            sacc[nf][0] = p0; sacc[nf][1] = p1; sacc[nf][2] = p2; sacc[nf][3] = p3;
            rs0 += p0 + p1; rs1 += p2 + p3;
        }
        rs0 += __shfl_xor_sync(0xffffffffu, rs0, 1);
        rs0 += __shfl_xor_sync(0xffffffffu, rs0, 2);
        rs1 += __shfl_xor_sync(0xffffffffu, rs1, 1);
        rs1 += __shfl_xor_sync(0xffffffffu, rs1, 2);
        l0 = l0 * corr0 + rs0;
        l1 = l1 * corr1 + rs1;

#pragma unroll
        for (int nf = 0; nf < 8; nf++) {
            oacc[nf][0] *= corr0; oacc[nf][1] *= corr0;
            oacc[nf][2] *= corr1; oacc[nf][3] *= corr1;
        }

        // ---- O += P V (single-pass fp16) ----
#pragma unroll
        for (int ks = 0; ks < 4; ks++) {
            uint32_t pah[4];
            pah[0] = packlo_h(sacc[2*ks][0],   sacc[2*ks][1]);
            pah[1] = packlo_h(sacc[2*ks][2],   sacc[2*ks][3]);
            pah[2] = packlo_h(sacc[2*ks+1][0], sacc[2*ks+1][1]);
            pah[3] = packlo_h(sacc[2*ks+1][2], sacc[2*ks+1][3]);
#pragma unroll
            for (int nb = 0; nb < 4; nb++) {
                uint32_t vhx[4];
                uint32_t vd = (vElem + (uint32_t)(ks * 16 * AROW) + (uint32_t)(nb * 16)) * 2;
                ldm4t(vhx, vh32 + vd);
                mma_f16(oacc[2*nb],   pah, vhx[0], vhx[1]);
                mma_f16(oacc[2*nb+1], pah, vhx[2], vhx[3]);
            }
        }
    }

    // ---- epilogue: normalize + store to [B, S, D] ----
    const float inv0 = 1.0f / l0;
    const float inv1 = 1.0f / l1;
    float* op = out + (size_t)b * SEQ * DM + (size_t)h * HW;
#pragma unroll
    for (int nf = 0; nf < 8; nf++) {
        int col = nf * 8 + t2;
        *(float2*)(op + (size_t)row0 * DM + col) =
            make_float2(oacc[nf][0] * inv0, oacc[nf][1] * inv0);
        *(float2*)(op + (size_t)row1 * DM + col) =
            make_float2(oacc[nf][2] * inv1, oacc[nf][3] * inv1);
    }
}

// ---------------------------------------------------------------------------
// Launch: inputs order = queries, keys, values, mask, Wq, Wk, Wv.
// ---------------------------------------------------------------------------
extern "C" void kernel_launch(void* const* d_in, const int* in_sizes, int n_in,
                              void* d_out, int out_size)
{
    (void)in_sizes; (void)n_in; (void)out_size;
    const float4* q  = (const float4*)d_in[0];
    const float4* k  = (const float4*)d_in[1];
    const float4* v  = (const float4*)d_in[2];
    const float4* wq = (const float4*)d_in[4];
    const float4* wk = (const float4*)d_in[5];
    const float4* wv = (const float4*)d_in[6];
    float* out = (float*)d_out;

    const int proj_smem = 3 * PSTG;            // 61440 B
    cudaFuncSetAttribute(proj_mma, cudaFuncAttributeMaxDynamicSharedMemorySize, proj_smem);
    const int attn_smem = QTB + 6 * KTB;       // 73728 B
    cudaFuncSetAttribute(attn_mma, cudaFuncAttributeMaxDynamicSharedMemorySize, attn_smem);

    split_kernel<<<dim3(4096, 6), 256>>>(q, k, v, wq, wk, wv);
    proj_mma<<<dim3(DM/128, (BATCH*SEQ)/128, 3), 256, proj_smem>>>();
    attn_mma<<<dim3(SEQ/128, BATCH*NH), 256, attn_smem>>>(out);
}

// round 15
// speedup vs baseline: 2.5163x; 1.0475x over previous
#include <cuda_runtime.h>
#include <cuda_fp16.h>
#include <cstdint>
#include <math.h>

#define BATCH 2
#define SEQ   2048
#define DM    1024
#define NH    16
#define HW    64
#define SM_SCALE 0.125f   // 1/sqrt(64)
#define L2E   1.44269504f

#define NELEM (BATCH*NH*SEQ*HW)
#define XN    (BATCH*SEQ*DM)
#define WN    (DM*DM)

// Projected Q/K/V (single fp16 plane each) in [B, H, S, hw] layout.
__device__ __half g_qh[NELEM];
__device__ __half g_kh[NELEM];
__device__ __half g_vh[NELEM];
// fp16 planes of inputs X and weights W for the projections.
__device__ __half g_xh[3*XN];
__device__ __half g_wh[3*WN];

// ---------------------------------------------------------------------------
// Helpers
// ---------------------------------------------------------------------------
__device__ __forceinline__ uint32_t smem_u32(const void* p) {
    uint32_t a;
    asm("{ .reg .u64 t; cvta.to.shared.u64 t, %1; cvt.u32.u64 %0, t; }"
        : "=r"(a) : "l"(p));
    return a;
}

__device__ __forceinline__ void ldm4(uint32_t r[4], uint32_t addr) {
    asm volatile("ldmatrix.sync.aligned.m8n8.x4.shared.b16 {%0,%1,%2,%3}, [%4];"
                 : "=r"(r[0]), "=r"(r[1]), "=r"(r[2]), "=r"(r[3]) : "r"(addr));
}
__device__ __forceinline__ void ldm4t(uint32_t r[4], uint32_t addr) {
    asm volatile("ldmatrix.sync.aligned.m8n8.x4.trans.shared.b16 {%0,%1,%2,%3}, [%4];"
                 : "=r"(r[0]), "=r"(r[1]), "=r"(r[2]), "=r"(r[3]) : "r"(addr));
}

__device__ __forceinline__ void mma_f16(float acc[4], const uint32_t a[4],
                                        uint32_t b0, uint32_t b1) {
    asm volatile(
        "mma.sync.aligned.m16n8k16.row.col.f32.f16.f16.f32 "
        "{%0,%1,%2,%3}, {%4,%5,%6,%7}, {%8,%9}, {%0,%1,%2,%3};"
        : "+f"(acc[0]), "+f"(acc[1]), "+f"(acc[2]), "+f"(acc[3])
        : "r"(a[0]), "r"(a[1]), "r"(a[2]), "r"(a[3]), "r"(b0), "r"(b1));
}

__device__ __forceinline__ uint32_t packlo_h(float a, float b) {
    __half2 h = __floats2half2_rn(a, b);
    return *reinterpret_cast<uint32_t*>(&h);
}

__device__ __forceinline__ void cpa16(uint32_t saddr, const void* g) {
    asm volatile("cp.async.cg.shared.global [%0], [%1], 16;"
                 :: "r"(saddr), "l"(g) : "memory");
}
#define CPA_COMMIT() asm volatile("cp.async.commit_group;" ::: "memory")
#define CPA_WAIT0()  asm volatile("cp.async.wait_group 0;" ::: "memory")

// ---------------------------------------------------------------------------
// Split inputs/weights into single fp16 planes (one bandwidth pass).
// ---------------------------------------------------------------------------
__global__ __launch_bounds__(256) void split_kernel(
    const float4* __restrict__ xq, const float4* __restrict__ xk,
    const float4* __restrict__ xv, const float4* __restrict__ wq,
    const float4* __restrict__ wk, const float4* __restrict__ wv)
{
    const int y = blockIdx.y;
    const float4* src;
    __half* dh;
    if (y < 3) {
        src = (y == 0) ? xq : (y == 1) ? xk : xv;
        dh = g_xh + (size_t)y * XN;
    } else {
        if (blockIdx.x >= 1024) return;
        int w = y - 3;
        src = (w == 0) ? wq : (w == 1) ? wk : wv;
        dh = g_wh + (size_t)w * WN;
    }
    size_t i = (size_t)blockIdx.x * 256 + threadIdx.x;
    float4 a = src[i];
    *(uint2*)(dh + i * 4) = make_uint2(packlo_h(a.x, a.y), packlo_h(a.z, a.w));
}

// ---------------------------------------------------------------------------
// Projection GEMM on mma.sync fp16, single pass.
// CTA 128x128, warp tile 32x64, 8 warps (4M x 2N), 2 CTAs/SM.
// K-chunk 32, 4 stages, TWO chunks per iteration, ONE barrier per pair.
// grid = (8, 32, 3), block = 256. smem 4 x 20480 = 81920 B.
// ---------------------------------------------------------------------------
#define SROW   40
#define PA_TB  (128*SROW*2)        // 10240 B per A tile (128 rows x 32 fp16)
#define PB_TB  (128*SROW*2)        // 10240 B per B tile
#define PSTG   (PA_TB + PB_TB)     // 20480 B per stage

__global__ __launch_bounds__(256, 2) void proj_mma()
{
    extern __shared__ unsigned short psm[];
    const uint32_t base = smem_u32(psm);

    const int z = blockIdx.z;
    const __half* Ah = g_xh + (size_t)z * XN;
    const __half* Bh = g_wh + (size_t)z * WN;
    __half* Oh = (z == 0) ? g_qh : (z == 1) ? g_kh : g_vh;

    const int tid   = threadIdx.x;
    const int wid   = tid >> 5;
    const int lane  = tid & 31;
    const int warpM = wid >> 1;
    const int warpN = wid & 1;
    const int m0    = blockIdx.y * 128;
    const int n0    = blockIdx.x * 128;

    const uint32_t aOff = ((uint32_t)(warpM * 32 + (lane & 15)) * SROW +
                           ((uint32_t)(lane >> 4) << 3)) * 2;
    const uint32_t bOff = ((uint32_t)(warpN * 64 + (lane & 7) + ((lane >> 4) << 3)) * SROW +
                           (((uint32_t)(lane >> 3) & 1) << 3)) * 2;

    float acc[2][8][4];
#pragma unroll
    for (int mf = 0; mf < 2; mf++)
#pragma unroll
        for (int nf = 0; nf < 8; nf++)
#pragma unroll
            for (int i = 0; i < 4; i++) acc[mf][nf][i] = 0.0f;

    auto load_chunk = [&](int c, int s) {
        const uint32_t bb = base + (uint32_t)s * PSTG;
        const int k0 = c * 32;
#pragma unroll
        for (int t = 0; t < 2; t++) {
            int i = tid + t * 256;
            int r = i >> 2, c8 = i & 3;
            uint32_t soff = (uint32_t)(r * SROW + c8 * 8) * 2;
            cpa16(bb + soff, Ah + (size_t)(m0 + r) * DM + k0 + c8 * 8);
            cpa16(bb + PA_TB + soff, Bh + (size_t)(n0 + r) * DM + k0 + c8 * 8);
        }
    };

    auto compute_chunk = [&](int s) {
        const uint32_t ah32 = base + (uint32_t)s * PSTG;
        const uint32_t bh32 = ah32 + PA_TB;
#pragma unroll
        for (int ks = 0; ks < 2; ks++) {
            const uint32_t kByte = (uint32_t)(ks * 32);
            uint32_t ah[2][4], bh[4][4];
#pragma unroll
            for (int mf = 0; mf < 2; mf++)
                ldm4(ah[mf], ah32 + aOff + (uint32_t)(mf * 16 * SROW * 2) + kByte);
#pragma unroll
            for (int pp = 0; pp < 4; pp++)
                ldm4(bh[pp], bh32 + bOff + (uint32_t)(pp * 16 * SROW * 2) + kByte);
#pragma unroll
            for (int mf = 0; mf < 2; mf++)
#pragma unroll
                for (int nf = 0; nf < 8; nf++) {
                    const int pp = nf >> 1, q = (nf & 1) * 2;
                    mma_f16(acc[mf][nf], ah[mf], bh[pp][q], bh[pp][q+1]);
                }
        }
    };

    // Preload pair 0 (chunks 0,1 -> stages 0,1) as one group.
    load_chunk(0, 0);
    load_chunk(1, 1);
    CPA_COMMIT();

    for (int ip = 0; ip < 16; ip++) {         // pairs of chunks
        CPA_WAIT0();
        __syncthreads();                       // pair ip-1 fully consumed
        if (ip < 15) {                         // refill pair ip+1 into the stages
            load_chunk(2 * ip + 2, (2 * ip + 2) & 3);   // freed by pair ip-1
            load_chunk(2 * ip + 3, (2 * ip + 3) & 3);
        }
        CPA_COMMIT();
        compute_chunk((2 * ip) & 3);
        compute_chunk((2 * ip + 1) & 3);
    }

    // Epilogue: single fp16 plane, [B, H, S, hw] layout.
    const int g  = lane >> 2;
    const int t2 = (lane & 3) << 1;
#pragma unroll
    for (int mf = 0; mf < 2; mf++) {
        int mA  = m0 + warpM * 32 + mf * 16 + g;
        int mB  = mA + 8;
        int bbA = mA >> 11, ssA = mA & (SEQ - 1);
        int bbB = mB >> 11, ssB = mB & (SEQ - 1);
#pragma unroll
        for (int nf = 0; nf < 8; nf++) {
            int n  = n0 + warpN * 64 + nf * 8 + t2;
            int hh = n >> 6, dd = n & 63;
            size_t offA = (((size_t)(bbA * NH + hh)) * SEQ + ssA) * HW + dd;
            size_t offB = (((size_t)(bbB * NH + hh)) * SEQ + ssB) * HW + dd;
            *(uint32_t*)(Oh + offA) = packlo_h(acc[mf][nf][0], acc[mf][nf][1]);
            *(uint32_t*)(Oh + offB) = packlo_h(acc[mf][nf][2], acc[mf][nf][3]);
        }
    }
}

// ---------------------------------------------------------------------------
// Flash attention on mma.sync fp16: Q/K/V/P all single fp16 (fp32 accum).
// K-tile 64 rows; 4 KV stages; TWO tiles per iteration, ONE barrier per pair.
// smem = QTB + 8*KTB = 92160 B -> 2 CTAs/SM.
// ---------------------------------------------------------------------------
#define AROW 72
#define QTB  (128*AROW*2)
#define KTB  (64*AROW*2)

__device__ __forceinline__ void tile_async64(uint32_t sbase, const __half* g,
                                             int row0, int tid) {
#pragma unroll
    for (int t = 0; t < 2; t++) {
        int i  = tid + t * 256;
        int r  = i >> 3, c8 = i & 7;
        cpa16(sbase + (uint32_t)(r * AROW + c8 * 8) * 2,
              g + (size_t)(row0 + r) * HW + c8 * 8);
    }
}

__global__ __launch_bounds__(256, 2) void attn_mma(float* __restrict__ out)
{
    extern __shared__ unsigned short asm_[];
    const uint32_t base = smem_u32(asm_);
    const uint32_t qh32 = base;
    const uint32_t kvbase = base + QTB;   // stage s: Kh at (2s)KTB, Vh at (2s+1)KTB

    const int bh = blockIdx.y;
    const int b  = bh >> 4;
    const int h  = bh & 15;
    const int qt = (int)gridDim.x - 1 - (int)blockIdx.x;
    const int q0 = qt * 128;

    const int tid  = threadIdx.x;
    const int warp = tid >> 5;
    const int lane = tid & 31;
    const int g    = lane >> 2;
    const int t2   = (lane & 3) << 1;

    const float SC2    = SM_SCALE * L2E;
    const float slope2 = exp2f(-0.5f * (float)(h + 1)) * L2E;

    const __half* Qh = g_qh + (size_t)bh * SEQ * HW;
    const __half* Kh = g_kh + (size_t)bh * SEQ * HW;
    const __half* Vh = g_vh + (size_t)bh * SEQ * HW;

#pragma unroll
    for (int t = 0; t < 4; t++) {
        int i = tid + t * 256;
        int r = i >> 3, c8 = i & 7;
        *(uint4*)((char*)asm_ + (uint32_t)(r * AROW + c8 * 8) * 2) =
            *(const uint4*)(Qh + (size_t)(q0 + r) * HW + c8 * 8);
    }

    const uint32_t aElem = (uint32_t)((warp * 16 + (lane & 15)) * AROW + ((lane >> 4) << 3));
    const uint32_t bElem = (uint32_t)(((lane & 7) + ((lane >> 4) << 3)) * AROW + (((lane >> 3) & 1) << 3));
    const uint32_t vElem = (uint32_t)((lane & 15) * AROW + ((lane >> 4) << 3));

    float oacc[8][4];
#pragma unroll
    for (int nf = 0; nf < 8; nf++)
#pragma unroll
        for (int e = 0; e < 4; e++) oacc[nf][e] = 0.0f;

    float m0r = -3e38f, m1r = -3e38f, l0 = 0.0f, l1 = 0.0f;
    const int row0 = q0 + warp * 16 + g;
    const int row1 = row0 + 8;

    // Process one 64-col K/V tile resident in stage s.
    auto do_tile = [&](int kt, int s, bool diag) {
        const uint32_t kh32 = kvbase + (uint32_t)(2 * s + 0) * KTB;
        const uint32_t vh32 = kvbase + (uint32_t)(2 * s + 1) * KTB;
        const int k0g = kt * 64;

        float sacc[8][4];
#pragma unroll
        for (int nf = 0; nf < 8; nf++)
#pragma unroll
            for (int e = 0; e < 4; e++) sacc[nf][e] = 0.0f;

#pragma unroll
        for (int ks = 0; ks < 4; ks++) {
            uint32_t ah[4];
            ldm4(ah, qh32 + (aElem + ks * 16) * 2);
#pragma unroll
            for (int pp = 0; pp < 4; pp++) {
                uint32_t bhx[4];
                uint32_t bd = (bElem + (uint32_t)(pp * 16 * AROW) + (uint32_t)(ks * 16)) * 2;
                ldm4(bhx, kh32 + bd);
                mma_f16(sacc[2*pp],   ah, bhx[0], bhx[1]);
                mma_f16(sacc[2*pp+1], ah, bhx[2], bhx[3]);
            }
        }

        float mx0 = -3e38f, mx1 = -3e38f;
#pragma unroll
        for (int nf = 0; nf < 8; nf++) {
            int c0 = k0g + nf * 8 + t2;
            int c1 = c0 + 1;
            float v0 = sacc[nf][0] * SC2 + slope2 * (float)(c0 - row0);
            float v1 = sacc[nf][1] * SC2 + slope2 * (float)(c1 - row0);
            float v2 = sacc[nf][2] * SC2 + slope2 * (float)(c0 - row1);
            float v3 = sacc[nf][3] * SC2 + slope2 * (float)(c1 - row1);
            if (diag) {
                if (c0 > row0) v0 = -3e38f;
                if (c1 > row0) v1 = -3e38f;
                if (c0 > row1) v2 = -3e38f;
                if (c1 > row1) v3 = -3e38f;
            }
            sacc[nf][0] = v0; sacc[nf][1] = v1; sacc[nf][2] = v2; sacc[nf][3] = v3;
            mx0 = fmaxf(mx0, fmaxf(v0, v1));
            mx1 = fmaxf(mx1, fmaxf(v2, v3));
        }
        mx0 = fmaxf(mx0, __shfl_xor_sync(0xffffffffu, mx0, 1));
        mx0 = fmaxf(mx0, __shfl_xor_sync(0xffffffffu, mx0, 2));
        mx1 = fmaxf(mx1, __shfl_xor_sync(0xffffffffu, mx1, 1));
        mx1 = fmaxf(mx1, __shfl_xor_sync(0xffffffffu, mx1, 2));

        float mn0 = fmaxf(m0r, mx0);
        float mn1 = fmaxf(m1r, mx1);
        float corr0 = exp2f(m0r - mn0);
        float corr1 = exp2f(m1r - mn1);
        m0r = mn0; m1r = mn1;

        float rs0 = 0.0f, rs1 = 0.0f;
#pragma unroll
        for (int nf = 0; nf < 8; nf++) {
            float p0 = exp2f(sacc[nf][0] - mn0);
            float p1 = exp2f(sacc[nf][1] - mn0);
            float p2 = exp2f(sacc[nf][2] - mn1);
            float p3 = exp2f(sacc[nf][3] - mn1);
            sacc[nf][0] = p0; sacc[nf][1] = p1; sacc[nf][2] = p2; sacc[nf][3] = p3;
            rs0 += p0 + p1; rs1 += p2 + p3;
        }
        rs0 += __shfl_xor_sync(0xffffffffu, rs0, 1);
        rs0 += __shfl_xor_sync(0xffffffffu, rs0, 2);
        rs1 += __shfl_xor_sync(0xffffffffu, rs1, 1);
        rs1 += __shfl_xor_sync(0xffffffffu, rs1, 2);
        l0 = l0 * corr0 + rs0;
        l1 = l1 * corr1 + rs1;

#pragma unroll
        for (int nf = 0; nf < 8; nf++) {
            oacc[nf][0] *= corr0; oacc[nf][1] *= corr0;
            oacc[nf][2] *= corr1; oacc[nf][3] *= corr1;
        }

#pragma unroll
        for (int ks = 0; ks < 4; ks++) {
            uint32_t pah[4];
            pah[0] = packlo_h(sacc[2*ks][0],   sacc[2*ks][1]);
            pah[1] = packlo_h(sacc[2*ks][2],   sacc[2*ks][3]);
            pah[2] = packlo_h(sacc[2*ks+1][0], sacc[2*ks+1][1]);
            pah[3] = packlo_h(sacc[2*ks+1][2], sacc[2*ks+1][3]);
#pragma unroll
            for (int nb = 0; nb < 4; nb++) {
                uint32_t vhx[4];
                uint32_t vd = (vElem + (uint32_t)(ks * 16 * AROW) + (uint32_t)(nb * 16)) * 2;
                ldm4t(vhx, vh32 + vd);
                mma_f16(oacc[2*nb],   pah, vhx[0], vhx[1]);
                mma_f16(oacc[2*nb+1], pah, vhx[2], vhx[3]);
            }
        }
    };

    const int npairs = qt + 1;   // nkt = 2*qt+2 tiles, always even

    // Preload pair 0 (tiles 0,1 -> stages 0,1) as one group.
    tile_async64(kvbase + 0 * KTB, Kh, 0, tid);
    tile_async64(kvbase + 1 * KTB, Vh, 0, tid);
    tile_async64(kvbase + 2 * KTB, Kh, 64, tid);
    tile_async64(kvbase + 3 * KTB, Vh, 64, tid);
    CPA_COMMIT();

    for (int ip = 0; ip < npairs; ip++) {
        CPA_WAIT0();
        __syncthreads();                       // pair ip-1 fully consumed
        if (ip + 1 < npairs) {                 // refill pair ip+1 into freed stages
            int t0 = 2 * ip + 2;
            int s0 = t0 & 3, s1 = (t0 + 1) & 3;
            tile_async64(kvbase + (uint32_t)(2 * s0 + 0) * KTB, Kh, t0 * 64, tid);
            tile_async64(kvbase + (uint32_t)(2 * s0 + 1) * KTB, Vh, t0 * 64, tid);
            tile_async64(kvbase + (uint32_t)(2 * s1 + 0) * KTB, Kh, (t0 + 1) * 64, tid);
            tile_async64(kvbase + (uint32_t)(2 * s1 + 1) * KTB, Vh, (t0 + 1) * 64, tid);
        }
        CPA_COMMIT();
        int kt0 = 2 * ip;
        do_tile(kt0,     kt0 & 3,       kt0     >= 2 * qt);
        do_tile(kt0 + 1, (kt0 + 1) & 3, kt0 + 1 >= 2 * qt);
    }

    // ---- epilogue: normalize + store to [B, S, D] ----
    const float inv0 = 1.0f / l0;
    const float inv1 = 1.0f / l1;
    float* op = out + (size_t)b * SEQ * DM + (size_t)h * HW;
#pragma unroll
    for (int nf = 0; nf < 8; nf++) {
        int col = nf * 8 + t2;
        *(float2*)(op + (size_t)row0 * DM + col) =
            make_float2(oacc[nf][0] * inv0, oacc[nf][1] * inv0);
        *(float2*)(op + (size_t)row1 * DM + col) =
            make_float2(oacc[nf][2] * inv1, oacc[nf][3] * inv1);
    }
}

// ---------------------------------------------------------------------------
// Launch: inputs order = queries, keys, values, mask, Wq, Wk, Wv.
// ---------------------------------------------------------------------------
extern "C" void kernel_launch(void* const* d_in, const int* in_sizes, int n_in,
                              void* d_out, int out_size)
{
    (void)in_sizes; (void)n_in; (void)out_size;
    const float4* q  = (const float4*)d_in[0];
    const float4* k  = (const float4*)d_in[1];
    const float4* v  = (const float4*)d_in[2];
    const float4* wq = (const float4*)d_in[4];
    const float4* wk = (const float4*)d_in[5];
    const float4* wv = (const float4*)d_in[6];
    float* out = (float*)d_out;

    const int proj_smem = 4 * PSTG;            // 81920 B
    cudaFuncSetAttribute(proj_mma, cudaFuncAttributeMaxDynamicSharedMemorySize, proj_smem);
    const int attn_smem = QTB + 8 * KTB;       // 92160 B
    cudaFuncSetAttribute(attn_mma, cudaFuncAttributeMaxDynamicSharedMemorySize, attn_smem);

    split_kernel<<<dim3(4096, 6), 256>>>(q, k, v, wq, wk, wv);
    proj_mma<<<dim3(DM/128, (BATCH*SEQ)/128, 3), 256, proj_smem>>>();
    attn_mma<<<dim3(SEQ/128, BATCH*NH), 256, attn_smem>>>(out);
}

// round 16
// speedup vs baseline: 2.5208x; 1.0018x over previous
#include <cuda_runtime.h>
#include <cuda_fp16.h>
#include <cstdint>
#include <math.h>

#define BATCH 2
#define SEQ   2048
#define DM    1024
#define NH    16
#define HW    64
#define SM_SCALE 0.125f   // 1/sqrt(64)
#define L2E   1.44269504f

#define NELEM (BATCH*NH*SEQ*HW)
#define XN    (BATCH*SEQ*DM)
#define WN    (DM*DM)

// Projected Q/K/V (single fp16 plane each) in [B, H, S, hw] layout.
__device__ __half g_qh[NELEM];
__device__ __half g_kh[NELEM];
__device__ __half g_vh[NELEM];
// fp16 planes of inputs X and weights W for the projections.
__device__ __half g_xh[3*XN];
__device__ __half g_wh[3*WN];

// ---------------------------------------------------------------------------
// Helpers
// ---------------------------------------------------------------------------
__device__ __forceinline__ uint32_t smem_u32(const void* p) {
    uint32_t a;
    asm("{ .reg .u64 t; cvta.to.shared.u64 t, %1; cvt.u32.u64 %0, t; }"
        : "=r"(a) : "l"(p));
    return a;
}

__device__ __forceinline__ void ldm4(uint32_t r[4], uint32_t addr) {
    asm volatile("ldmatrix.sync.aligned.m8n8.x4.shared.b16 {%0,%1,%2,%3}, [%4];"
                 : "=r"(r[0]), "=r"(r[1]), "=r"(r[2]), "=r"(r[3]) : "r"(addr));
}
__device__ __forceinline__ void ldm4t(uint32_t r[4], uint32_t addr) {
    asm volatile("ldmatrix.sync.aligned.m8n8.x4.trans.shared.b16 {%0,%1,%2,%3}, [%4];"
                 : "=r"(r[0]), "=r"(r[1]), "=r"(r[2]), "=r"(r[3]) : "r"(addr));
}

__device__ __forceinline__ void mma_f16(float acc[4], const uint32_t a[4],
                                        uint32_t b0, uint32_t b1) {
    asm volatile(
        "mma.sync.aligned.m16n8k16.row.col.f32.f16.f16.f32 "
        "{%0,%1,%2,%3}, {%4,%5,%6,%7}, {%8,%9}, {%0,%1,%2,%3};"
        : "+f"(acc[0]), "+f"(acc[1]), "+f"(acc[2]), "+f"(acc[3])
        : "r"(a[0]), "r"(a[1]), "r"(a[2]), "r"(a[3]), "r"(b0), "r"(b1));
}

__device__ __forceinline__ uint32_t packlo_h(float a, float b) {
    __half2 h = __floats2half2_rn(a, b);
    return *reinterpret_cast<uint32_t*>(&h);
}
// exp2 of a float pair on the f16x2 MUFU path; result = packed fp16 pair.
__device__ __forceinline__ uint32_t hexp2_pack(float a, float b) {
    __half2 h = h2exp2(__floats2half2_rn(a, b));
    return *reinterpret_cast<uint32_t*>(&h);
}

__device__ __forceinline__ void cpa16(uint32_t saddr, const void* g) {
    asm volatile("cp.async.cg.shared.global [%0], [%1], 16;"
                 :: "r"(saddr), "l"(g) : "memory");
}
#define CPA_COMMIT() asm volatile("cp.async.commit_group;" ::: "memory")
#define CPA_WAIT0()  asm volatile("cp.async.wait_group 0;" ::: "memory")

// ---------------------------------------------------------------------------
// Split inputs/weights into single fp16 planes (one bandwidth pass).
// ---------------------------------------------------------------------------
__global__ __launch_bounds__(256) void split_kernel(
    const float4* __restrict__ xq, const float4* __restrict__ xk,
    const float4* __restrict__ xv, const float4* __restrict__ wq,
    const float4* __restrict__ wk, const float4* __restrict__ wv)
{
    const int y = blockIdx.y;
    const float4* src;
    __half* dh;
    if (y < 3) {
        src = (y == 0) ? xq : (y == 1) ? xk : xv;
        dh = g_xh + (size_t)y * XN;
    } else {
        if (blockIdx.x >= 1024) return;
        int w = y - 3;
        src = (w == 0) ? wq : (w == 1) ? wk : wv;
        dh = g_wh + (size_t)w * WN;
    }
    size_t i = (size_t)blockIdx.x * 256 + threadIdx.x;
    float4 a = src[i];
    *(uint2*)(dh + i * 4) = make_uint2(packlo_h(a.x, a.y), packlo_h(a.z, a.w));
}

// ---------------------------------------------------------------------------
// Projection GEMM on mma.sync fp16, single pass.
// CTA 128x128, warp tile 32x64, 8 warps (4M x 2N), 2 CTAs/SM.
// K-chunk 32, 4 stages, TWO chunks per iteration, ONE barrier per pair.
// grid = (8, 32, 3), block = 256. smem 4 x 20480 = 81920 B.
// ---------------------------------------------------------------------------
#define SROW   40
#define PA_TB  (128*SROW*2)
#define PB_TB  (128*SROW*2)
#define PSTG   (PA_TB + PB_TB)

__global__ __launch_bounds__(256, 2) void proj_mma()
{
    extern __shared__ unsigned short psm[];
    const uint32_t base = smem_u32(psm);

    const int z = blockIdx.z;
    const __half* Ah = g_xh + (size_t)z * XN;
    const __half* Bh = g_wh + (size_t)z * WN;
    __half* Oh = (z == 0) ? g_qh : (z == 1) ? g_kh : g_vh;

    const int tid   = threadIdx.x;
    const int wid   = tid >> 5;
    const int lane  = tid & 31;
    const int warpM = wid >> 1;
    const int warpN = wid & 1;
    const int m0    = blockIdx.y * 128;
    const int n0    = blockIdx.x * 128;

    const uint32_t aOff = ((uint32_t)(warpM * 32 + (lane & 15)) * SROW +
                           ((uint32_t)(lane >> 4) << 3)) * 2;
    const uint32_t bOff = ((uint32_t)(warpN * 64 + (lane & 7) + ((lane >> 4) << 3)) * SROW +
                           (((uint32_t)(lane >> 3) & 1) << 3)) * 2;

    float acc[2][8][4];
#pragma unroll
    for (int mf = 0; mf < 2; mf++)
#pragma unroll
        for (int nf = 0; nf < 8; nf++)
#pragma unroll
            for (int i = 0; i < 4; i++) acc[mf][nf][i] = 0.0f;

    auto load_chunk = [&](int c, int s) {
        const uint32_t bb = base + (uint32_t)s * PSTG;
        const int k0 = c * 32;
#pragma unroll
        for (int t = 0; t < 2; t++) {
            int i = tid + t * 256;
            int r = i >> 2, c8 = i & 3;
            uint32_t soff = (uint32_t)(r * SROW + c8 * 8) * 2;
            cpa16(bb + soff, Ah + (size_t)(m0 + r) * DM + k0 + c8 * 8);
            cpa16(bb + PA_TB + soff, Bh + (size_t)(n0 + r) * DM + k0 + c8 * 8);
        }
    };

    auto compute_chunk = [&](int s) {
        const uint32_t ah32 = base + (uint32_t)s * PSTG;
        const uint32_t bh32 = ah32 + PA_TB;
#pragma unroll
        for (int ks = 0; ks < 2; ks++) {
            const uint32_t kByte = (uint32_t)(ks * 32);
            uint32_t ah[2][4], bh[4][4];
#pragma unroll
            for (int mf = 0; mf < 2; mf++)
                ldm4(ah[mf], ah32 + aOff + (uint32_t)(mf * 16 * SROW * 2) + kByte);
#pragma unroll
            for (int pp = 0; pp < 4; pp++)
                ldm4(bh[pp], bh32 + bOff + (uint32_t)(pp * 16 * SROW * 2) + kByte);
#pragma unroll
            for (int mf = 0; mf < 2; mf++)
#pragma unroll
                for (int nf = 0; nf < 8; nf++) {
                    const int pp = nf >> 1, q = (nf & 1) * 2;
                    mma_f16(acc[mf][nf], ah[mf], bh[pp][q], bh[pp][q+1]);
                }
        }
    };

    load_chunk(0, 0);
    load_chunk(1, 1);
    CPA_COMMIT();

    for (int ip = 0; ip < 16; ip++) {
        CPA_WAIT0();
        __syncthreads();
        if (ip < 15) {
            load_chunk(2 * ip + 2, (2 * ip + 2) & 3);
            load_chunk(2 * ip + 3, (2 * ip + 3) & 3);
        }
        CPA_COMMIT();
        compute_chunk((2 * ip) & 3);
        compute_chunk((2 * ip + 1) & 3);
    }

    const int g  = lane >> 2;
    const int t2 = (lane & 3) << 1;
#pragma unroll
    for (int mf = 0; mf < 2; mf++) {
        int mA  = m0 + warpM * 32 + mf * 16 + g;
        int mB  = mA + 8;
        int bbA = mA >> 11, ssA = mA & (SEQ - 1);
        int bbB = mB >> 11, ssB = mB & (SEQ - 1);
#pragma unroll
        for (int nf = 0; nf < 8; nf++) {
            int n  = n0 + warpN * 64 + nf * 8 + t2;
            int hh = n >> 6, dd = n & 63;
            size_t offA = (((size_t)(bbA * NH + hh)) * SEQ + ssA) * HW + dd;
            size_t offB = (((size_t)(bbB * NH + hh)) * SEQ + ssB) * HW + dd;
            *(uint32_t*)(Oh + offA) = packlo_h(acc[mf][nf][0], acc[mf][nf][1]);
            *(uint32_t*)(Oh + offB) = packlo_h(acc[mf][nf][2], acc[mf][nf][3]);
        }
    }
}

// ---------------------------------------------------------------------------
// Flash attention, fp16 mma.sync. Softmax exp on f16x2 MUFU (h2exp2) with the
// result doubling as the packed P fragment; row sums via MMA-with-ones (no
// shuffles). K-tile 64 rows; 4 KV stages; one barrier per tile pair.
// smem = QTB + 8*KTB = 92160 B -> 2 CTAs/SM.
// ---------------------------------------------------------------------------
#define AROW 72
#define QTB  (128*AROW*2)
#define KTB  (64*AROW*2)
#define ONES_H2 0x3C003C00u   // fp16 {1.0, 1.0}

__device__ __forceinline__ void tile_async64(uint32_t sbase, const __half* g,
                                             int row0, int tid) {
#pragma unroll
    for (int t = 0; t < 2; t++) {
        int i  = tid + t * 256;
        int r  = i >> 3, c8 = i & 7;
        cpa16(sbase + (uint32_t)(r * AROW + c8 * 8) * 2,
              g + (size_t)(row0 + r) * HW + c8 * 8);
    }
}

__global__ __launch_bounds__(256, 2) void attn_mma(float* __restrict__ out)
{
    extern __shared__ unsigned short asm_[];
    const uint32_t base = smem_u32(asm_);
    const uint32_t qh32 = base;
    const uint32_t kvbase = base + QTB;

    const int bh = blockIdx.y;
    const int b  = bh >> 4;
    const int h  = bh & 15;
    const int qt = (int)gridDim.x - 1 - (int)blockIdx.x;
    const int q0 = qt * 128;

    const int tid  = threadIdx.x;
    const int warp = tid >> 5;
    const int lane = tid & 31;
    const int g    = lane >> 2;
    const int t2   = (lane & 3) << 1;

    const float SC2    = SM_SCALE * L2E;
    const float slope2 = exp2f(-0.5f * (float)(h + 1)) * L2E;

    const __half* Qh = g_qh + (size_t)bh * SEQ * HW;
    const __half* Kh = g_kh + (size_t)bh * SEQ * HW;
    const __half* Vh = g_vh + (size_t)bh * SEQ * HW;

#pragma unroll
    for (int t = 0; t < 4; t++) {
        int i = tid + t * 256;
        int r = i >> 3, c8 = i & 7;
        *(uint4*)((char*)asm_ + (uint32_t)(r * AROW + c8 * 8) * 2) =
            *(const uint4*)(Qh + (size_t)(q0 + r) * HW + c8 * 8);
    }

    const uint32_t aElem = (uint32_t)((warp * 16 + (lane & 15)) * AROW + ((lane >> 4) << 3));
    const uint32_t bElem = (uint32_t)(((lane & 7) + ((lane >> 4) << 3)) * AROW + (((lane >> 3) & 1) << 3));
    const uint32_t vElem = (uint32_t)((lane & 15) * AROW + ((lane >> 4) << 3));

    float oacc[8][4];
#pragma unroll
    for (int nf = 0; nf < 8; nf++)
#pragma unroll
        for (int e = 0; e < 4; e++) oacc[nf][e] = 0.0f;

    float m0r = -3e38f, m1r = -3e38f, l0 = 0.0f, l1 = 0.0f;
    const int row0 = q0 + warp * 16 + g;
    const int row1 = row0 + 8;

    auto do_tile = [&](int kt, int s, bool diag) {
        const uint32_t kh32 = kvbase + (uint32_t)(2 * s + 0) * KTB;
        const uint32_t vh32 = kvbase + (uint32_t)(2 * s + 1) * KTB;
        const int k0g = kt * 64;

        float sacc[8][4];
#pragma unroll
        for (int nf = 0; nf < 8; nf++)
#pragma unroll
            for (int e = 0; e < 4; e++) sacc[nf][e] = 0.0f;

#pragma unroll
        for (int ks = 0; ks < 4; ks++) {
            uint32_t ah[4];
            ldm4(ah, qh32 + (aElem + ks * 16) * 2);
#pragma unroll
            for (int pp = 0; pp < 4; pp++) {
                uint32_t bhx[4];
                uint32_t bd = (bElem + (uint32_t)(pp * 16 * AROW) + (uint32_t)(ks * 16)) * 2;
                ldm4(bhx, kh32 + bd);
                mma_f16(sacc[2*pp],   ah, bhx[0], bhx[1]);
                mma_f16(sacc[2*pp+1], ah, bhx[2], bhx[3]);
            }
        }

        // scale + ALiBi + causal (log2 domain); row max
        float mx0 = -3e38f, mx1 = -3e38f;
#pragma unroll
        for (int nf = 0; nf < 8; nf++) {
            int c0 = k0g + nf * 8 + t2;
            int c1 = c0 + 1;
            float v0 = sacc[nf][0] * SC2 + slope2 * (float)(c0 - row0);
            float v1 = sacc[nf][1] * SC2 + slope2 * (float)(c1 - row0);
            float v2 = sacc[nf][2] * SC2 + slope2 * (float)(c0 - row1);
            float v3 = sacc[nf][3] * SC2 + slope2 * (float)(c1 - row1);
            if (diag) {
                if (c0 > row0) v0 = -3e38f;
                if (c1 > row0) v1 = -3e38f;
                if (c0 > row1) v2 = -3e38f;
                if (c1 > row1) v3 = -3e38f;
            }
            sacc[nf][0] = v0; sacc[nf][1] = v1; sacc[nf][2] = v2; sacc[nf][3] = v3;
            mx0 = fmaxf(mx0, fmaxf(v0, v1));
            mx1 = fmaxf(mx1, fmaxf(v2, v3));
        }
        mx0 = fmaxf(mx0, __shfl_xor_sync(0xffffffffu, mx0, 1));
        mx0 = fmaxf(mx0, __shfl_xor_sync(0xffffffffu, mx0, 2));
        mx1 = fmaxf(mx1, __shfl_xor_sync(0xffffffffu, mx1, 1));
        mx1 = fmaxf(mx1, __shfl_xor_sync(0xffffffffu, mx1, 2));

        float mn0 = fmaxf(m0r, mx0);
        float mn1 = fmaxf(m1r, mx1);
        float corr0 = exp2f(m0r - mn0);
        float corr1 = exp2f(m1r - mn1);
        m0r = mn0; m1r = mn1;

#pragma unroll
        for (int nf = 0; nf < 8; nf++) {
            oacc[nf][0] *= corr0; oacc[nf][1] *= corr0;
            oacc[nf][2] *= corr1; oacc[nf][3] *= corr1;
        }

        // P = exp2(v - m) on f16x2 MUFU -> packed fp16 fragments directly.
        // Row sums via MMA with all-ones B fragment (no shuffles).
        float lacc[4] = {0.f, 0.f, 0.f, 0.f};
#pragma unroll
        for (int ks = 0; ks < 4; ks++) {
            uint32_t pah[4];
            pah[0] = hexp2_pack(sacc[2*ks][0]   - mn0, sacc[2*ks][1]   - mn0);
            pah[1] = hexp2_pack(sacc[2*ks][2]   - mn1, sacc[2*ks][3]   - mn1);
            pah[2] = hexp2_pack(sacc[2*ks+1][0] - mn0, sacc[2*ks+1][1] - mn0);
            pah[3] = hexp2_pack(sacc[2*ks+1][2] - mn1, sacc[2*ks+1][3] - mn1);
            mma_f16(lacc, pah, ONES_H2, ONES_H2);
#pragma unroll
            for (int nb = 0; nb < 4; nb++) {
                uint32_t vhx[4];
                uint32_t vd = (vElem + (uint32_t)(ks * 16 * AROW) + (uint32_t)(nb * 16)) * 2;
                ldm4t(vhx, vh32 + vd);
                mma_f16(oacc[2*nb],   pah, vhx[0], vhx[1]);
                mma_f16(oacc[2*nb+1], pah, vhx[2], vhx[3]);
            }
        }
        l0 = l0 * corr0 + lacc[0];
        l1 = l1 * corr1 + lacc[2];
    };

    const int npairs = qt + 1;   // nkt = 2*qt+2 tiles, always even

    tile_async64(kvbase + 0 * KTB, Kh, 0, tid);
    tile_async64(kvbase + 1 * KTB, Vh, 0, tid);
    tile_async64(kvbase + 2 * KTB, Kh, 64, tid);
    tile_async64(kvbase + 3 * KTB, Vh, 64, tid);
    CPA_COMMIT();

    for (int ip = 0; ip < npairs; ip++) {
        CPA_WAIT0();
        __syncthreads();
        if (ip + 1 < npairs) {
            int t0 = 2 * ip + 2;
            int s0 = t0 & 3, s1 = (t0 + 1) & 3;
            tile_async64(kvbase + (uint32_t)(2 * s0 + 0) * KTB, Kh, t0 * 64, tid);
            tile_async64(kvbase + (uint32_t)(2 * s0 + 1) * KTB, Vh, t0 * 64, tid);
            tile_async64(kvbase + (uint32_t)(2 * s1 + 0) * KTB, Kh, (t0 + 1) * 64, tid);
            tile_async64(kvbase + (uint32_t)(2 * s1 + 1) * KTB, Vh, (t0 + 1) * 64, tid);
        }
        CPA_COMMIT();
        int kt0 = 2 * ip;
        do_tile(kt0,     kt0 & 3,       kt0     >= 2 * qt);
        do_tile(kt0 + 1, (kt0 + 1) & 3, kt0 + 1 >= 2 * qt);
    }

    // ---- epilogue: normalize + store to [B, S, D] ----
    const float inv0 = 1.0f / l0;
    const float inv1 = 1.0f / l1;
    float* op = out + (size_t)b * SEQ * DM + (size_t)h * HW;
#pragma unroll
    for (int nf = 0; nf < 8; nf++) {
        int col = nf * 8 + t2;
        *(float2*)(op + (size_t)row0 * DM + col) =
            make_float2(oacc[nf][0] * inv0, oacc[nf][1] * inv0);
        *(float2*)(op + (size_t)row1 * DM + col) =
            make_float2(oacc[nf][2] * inv1, oacc[nf][3] * inv1);
    }
}

// ---------------------------------------------------------------------------
// Launch: inputs order = queries, keys, values, mask, Wq, Wk, Wv.
// ---------------------------------------------------------------------------
extern "C" void kernel_launch(void* const* d_in, const int* in_sizes, int n_in,
                              void* d_out, int out_size)
{
    (void)in_sizes; (void)n_in; (void)out_size;
    const float4* q  = (const float4*)d_in[0];
    const float4* k  = (const float4*)d_in[1];
    const float4* v  = (const float4*)d_in[2];
    const float4* wq = (const float4*)d_in[4];
    const float4* wk = (const float4*)d_in[5];
    const float4* wv = (const float4*)d_in[6];
    float* out = (float*)d_out;

    const int proj_smem = 4 * PSTG;            // 81920 B
    cudaFuncSetAttribute(proj_mma, cudaFuncAttributeMaxDynamicSharedMemorySize, proj_smem);
    const int attn_smem = QTB + 8 * KTB;       // 92160 B
    cudaFuncSetAttribute(attn_mma, cudaFuncAttributeMaxDynamicSharedMemorySize, attn_smem);

    split_kernel<<<dim3(4096, 6), 256>>>(q, k, v, wq, wk, wv);
    proj_mma<<<dim3(DM/128, (BATCH*SEQ)/128, 3), 256, proj_smem>>>();
    attn_mma<<<dim3(SEQ/128, BATCH*NH), 256, attn_smem>>>(out);
}